// round 2
// baseline (speedup 1.0000x reference)
#include <cuda_runtime.h>

#define NN   50000
#define EE   800000
#define C1   128
#define C2   512
#define C3   256
#define CCAT 384
#define CM   128
#define HEADS 4

// ---------------- scratch (static device globals; no allocation) -------------
__device__ float    g_dinv[NN];
__device__ float    g_h1 [NN*C1];
__device__ float    g_g1 [NN*C1];
__device__ float    g_h2 [NN*C2];
__device__ float    g_gat[NN*C2];
__device__ float    g_h3 [NN*C3];
__device__ float    g_g2 [NN*C3];
__device__ float    g_cat[NN*CCAT];
__device__ float    g_mh [NN*CM];
__device__ float    g_asrc[NN*HEADS];
__device__ float    g_adst[NN*HEADS];
__device__ unsigned g_menc[NN*HEADS];
__device__ float    g_m   [NN*HEADS];
__device__ float    g_z   [NN*HEADS];
__device__ float    g_aself[NN*HEADS];
__device__ float    g_alpha[EE*HEADS];

// buffer ids for generic kernels
#define ID_H1  0
#define ID_G1  1
#define ID_H2  2
#define ID_GAT 3
#define ID_H3  4
#define ID_G2  5
#define ID_CAT 6
#define ID_MH  7

__device__ __forceinline__ float* buf(int id) {
    switch (id) {
        case ID_H1:  return g_h1;
        case ID_G1:  return g_g1;
        case ID_H2:  return g_h2;
        case ID_GAT: return g_gat;
        case ID_H3:  return g_h3;
        case ID_G2:  return g_g2;
        case ID_CAT: return g_cat;
        default:     return g_mh;
    }
}

// order-preserving float<->uint for atomicMax
__device__ __forceinline__ unsigned fenc(float f) {
    unsigned u = __float_as_uint(f);
    return (u & 0x80000000u) ? ~u : (u | 0x80000000u);
}
__device__ __forceinline__ float fdec(unsigned u) {
    return (u & 0x80000000u) ? __uint_as_float(u & 0x7FFFFFFFu) : __uint_as_float(~u);
}
__device__ __forceinline__ float lrelu(float x) { return x >= 0.f ? x : 0.2f * x; }

// ---------------- degree ----------------------------------------------------
__global__ void k_deg_init() {
    int i = blockIdx.x * blockDim.x + threadIdx.x;
    if (i < NN) g_dinv[i] = 1.0f;                 // self-loop
}
__global__ void k_deg_acc(const int* __restrict__ ei) {
    int e = blockIdx.x * blockDim.x + threadIdx.x;
    if (e < EE) atomicAdd(&g_dinv[ei[EE + e]], 1.0f);
}
__global__ void k_deg_fin() {
    int i = blockIdx.x * blockDim.x + threadIdx.x;
    if (i < NN) g_dinv[i] = rsqrtf(g_dinv[i]);
}

// ---------------- generic SGEMM: C[M,Nc] = A[M,K] @ B[K,Nc] (+bias, relu) ----
// 128x128x16 tiles, 8x8 per thread, 256 threads
__global__ void __launch_bounds__(256) k_sgemm(
    const float* __restrict__ Aext, int Aid,
    const float* __restrict__ B, const float* __restrict__ bias,
    int Cid, int M, int Nc, int K, int doRelu)
{
    __shared__ float As[16][128];
    __shared__ float Bs[16][128];
    const float* A = Aext ? Aext : buf(Aid);
    float* C = buf(Cid);

    int tid  = threadIdx.x;
    int brow = blockIdx.y * 128;
    int bcol = blockIdx.x * 128;

    int arow = tid >> 2;            // 0..63
    int acol = (tid & 3) * 4;
    int brw  = tid >> 5;            // 0..7
    int bcl  = (tid & 31) * 4;
    int ty   = tid >> 4;            // 0..15
    int tx   = tid & 15;

    float acc[8][8];
#pragma unroll
    for (int i = 0; i < 8; i++)
#pragma unroll
        for (int j = 0; j < 8; j++) acc[i][j] = 0.f;

    for (int k0 = 0; k0 < K; k0 += 16) {
        float4 a0 = make_float4(0, 0, 0, 0), a1 = a0;
        if (brow + arow < M)      a0 = *(const float4*)&A[(size_t)(brow + arow) * K + k0 + acol];
        if (brow + arow + 64 < M) a1 = *(const float4*)&A[(size_t)(brow + arow + 64) * K + k0 + acol];
        As[acol + 0][arow] = a0.x; As[acol + 1][arow] = a0.y;
        As[acol + 2][arow] = a0.z; As[acol + 3][arow] = a0.w;
        As[acol + 0][arow + 64] = a1.x; As[acol + 1][arow + 64] = a1.y;
        As[acol + 2][arow + 64] = a1.z; As[acol + 3][arow + 64] = a1.w;

        *(float4*)&Bs[brw][bcl]     = *(const float4*)&B[(size_t)(k0 + brw) * Nc + bcol + bcl];
        *(float4*)&Bs[brw + 8][bcl] = *(const float4*)&B[(size_t)(k0 + brw + 8) * Nc + bcol + bcl];
        __syncthreads();

#pragma unroll
        for (int kk = 0; kk < 16; kk++) {
            float a[8], b[8];
            *(float4*)&a[0] = *(float4*)&As[kk][ty * 8];
            *(float4*)&a[4] = *(float4*)&As[kk][ty * 8 + 4];
            *(float4*)&b[0] = *(float4*)&Bs[kk][tx * 8];
            *(float4*)&b[4] = *(float4*)&Bs[kk][tx * 8 + 4];
#pragma unroll
            for (int i = 0; i < 8; i++)
#pragma unroll
                for (int j = 0; j < 8; j++) acc[i][j] += a[i] * b[j];
        }
        __syncthreads();
    }

#pragma unroll
    for (int i = 0; i < 8; i++) {
        int r = brow + ty * 8 + i;
        if (r >= M) continue;
#pragma unroll
        for (int j = 0; j < 8; j++) {
            int c = bcol + tx * 8 + j;
            float v = acc[i][j] + (bias ? bias[c] : 0.f);
            if (doRelu) v = fmaxf(v, 0.f);
            C[(size_t)r * Nc + c] = v;
        }
    }
}

// ---------------- GCN init (self loop + bias) and scatter --------------------
__global__ void k_gcn_init(int Hid, int Oid, const float* __restrict__ bias, int C) {
    int idx = blockIdx.x * blockDim.x + threadIdx.x;
    if (idx >= NN * C) return;
    int n = idx / C, c = idx % C;
    float di = g_dinv[n];
    buf(Oid)[idx] = buf(Hid)[idx] * di * di + bias[c];
}

__global__ void k_gcn_scatter(const int* __restrict__ ei, int Hid, int Oid, int C) {
    int pe = C >> 2;                       // threads per edge (float4 each)
    int t = blockIdx.x * blockDim.x + threadIdx.x;
    if (t >= EE * pe) return;
    int e = t / pe;
    int c = (t - e * pe) * 4;
    int s = ei[e];
    int d = ei[EE + e];
    float w = g_dinv[s] * g_dinv[d];
    const float* H = buf(Hid);
    float* O = buf(Oid);
    float4 v = *(const float4*)&H[(size_t)s * C + c];
    float* o = &O[(size_t)d * C + c];
    atomicAdd(o + 0, v.x * w);
    atomicAdd(o + 1, v.y * w);
    atomicAdd(o + 2, v.z * w);
    atomicAdd(o + 3, v.w * w);
}

__global__ void k_relu_ip(int id, int total) {
    int i = blockIdx.x * blockDim.x + threadIdx.x;
    if (i < total) {
        float* p = buf(id);
        p[i] = fmaxf(p[i], 0.f);
    }
}

// ---------------- GAT --------------------------------------------------------
// attention scores per (node, head): warp reduction over 128 channels
__global__ void k_att(const float* __restrict__ attS, const float* __restrict__ attD) {
    int gw = (blockIdx.x * blockDim.x + threadIdx.x) >> 5;
    int lane = threadIdx.x & 31;
    if (gw >= NN * HEADS) return;
    int n = gw / HEADS, h = gw - n * HEADS;
    const float* hp = &g_h2[(size_t)n * C2 + h * 128];
    const float* as = &attS[h * 128];
    const float* ad = &attD[h * 128];
    float ss = 0.f, sd = 0.f;
#pragma unroll
    for (int c = lane; c < 128; c += 32) {
        float v = hp[c];
        ss += v * as[c];
        sd += v * ad[c];
    }
#pragma unroll
    for (int o = 16; o; o >>= 1) {
        ss += __shfl_xor_sync(0xffffffffu, ss, o);
        sd += __shfl_xor_sync(0xffffffffu, sd, o);
    }
    if (lane == 0) {
        g_asrc[gw] = ss;
        g_adst[gw] = sd;
        g_menc[gw] = fenc(lrelu(ss + sd));      // self-loop seeds the max
    }
}

__global__ void k_emax(const int* __restrict__ ei) {
    int t = blockIdx.x * blockDim.x + threadIdx.x;
    if (t >= EE * HEADS) return;
    int e = t >> 2, h = t & 3;
    int s = ei[e], d = ei[EE + e];
    float ev = lrelu(g_asrc[s * HEADS + h] + g_adst[d * HEADS + h]);
    atomicMax(&g_menc[d * HEADS + h], fenc(ev));
}

__global__ void k_zinit() {
    int w = blockIdx.x * blockDim.x + threadIdx.x;
    if (w >= NN * HEADS) return;
    float m = fdec(g_menc[w]);
    g_m[w] = m;
    float e = lrelu(g_asrc[w] + g_adst[w]);
    g_z[w] = expf(e - m);                      // self-loop contribution
}

__global__ void k_zacc(const int* __restrict__ ei) {
    int t = blockIdx.x * blockDim.x + threadIdx.x;
    if (t >= EE * HEADS) return;
    int e = t >> 2, h = t & 3;
    int s = ei[e], d = ei[EE + e];
    float ev = lrelu(g_asrc[s * HEADS + h] + g_adst[d * HEADS + h]);
    atomicAdd(&g_z[d * HEADS + h], expf(ev - g_m[d * HEADS + h]));
}

__global__ void k_alpha(const int* __restrict__ ei) {
    int t = blockIdx.x * blockDim.x + threadIdx.x;
    if (t >= EE * HEADS) return;
    int e = t >> 2, h = t & 3;
    int s = ei[e], d = ei[EE + e];
    int dh = d * HEADS + h;
    float ev = lrelu(g_asrc[s * HEADS + h] + g_adst[dh]);
    g_alpha[t] = expf(ev - g_m[dh]) / g_z[dh];
}

__global__ void k_aself() {
    int w = blockIdx.x * blockDim.x + threadIdx.x;
    if (w >= NN * HEADS) return;
    float e = lrelu(g_asrc[w] + g_adst[w]);
    g_aself[w] = expf(e - g_m[w]) / g_z[w];
}

__global__ void k_gat_init(const float* __restrict__ gat_b) {
    int idx = blockIdx.x * blockDim.x + threadIdx.x;
    if (idx >= NN * C2) return;
    int n = idx / C2, c = idx - n * C2;
    g_gat[idx] = g_h2[idx] * g_aself[n * HEADS + (c >> 7)] + gat_b[c];
}

__global__ void k_gat_scatter(const int* __restrict__ ei) {
    int t = blockIdx.x * blockDim.x + threadIdx.x;
    if (t >= EE * 128) return;                  // 128 float4-threads per edge (C2=512)
    int e = t >> 7;
    int c = (t & 127) * 4;
    int s = ei[e];
    int d = ei[EE + e];
    float a = g_alpha[e * HEADS + (c >> 7)];
    float4 v = *(const float4*)&g_h2[(size_t)s * C2 + c];
    float* o = &g_gat[(size_t)d * C2 + c];
    atomicAdd(o + 0, v.x * a);
    atomicAdd(o + 1, v.y * a);
    atomicAdd(o + 2, v.z * a);
    atomicAdd(o + 3, v.w * a);
}

// ---------------- LayerNorm (one block of 128 threads per node) --------------
__global__ void k_ln(int Xid, int Yid, const float* __restrict__ gw,
                     const float* __restrict__ bw, int C, int ldY, int doRelu)
{
    int n = blockIdx.x;
    const float* x = buf(Xid) + (size_t)n * C;
    float* y = buf(Yid) + (size_t)n * ldY;
    int tid = threadIdx.x, lane = tid & 31, warp = tid >> 5;

    float s = 0.f, s2 = 0.f;
    for (int c = tid; c < C; c += 128) {
        float v = x[c];
        s += v; s2 += v * v;
    }
#pragma unroll
    for (int o = 16; o; o >>= 1) {
        s  += __shfl_xor_sync(0xffffffffu, s, o);
        s2 += __shfl_xor_sync(0xffffffffu, s2, o);
    }
    __shared__ float shs[4], shs2[4], smu, sinv;
    if (lane == 0) { shs[warp] = s; shs2[warp] = s2; }
    __syncthreads();
    if (tid == 0) {
        float S = shs[0] + shs[1] + shs[2] + shs[3];
        float S2 = shs2[0] + shs2[1] + shs2[2] + shs2[3];
        float mu = S / C;
        float var = S2 / C - mu * mu;
        smu = mu;
        sinv = rsqrtf(var + 1e-5f);
    }
    __syncthreads();
    float mu = smu, inv = sinv;
    for (int c = tid; c < C; c += 128) {
        float v = (x[c] - mu) * inv * gw[c] + bw[c];
        if (doRelu) v = fmaxf(v, 0.f);
        y[c] = v;
    }
}

// copy x into the concat buffer tail
__global__ void k_catx(const float* __restrict__ x) {
    int idx = blockIdx.x * blockDim.x + threadIdx.x;
    if (idx >= NN * C1) return;
    int n = idx / C1, c = idx - n * C1;
    g_cat[(size_t)n * CCAT + C3 + c] = x[idx];
}

// final MLP layer: [N,128] @ [128,2] + b. One warp per node.
__global__ void k_out(const float* __restrict__ w2, const float* __restrict__ b2,
                      float* __restrict__ out)
{
    int gw = (blockIdx.x * blockDim.x + threadIdx.x) >> 5;
    int lane = threadIdx.x & 31;
    if (gw >= NN) return;
    const float* hp = &g_mh[(size_t)gw * CM];
    float a0 = 0.f, a1 = 0.f;
#pragma unroll
    for (int c = lane; c < CM; c += 32) {
        float v = hp[c];
        a0 += v * w2[c * 2];
        a1 += v * w2[c * 2 + 1];
    }
#pragma unroll
    for (int o = 16; o; o >>= 1) {
        a0 += __shfl_xor_sync(0xffffffffu, a0, o);
        a1 += __shfl_xor_sync(0xffffffffu, a1, o);
    }
    if (lane == 0) {
        out[gw * 2 + 0] = a0 + b2[0];
        out[gw * 2 + 1] = a1 + b2[1];
    }
}

// ---------------- launch -----------------------------------------------------
static inline int cdiv(int a, int b) { return (a + b - 1) / b; }

extern "C" void kernel_launch(void* const* d_in, const int* in_sizes, int n_in,
                              void* d_out, int out_size)
{
    (void)in_sizes; (void)n_in; (void)out_size;
    const float* x      = (const float*)d_in[0];
    const int*   ei     = (const int*)d_in[1];        // int32 (harness downcasts int64)
    const float* gcn1_w = (const float*)d_in[2];
    const float* gcn1_b = (const float*)d_in[3];
    const float* gat_w  = (const float*)d_in[4];
    const float* att_s  = (const float*)d_in[5];
    const float* att_d  = (const float*)d_in[6];
    const float* gat_b  = (const float*)d_in[7];
    const float* n1_g   = (const float*)d_in[8];
    const float* n1_b   = (const float*)d_in[9];
    const float* gcn2_w = (const float*)d_in[10];
    const float* gcn2_b = (const float*)d_in[11];
    const float* n2_g   = (const float*)d_in[12];
    const float* n2_b   = (const float*)d_in[13];
    const float* mlp_w1 = (const float*)d_in[14];
    const float* mlp_b1 = (const float*)d_in[15];
    const float* mlp_w2 = (const float*)d_in[16];
    const float* mlp_b2 = (const float*)d_in[17];
    float* out = (float*)d_out;

    const int T = 256;
    int mblk = cdiv(NN, 128);   // 391

    // degrees
    k_deg_init<<<cdiv(NN, T), T>>>();
    k_deg_acc<<<cdiv(EE, T), T>>>(ei);
    k_deg_fin<<<cdiv(NN, T), T>>>();

    // GCN1
    k_sgemm<<<dim3(1, mblk), T>>>(x, -1, gcn1_w, nullptr, ID_H1, NN, C1, C1, 0);
    k_gcn_init<<<cdiv(NN * C1, T), T>>>(ID_H1, ID_G1, gcn1_b, C1);
    k_gcn_scatter<<<cdiv(EE * (C1 / 4), T), T>>>(ei, ID_H1, ID_G1, C1);
    k_relu_ip<<<cdiv(NN * C1, T), T>>>(ID_G1, NN * C1);

    // GAT
    k_sgemm<<<dim3(C2 / 128, mblk), T>>>(nullptr, ID_G1, gat_w, nullptr, ID_H2, NN, C2, C1, 0);
    k_att<<<cdiv(NN * HEADS * 32, T), T>>>(att_s, att_d);
    k_emax<<<cdiv(EE * HEADS, T), T>>>(ei);
    k_zinit<<<cdiv(NN * HEADS, T), T>>>();
    k_zacc<<<cdiv(EE * HEADS, T), T>>>(ei);
    k_alpha<<<cdiv(EE * HEADS, T), T>>>(ei);
    k_aself<<<cdiv(NN * HEADS, T), T>>>();
    k_gat_init<<<cdiv(NN * C2, T), T>>>(gat_b);
    k_gat_scatter<<<cdiv(EE * 128, T), T>>>(ei);

    // LN1 (in place)
    k_ln<<<NN, 128>>>(ID_GAT, ID_GAT, n1_g, n1_b, C2, C2, 0);

    // GCN2
    k_sgemm<<<dim3(C3 / 128, mblk), T>>>(nullptr, ID_GAT, gcn2_w, nullptr, ID_H3, NN, C3, C2, 0);
    k_gcn_init<<<cdiv(NN * C3, T), T>>>(ID_H3, ID_G2, gcn2_b, C3);
    k_gcn_scatter<<<cdiv(EE * (C3 / 4), T), T>>>(ei, ID_H3, ID_G2, C3);

    // LN2 + relu into concat buffer; append x
    k_ln<<<NN, 128>>>(ID_G2, ID_CAT, n2_g, n2_b, C3, CCAT, 1);
    k_catx<<<cdiv(NN * C1, T), T>>>(x);

    // MLP
    k_sgemm<<<dim3(CM / 128, mblk), T>>>(nullptr, ID_CAT, mlp_w1, mlp_b1, ID_MH, NN, CM, CCAT, 1);
    k_out<<<cdiv(NN * 32, T), T>>>(mlp_w2, mlp_b2, out);
}

// round 3
// speedup vs baseline: 2.1928x; 2.1928x over previous
#include <cuda_runtime.h>

#define NN   50000
#define EE   800000
#define C1   128
#define C2   512
#define C3   256
#define CCAT 384
#define CM   128
#define HEADS 4

// ---------------- scratch (static device globals; no allocation) -------------
__device__ float    g_dinv[NN];
__device__ int      g_cnt[NN];
__device__ int      g_cursor[NN];
__device__ int      g_rowptr[NN + 1];
__device__ int      g_col[EE];          // src node per dst-sorted edge
__device__ float    g_h1 [NN*C1];
__device__ float    g_g1 [NN*C1];
__device__ float    g_h2 [NN*C2];
__device__ float    g_gat[NN*C2];
__device__ float    g_h3 [NN*C3];
__device__ float    g_g2 [NN*C3];
__device__ float    g_cat[NN*CCAT];
__device__ float    g_mh [NN*CM];
__device__ float    g_asrc[NN*HEADS];
__device__ float    g_adst[NN*HEADS];

// buffer ids for generic kernels
#define ID_H1  0
#define ID_G1  1
#define ID_H2  2
#define ID_GAT 3
#define ID_H3  4
#define ID_G2  5
#define ID_CAT 6
#define ID_MH  7

__device__ __forceinline__ float* buf(int id) {
    switch (id) {
        case ID_H1:  return g_h1;
        case ID_G1:  return g_g1;
        case ID_H2:  return g_h2;
        case ID_GAT: return g_gat;
        case ID_H3:  return g_h3;
        case ID_G2:  return g_g2;
        case ID_CAT: return g_cat;
        default:     return g_mh;
    }
}

__device__ __forceinline__ float lrelu(float x) { return x >= 0.f ? x : 0.2f * x; }

// ---------------- CSR build --------------------------------------------------
__global__ void k_zero() {
    int i = blockIdx.x * blockDim.x + threadIdx.x;
    if (i < NN) { g_cnt[i] = 0; g_cursor[i] = 0; }
}
__global__ void k_count(const int* __restrict__ ei) {
    int e = blockIdx.x * blockDim.x + threadIdx.x;
    if (e < EE) atomicAdd(&g_cnt[ei[EE + e]], 1);
}
// single-block exclusive scan of g_cnt -> g_rowptr, plus dinv = rsqrt(cnt+1)
__global__ void __launch_bounds__(1024) k_scan() {
    __shared__ int s[1024];
    __shared__ int carry;
    int tid = threadIdx.x;
    if (tid == 0) carry = 0;
    __syncthreads();
    for (int base = 0; base < NN; base += 1024) {
        int i = base + tid;
        int v = (i < NN) ? g_cnt[i] : 0;
        if (i < NN) g_dinv[i] = rsqrtf((float)(v + 1));
        s[tid] = v;
        __syncthreads();
#pragma unroll
        for (int off = 1; off < 1024; off <<= 1) {
            int t = (tid >= off) ? s[tid - off] : 0;
            __syncthreads();
            s[tid] += t;
            __syncthreads();
        }
        int c0 = carry;
        if (i < NN) g_rowptr[i] = c0 + s[tid] - v;
        int total = s[1023];
        __syncthreads();
        if (tid == 0) carry = c0 + total;
        __syncthreads();
    }
    if (tid == 0) g_rowptr[NN] = carry;   // == EE
}
__global__ void k_fill(const int* __restrict__ ei) {
    int e = blockIdx.x * blockDim.x + threadIdx.x;
    if (e >= EE) return;
    int d = ei[EE + e];
    int pos = atomicAdd(&g_cursor[d], 1);
    g_col[g_rowptr[d] + pos] = ei[e];
}

// ---------------- generic SGEMM: C[M,Nc] = A[M,K] @ B[K,Nc] (+bias, relu) ----
__global__ void __launch_bounds__(256) k_sgemm(
    const float* __restrict__ Aext, int Aid,
    const float* __restrict__ B, const float* __restrict__ bias,
    int Cid, int M, int Nc, int K, int doRelu)
{
    __shared__ float As[16][128];
    __shared__ float Bs[16][128];
    const float* A = Aext ? Aext : buf(Aid);
    float* C = buf(Cid);

    int tid  = threadIdx.x;
    int brow = blockIdx.y * 128;
    int bcol = blockIdx.x * 128;

    int arow = tid >> 2;
    int acol = (tid & 3) * 4;
    int brw  = tid >> 5;
    int bcl  = (tid & 31) * 4;
    int ty   = tid >> 4;
    int tx   = tid & 15;

    float acc[8][8];
#pragma unroll
    for (int i = 0; i < 8; i++)
#pragma unroll
        for (int j = 0; j < 8; j++) acc[i][j] = 0.f;

    for (int k0 = 0; k0 < K; k0 += 16) {
        float4 a0 = make_float4(0, 0, 0, 0), a1 = a0;
        if (brow + arow < M)      a0 = *(const float4*)&A[(size_t)(brow + arow) * K + k0 + acol];
        if (brow + arow + 64 < M) a1 = *(const float4*)&A[(size_t)(brow + arow + 64) * K + k0 + acol];
        As[acol + 0][arow] = a0.x; As[acol + 1][arow] = a0.y;
        As[acol + 2][arow] = a0.z; As[acol + 3][arow] = a0.w;
        As[acol + 0][arow + 64] = a1.x; As[acol + 1][arow + 64] = a1.y;
        As[acol + 2][arow + 64] = a1.z; As[acol + 3][arow + 64] = a1.w;

        *(float4*)&Bs[brw][bcl]     = *(const float4*)&B[(size_t)(k0 + brw) * Nc + bcol + bcl];
        *(float4*)&Bs[brw + 8][bcl] = *(const float4*)&B[(size_t)(k0 + brw + 8) * Nc + bcol + bcl];
        __syncthreads();

#pragma unroll
        for (int kk = 0; kk < 16; kk++) {
            float a[8], b[8];
            *(float4*)&a[0] = *(float4*)&As[kk][ty * 8];
            *(float4*)&a[4] = *(float4*)&As[kk][ty * 8 + 4];
            *(float4*)&b[0] = *(float4*)&Bs[kk][tx * 8];
            *(float4*)&b[4] = *(float4*)&Bs[kk][tx * 8 + 4];
#pragma unroll
            for (int i = 0; i < 8; i++)
#pragma unroll
                for (int j = 0; j < 8; j++) acc[i][j] += a[i] * b[j];
        }
        __syncthreads();
    }

#pragma unroll
    for (int i = 0; i < 8; i++) {
        int r = brow + ty * 8 + i;
        if (r >= M) continue;
#pragma unroll
        for (int j = 0; j < 8; j++) {
            int c = bcol + tx * 8 + j;
            float v = acc[i][j] + (bias ? bias[c] : 0.f);
            if (doRelu) v = fmaxf(v, 0.f);
            C[(size_t)r * Nc + c] = v;
        }
    }
}

// ---------------- GCN gather (CSR): out[d] = dinv[d]*(Σ dinv[s]h[s] + dinv[d]h[d]) + b
// threads_per_node = C/4; block = 128 threads
__global__ void __launch_bounds__(128) k_gcn_gather(
    int Hid, int Oid, const float* __restrict__ bias, int C, int doRelu)
{
    int tpn = C >> 2;
    int npb = 128 / tpn;
    int local = threadIdx.x / tpn;
    int lane  = threadIdx.x - local * tpn;
    int n = blockIdx.x * npb + local;
    if (n >= NN) return;
    int c = lane * 4;
    const float* H = buf(Hid);
    float* O = buf(Oid);

    float4 hv = *(const float4*)&H[(size_t)n * C + c];
    float dn = g_dinv[n];
    float4 acc;
    acc.x = hv.x * dn; acc.y = hv.y * dn; acc.z = hv.z * dn; acc.w = hv.w * dn;

    int start = g_rowptr[n], end = g_rowptr[n + 1];
    for (int i = start; i < end; i++) {
        int s = g_col[i];
        float w = g_dinv[s];
        float4 v = *(const float4*)&H[(size_t)s * C + c];
        acc.x += v.x * w; acc.y += v.y * w; acc.z += v.z * w; acc.w += v.w * w;
    }
    float4 o;
    o.x = acc.x * dn + bias[c + 0];
    o.y = acc.y * dn + bias[c + 1];
    o.z = acc.z * dn + bias[c + 2];
    o.w = acc.w * dn + bias[c + 3];
    if (doRelu) {
        o.x = fmaxf(o.x, 0.f); o.y = fmaxf(o.y, 0.f);
        o.z = fmaxf(o.z, 0.f); o.w = fmaxf(o.w, 0.f);
    }
    *(float4*)&O[(size_t)n * C + c] = o;
}

// ---------------- GAT --------------------------------------------------------
// attention scores per (node, head): warp reduction over 128 channels
__global__ void k_att(const float* __restrict__ attS, const float* __restrict__ attD) {
    int gw = (blockIdx.x * blockDim.x + threadIdx.x) >> 5;
    int lane = threadIdx.x & 31;
    if (gw >= NN * HEADS) return;
    int n = gw / HEADS, h = gw - n * HEADS;
    const float* hp = &g_h2[(size_t)n * C2 + h * 128];
    const float* as = &attS[h * 128];
    const float* ad = &attD[h * 128];
    float ss = 0.f, sd = 0.f;
#pragma unroll
    for (int c = lane; c < 128; c += 32) {
        float v = hp[c];
        ss += v * as[c];
        sd += v * ad[c];
    }
#pragma unroll
    for (int o = 16; o; o >>= 1) {
        ss += __shfl_xor_sync(0xffffffffu, ss, o);
        sd += __shfl_xor_sync(0xffffffffu, sd, o);
    }
    if (lane == 0) {
        g_asrc[gw] = ss;
        g_adst[gw] = sd;
    }
}

// fused GAT softmax + aggregation: one block (128 thr) per dst node
#define GCHUNK 64
__global__ void __launch_bounds__(128) k_gat_fused(const float* __restrict__ gat_b) {
    int n = blockIdx.x;
    int tid = threadIdx.x;
    int lane = tid & 31, warp = tid >> 5;
    int start = g_rowptr[n], end = g_rowptr[n + 1];

    float adst[HEADS], selfe[HEADS];
#pragma unroll
    for (int h = 0; h < HEADS; h++) {
        adst[h]  = g_adst[n * HEADS + h];
        selfe[h] = lrelu(g_asrc[n * HEADS + h] + adst[h]);
    }

    __shared__ float s_red[4 * HEADS];
    __shared__ int   s_src[GCHUNK];
    __shared__ float s_al [GCHUNK * HEADS];

    // ---- pass 1: max ----
    float mx[HEADS];
#pragma unroll
    for (int h = 0; h < HEADS; h++) mx[h] = selfe[h];
    for (int i = start + tid; i < end; i += 128) {
        int s = g_col[i];
#pragma unroll
        for (int h = 0; h < HEADS; h++)
            mx[h] = fmaxf(mx[h], lrelu(g_asrc[s * HEADS + h] + adst[h]));
    }
#pragma unroll
    for (int h = 0; h < HEADS; h++)
#pragma unroll
        for (int o = 16; o; o >>= 1) mx[h] = fmaxf(mx[h], __shfl_xor_sync(0xffffffffu, mx[h], o));
    if (lane == 0)
#pragma unroll
        for (int h = 0; h < HEADS; h++) s_red[warp * HEADS + h] = mx[h];
    __syncthreads();
    float m[HEADS];
#pragma unroll
    for (int h = 0; h < HEADS; h++)
        m[h] = fmaxf(fmaxf(s_red[0 * HEADS + h], s_red[1 * HEADS + h]),
                     fmaxf(s_red[2 * HEADS + h], s_red[3 * HEADS + h]));
    __syncthreads();

    // ---- pass 2: z = sum of exp ----
    float zz[HEADS];
#pragma unroll
    for (int h = 0; h < HEADS; h++) zz[h] = (tid == 0) ? __expf(selfe[h] - m[h]) : 0.f;
    for (int i = start + tid; i < end; i += 128) {
        int s = g_col[i];
#pragma unroll
        for (int h = 0; h < HEADS; h++)
            zz[h] += __expf(lrelu(g_asrc[s * HEADS + h] + adst[h]) - m[h]);
    }
#pragma unroll
    for (int h = 0; h < HEADS; h++)
#pragma unroll
        for (int o = 16; o; o >>= 1) zz[h] += __shfl_xor_sync(0xffffffffu, zz[h], o);
    if (lane == 0)
#pragma unroll
        for (int h = 0; h < HEADS; h++) s_red[warp * HEADS + h] = zz[h];
    __syncthreads();
    float z[HEADS];
#pragma unroll
    for (int h = 0; h < HEADS; h++)
        z[h] = s_red[0 * HEADS + h] + s_red[1 * HEADS + h] + s_red[2 * HEADS + h] + s_red[3 * HEADS + h];
    __syncthreads();

    // ---- pass 3: aggregate channels ----
    int c = tid * 4;          // 0..508
    int hc = c >> 7;          // head of my channels
    float4 hv = *(const float4*)&g_h2[(size_t)n * C2 + c];
    float wself = __expf(selfe[hc] - m[hc]);
    float4 acc;
    acc.x = hv.x * wself; acc.y = hv.y * wself; acc.z = hv.z * wself; acc.w = hv.w * wself;

    for (int base = start; base < end; base += GCHUNK) {
        int cnt = min(GCHUNK, end - base);
        if (tid < cnt) {
            int s = g_col[base + tid];
            s_src[tid] = s;
#pragma unroll
            for (int h = 0; h < HEADS; h++)
                s_al[tid * HEADS + h] = __expf(lrelu(g_asrc[s * HEADS + h] + adst[h]) - m[h]);
        }
        __syncthreads();
        for (int j = 0; j < cnt; j++) {
            int s = s_src[j];
            float a = s_al[j * HEADS + hc];
            float4 v = *(const float4*)&g_h2[(size_t)s * C2 + c];
            acc.x += v.x * a; acc.y += v.y * a; acc.z += v.z * a; acc.w += v.w * a;
        }
        __syncthreads();
    }

    float rz = 1.0f / z[hc];
    float4 o;
    o.x = acc.x * rz + gat_b[c + 0];
    o.y = acc.y * rz + gat_b[c + 1];
    o.z = acc.z * rz + gat_b[c + 2];
    o.w = acc.w * rz + gat_b[c + 3];
    *(float4*)&g_gat[(size_t)n * C2 + c] = o;
}

// ---------------- LayerNorm (one block of 128 threads per node) --------------
__global__ void k_ln(int Xid, int Yid, const float* __restrict__ gw,
                     const float* __restrict__ bw, int C, int ldY, int doRelu)
{
    int n = blockIdx.x;
    const float* x = buf(Xid) + (size_t)n * C;
    float* y = buf(Yid) + (size_t)n * ldY;
    int tid = threadIdx.x, lane = tid & 31, warp = tid >> 5;

    float s = 0.f, s2 = 0.f;
    for (int c = tid; c < C; c += 128) {
        float v = x[c];
        s += v; s2 += v * v;
    }
#pragma unroll
    for (int o = 16; o; o >>= 1) {
        s  += __shfl_xor_sync(0xffffffffu, s, o);
        s2 += __shfl_xor_sync(0xffffffffu, s2, o);
    }
    __shared__ float shs[4], shs2[4], smu, sinv;
    if (lane == 0) { shs[warp] = s; shs2[warp] = s2; }
    __syncthreads();
    if (tid == 0) {
        float S = shs[0] + shs[1] + shs[2] + shs[3];
        float S2 = shs2[0] + shs2[1] + shs2[2] + shs2[3];
        float mu = S / C;
        float var = S2 / C - mu * mu;
        smu = mu;
        sinv = rsqrtf(var + 1e-5f);
    }
    __syncthreads();
    float mu = smu, inv = sinv;
    for (int c = tid; c < C; c += 128) {
        float v = (x[c] - mu) * inv * gw[c] + bw[c];
        if (doRelu) v = fmaxf(v, 0.f);
        y[c] = v;
    }
}

// copy x into the concat buffer tail
__global__ void k_catx(const float* __restrict__ x) {
    int idx = blockIdx.x * blockDim.x + threadIdx.x;
    if (idx >= NN * C1) return;
    int n = idx / C1, c = idx - n * C1;
    g_cat[(size_t)n * CCAT + C3 + c] = x[idx];
}

// final MLP layer: [N,128] @ [128,2] + b. One warp per node.
__global__ void k_out(const float* __restrict__ w2, const float* __restrict__ b2,
                      float* __restrict__ out)
{
    int gw = (blockIdx.x * blockDim.x + threadIdx.x) >> 5;
    int lane = threadIdx.x & 31;
    if (gw >= NN) return;
    const float* hp = &g_mh[(size_t)gw * CM];
    float a0 = 0.f, a1 = 0.f;
#pragma unroll
    for (int c = lane; c < CM; c += 32) {
        float v = hp[c];
        a0 += v * w2[c * 2];
        a1 += v * w2[c * 2 + 1];
    }
#pragma unroll
    for (int o = 16; o; o >>= 1) {
        a0 += __shfl_xor_sync(0xffffffffu, a0, o);
        a1 += __shfl_xor_sync(0xffffffffu, a1, o);
    }
    if (lane == 0) {
        out[gw * 2 + 0] = a0 + b2[0];
        out[gw * 2 + 1] = a1 + b2[1];
    }
}

// ---------------- launch -----------------------------------------------------
static inline int cdiv(int a, int b) { return (a + b - 1) / b; }

extern "C" void kernel_launch(void* const* d_in, const int* in_sizes, int n_in,
                              void* d_out, int out_size)
{
    (void)in_sizes; (void)n_in; (void)out_size;
    const float* x      = (const float*)d_in[0];
    const int*   ei     = (const int*)d_in[1];        // int32
    const float* gcn1_w = (const float*)d_in[2];
    const float* gcn1_b = (const float*)d_in[3];
    const float* gat_w  = (const float*)d_in[4];
    const float* att_s  = (const float*)d_in[5];
    const float* att_d  = (const float*)d_in[6];
    const float* gat_b  = (const float*)d_in[7];
    const float* n1_g   = (const float*)d_in[8];
    const float* n1_b   = (const float*)d_in[9];
    const float* gcn2_w = (const float*)d_in[10];
    const float* gcn2_b = (const float*)d_in[11];
    const float* n2_g   = (const float*)d_in[12];
    const float* n2_b   = (const float*)d_in[13];
    const float* mlp_w1 = (const float*)d_in[14];
    const float* mlp_b1 = (const float*)d_in[15];
    const float* mlp_w2 = (const float*)d_in[16];
    const float* mlp_b2 = (const float*)d_in[17];
    float* out = (float*)d_out;

    const int T = 256;
    int mblk = cdiv(NN, 128);   // 391

    // CSR build (by dst) + dinv
    k_zero <<<cdiv(NN, T), T>>>();
    k_count<<<cdiv(EE, T), T>>>(ei);
    k_scan <<<1, 1024>>>();
    k_fill <<<cdiv(EE, T), T>>>(ei);

    // GCN1: h1 = x@W1; gather + bias + relu -> g1
    k_sgemm<<<dim3(1, mblk), T>>>(x, -1, gcn1_w, nullptr, ID_H1, NN, C1, C1, 0);
    k_gcn_gather<<<NN / 4, 128>>>(ID_H1, ID_G1, gcn1_b, C1, 1);

    // GAT: h2 = g1@Wgat; scores; fused softmax+aggregate -> gat
    k_sgemm<<<dim3(C2 / 128, mblk), T>>>(nullptr, ID_G1, gat_w, nullptr, ID_H2, NN, C2, C1, 0);
    k_att<<<cdiv(NN * HEADS * 32, T), T>>>(att_s, att_d);
    k_gat_fused<<<NN, 128>>>(gat_b);

    // LN1 (in place)
    k_ln<<<NN, 128>>>(ID_GAT, ID_GAT, n1_g, n1_b, C2, C2, 0);

    // GCN2: h3 = gat@W2; gather + bias -> g2
    k_sgemm<<<dim3(C3 / 128, mblk), T>>>(nullptr, ID_GAT, gcn2_w, nullptr, ID_H3, NN, C3, C2, 0);
    k_gcn_gather<<<NN / 2, 128>>>(ID_H3, ID_G2, gcn2_b, C3, 0);

    // LN2 + relu into concat buffer; append x
    k_ln<<<NN, 128>>>(ID_G2, ID_CAT, n2_g, n2_b, C3, CCAT, 1);
    k_catx<<<cdiv(NN * C1, T), T>>>(x);

    // MLP
    k_sgemm<<<dim3(CM / 128, mblk), T>>>(nullptr, ID_CAT, mlp_w1, mlp_b1, ID_MH, NN, CM, CCAT, 1);
    k_out<<<cdiv(NN * 32, T), T>>>(mlp_w2, mlp_b2, out);
}

// round 4
// speedup vs baseline: 3.1990x; 1.4589x over previous
#include <cuda_runtime.h>
#include <cstdint>

#define NN   50000
#define EE   800000
#define C1   128
#define C2   512
#define C3   256
#define CCAT 384
#define CM   128
#define HEADS 4

// ---------------- scratch (static device globals; no allocation) -------------
__device__ float    g_dinv[NN];
__device__ int      g_cnt[NN];
__device__ int      g_cursor[NN];
__device__ int      g_rowptr[NN + 1];
__device__ int      g_col[EE];          // src node per dst-sorted edge
__device__ float    g_h1 [NN*C1];
__device__ float    g_g1 [NN*C1];
__device__ float    g_h2 [NN*C2];
__device__ float    g_gat[NN*C2];
__device__ float    g_h3 [NN*C3];
__device__ float    g_g2 [NN*C3];
__device__ float    g_cat[NN*CCAT];
__device__ float    g_mh [NN*CM];
__device__ float    g_asrc[NN*HEADS];
__device__ float    g_adst[NN*HEADS];

#define ID_H1  0
#define ID_G1  1
#define ID_H2  2
#define ID_GAT 3
#define ID_H3  4
#define ID_G2  5
#define ID_CAT 6
#define ID_MH  7

__device__ __forceinline__ float* buf(int id) {
    switch (id) {
        case ID_H1:  return g_h1;
        case ID_G1:  return g_g1;
        case ID_H2:  return g_h2;
        case ID_GAT: return g_gat;
        case ID_H3:  return g_h3;
        case ID_G2:  return g_g2;
        case ID_CAT: return g_cat;
        default:     return g_mh;
    }
}

__device__ __forceinline__ float lrelu(float x) { return x >= 0.f ? x : 0.2f * x; }

__device__ __forceinline__ uint32_t tf32r(float f) {
    uint32_t u;
    asm("cvt.rna.tf32.f32 %0, %1;" : "=r"(u) : "f"(f));
    return u;
}

// ---------------- CSR build --------------------------------------------------
__global__ void k_zero() {
    int i = blockIdx.x * blockDim.x + threadIdx.x;
    if (i < NN) { g_cnt[i] = 0; g_cursor[i] = 0; }
}
__global__ void k_count(const int* __restrict__ ei) {
    int e = blockIdx.x * blockDim.x + threadIdx.x;
    if (e < EE) atomicAdd(&g_cnt[ei[EE + e]], 1);
}
__global__ void __launch_bounds__(1024) k_scan() {
    __shared__ int s[1024];
    __shared__ int carry;
    int tid = threadIdx.x;
    if (tid == 0) carry = 0;
    __syncthreads();
    for (int base = 0; base < NN; base += 1024) {
        int i = base + tid;
        int v = (i < NN) ? g_cnt[i] : 0;
        if (i < NN) g_dinv[i] = rsqrtf((float)(v + 1));
        s[tid] = v;
        __syncthreads();
#pragma unroll
        for (int off = 1; off < 1024; off <<= 1) {
            int t = (tid >= off) ? s[tid - off] : 0;
            __syncthreads();
            s[tid] += t;
            __syncthreads();
        }
        int c0 = carry;
        if (i < NN) g_rowptr[i] = c0 + s[tid] - v;
        int total = s[1023];
        __syncthreads();
        if (tid == 0) carry = c0 + total;
        __syncthreads();
    }
    if (tid == 0) g_rowptr[NN] = carry;
}
__global__ void k_fill(const int* __restrict__ ei) {
    int e = blockIdx.x * blockDim.x + threadIdx.x;
    if (e >= EE) return;
    int d = ei[EE + e];
    int pos = atomicAdd(&g_cursor[d], 1);
    g_col[g_rowptr[d] + pos] = ei[e];
}

// ---------------- TF32 tensor-core GEMM: C[M,Nc] = A[M,K]@B[K,Nc] (+bias,relu)
// block tile 128x128x16, 8 warps, warp tile 64x32 via m16n8k8 mma
#define PADS 4
__global__ void __launch_bounds__(256) k_sgemm(
    const float* __restrict__ Aext, int Aid,
    const float* __restrict__ B, const float* __restrict__ bias,
    int Cid, int M, int Nc, int K, int doRelu)
{
    __shared__ float As[16][128 + PADS];   // [k][m], tf32-rounded
    __shared__ float Bs[16][128 + PADS];   // [k][n], tf32-rounded
    const float* A = Aext ? Aext : buf(Aid);
    float* C = buf(Cid);

    int tid  = threadIdx.x;
    int lane = tid & 31;
    int w    = tid >> 5;
    int wm   = w >> 2;        // 0..1
    int wn   = w & 3;         // 0..3
    int m0   = wm * 64;
    int n0   = wn * 32;
    int brow = blockIdx.y * 128;
    int bcol = blockIdx.x * 128;

    int arow = tid >> 2;            // 0..63
    int acol = (tid & 3) * 4;
    int brw  = tid >> 5;            // 0..7
    int bcl  = (tid & 31) * 4;

    float acc[4][4][4];
#pragma unroll
    for (int i = 0; i < 4; i++)
#pragma unroll
        for (int j = 0; j < 4; j++)
#pragma unroll
            for (int r = 0; r < 4; r++) acc[i][j][r] = 0.f;

    int r  = lane >> 2;     // 0..7
    int cA = lane & 3;      // 0..3

    for (int k0 = 0; k0 < K; k0 += 16) {
        float4 a0 = make_float4(0, 0, 0, 0), a1 = a0;
        if (brow + arow < M)      a0 = *(const float4*)&A[(size_t)(brow + arow) * K + k0 + acol];
        if (brow + arow + 64 < M) a1 = *(const float4*)&A[(size_t)(brow + arow + 64) * K + k0 + acol];
        As[acol + 0][arow] = __uint_as_float(tf32r(a0.x));
        As[acol + 1][arow] = __uint_as_float(tf32r(a0.y));
        As[acol + 2][arow] = __uint_as_float(tf32r(a0.z));
        As[acol + 3][arow] = __uint_as_float(tf32r(a0.w));
        As[acol + 0][arow + 64] = __uint_as_float(tf32r(a1.x));
        As[acol + 1][arow + 64] = __uint_as_float(tf32r(a1.y));
        As[acol + 2][arow + 64] = __uint_as_float(tf32r(a1.z));
        As[acol + 3][arow + 64] = __uint_as_float(tf32r(a1.w));

        float4 b0 = *(const float4*)&B[(size_t)(k0 + brw) * Nc + bcol + bcl];
        float4 b1 = *(const float4*)&B[(size_t)(k0 + brw + 8) * Nc + bcol + bcl];
        Bs[brw][bcl + 0] = __uint_as_float(tf32r(b0.x));
        Bs[brw][bcl + 1] = __uint_as_float(tf32r(b0.y));
        Bs[brw][bcl + 2] = __uint_as_float(tf32r(b0.z));
        Bs[brw][bcl + 3] = __uint_as_float(tf32r(b0.w));
        Bs[brw + 8][bcl + 0] = __uint_as_float(tf32r(b1.x));
        Bs[brw + 8][bcl + 1] = __uint_as_float(tf32r(b1.y));
        Bs[brw + 8][bcl + 2] = __uint_as_float(tf32r(b1.z));
        Bs[brw + 8][bcl + 3] = __uint_as_float(tf32r(b1.w));
        __syncthreads();

#pragma unroll
        for (int ks = 0; ks < 16; ks += 8) {
            uint32_t af[4][4];
#pragma unroll
            for (int mi = 0; mi < 4; mi++) {
                int mrow = m0 + mi * 16 + r;
                af[mi][0] = __float_as_uint(As[ks + cA][mrow]);
                af[mi][1] = __float_as_uint(As[ks + cA][mrow + 8]);
                af[mi][2] = __float_as_uint(As[ks + cA + 4][mrow]);
                af[mi][3] = __float_as_uint(As[ks + cA + 4][mrow + 8]);
            }
            uint32_t bf[4][2];
#pragma unroll
            for (int ni = 0; ni < 4; ni++) {
                int ncol = n0 + ni * 8 + r;
                bf[ni][0] = __float_as_uint(Bs[ks + cA][ncol]);
                bf[ni][1] = __float_as_uint(Bs[ks + cA + 4][ncol]);
            }
#pragma unroll
            for (int mi = 0; mi < 4; mi++)
#pragma unroll
                for (int ni = 0; ni < 4; ni++) {
                    asm volatile(
                        "mma.sync.aligned.m16n8k8.row.col.f32.tf32.tf32.f32 "
                        "{%0,%1,%2,%3}, {%4,%5,%6,%7}, {%8,%9}, {%0,%1,%2,%3};"
                        : "+f"(acc[mi][ni][0]), "+f"(acc[mi][ni][1]),
                          "+f"(acc[mi][ni][2]), "+f"(acc[mi][ni][3])
                        : "r"(af[mi][0]), "r"(af[mi][1]), "r"(af[mi][2]), "r"(af[mi][3]),
                          "r"(bf[ni][0]), "r"(bf[ni][1]));
                }
        }
        __syncthreads();
    }

    // epilogue
#pragma unroll
    for (int mi = 0; mi < 4; mi++) {
        int row0 = brow + m0 + mi * 16 + (lane >> 2);
#pragma unroll
        for (int ni = 0; ni < 4; ni++) {
            int col = bcol + n0 + ni * 8 + 2 * (lane & 3);
            float bx = bias ? bias[col]     : 0.f;
            float by = bias ? bias[col + 1] : 0.f;
            float v0 = acc[mi][ni][0] + bx;
            float v1 = acc[mi][ni][1] + by;
            float v2 = acc[mi][ni][2] + bx;
            float v3 = acc[mi][ni][3] + by;
            if (doRelu) {
                v0 = fmaxf(v0, 0.f); v1 = fmaxf(v1, 0.f);
                v2 = fmaxf(v2, 0.f); v3 = fmaxf(v3, 0.f);
            }
            if (row0 < M) {
                C[(size_t)row0 * Nc + col]     = v0;
                C[(size_t)row0 * Nc + col + 1] = v1;
            }
            if (row0 + 8 < M) {
                C[(size_t)(row0 + 8) * Nc + col]     = v2;
                C[(size_t)(row0 + 8) * Nc + col + 1] = v3;
            }
        }
    }
}

// ---------------- GCN gather (CSR) ------------------------------------------
__global__ void __launch_bounds__(128) k_gcn_gather(
    int Hid, int Oid, const float* __restrict__ bias, int C, int doRelu)
{
    int tpn = C >> 2;
    int npb = 128 / tpn;
    int local = threadIdx.x / tpn;
    int lane  = threadIdx.x - local * tpn;
    int n = blockIdx.x * npb + local;
    if (n >= NN) return;
    int c = lane * 4;
    const float* H = buf(Hid);
    float* O = buf(Oid);

    float4 hv = *(const float4*)&H[(size_t)n * C + c];
    float dn = g_dinv[n];
    float4 acc;
    acc.x = hv.x * dn; acc.y = hv.y * dn; acc.z = hv.z * dn; acc.w = hv.w * dn;

    int start = g_rowptr[n], end = g_rowptr[n + 1];
    for (int i = start; i < end; i++) {
        int s = g_col[i];
        float wgt = g_dinv[s];
        float4 v = *(const float4*)&H[(size_t)s * C + c];
        acc.x += v.x * wgt; acc.y += v.y * wgt; acc.z += v.z * wgt; acc.w += v.w * wgt;
    }
    float4 o;
    o.x = acc.x * dn + bias[c + 0];
    o.y = acc.y * dn + bias[c + 1];
    o.z = acc.z * dn + bias[c + 2];
    o.w = acc.w * dn + bias[c + 3];
    if (doRelu) {
        o.x = fmaxf(o.x, 0.f); o.y = fmaxf(o.y, 0.f);
        o.z = fmaxf(o.z, 0.f); o.w = fmaxf(o.w, 0.f);
    }
    *(float4*)&O[(size_t)n * C + c] = o;
}

// ---------------- GAT --------------------------------------------------------
__global__ void k_att(const float* __restrict__ attS, const float* __restrict__ attD) {
    int gw = (blockIdx.x * blockDim.x + threadIdx.x) >> 5;
    int lane = threadIdx.x & 31;
    if (gw >= NN * HEADS) return;
    int n = gw / HEADS, h = gw - n * HEADS;
    const float* hp = &g_h2[(size_t)n * C2 + h * 128];
    const float* as = &attS[h * 128];
    const float* ad = &attD[h * 128];
    float ss = 0.f, sd = 0.f;
#pragma unroll
    for (int c = lane; c < 128; c += 32) {
        float v = hp[c];
        ss += v * as[c];
        sd += v * ad[c];
    }
#pragma unroll
    for (int o = 16; o; o >>= 1) {
        ss += __shfl_xor_sync(0xffffffffu, ss, o);
        sd += __shfl_xor_sync(0xffffffffu, sd, o);
    }
    if (lane == 0) {
        g_asrc[gw] = ss;
        g_adst[gw] = sd;
    }
}

#define GCHUNK 64
__global__ void __launch_bounds__(128) k_gat_fused(const float* __restrict__ gat_b) {
    int n = blockIdx.x;
    int tid = threadIdx.x;
    int lane = tid & 31, warp = tid >> 5;
    int start = g_rowptr[n], end = g_rowptr[n + 1];

    float adst[HEADS], selfe[HEADS];
#pragma unroll
    for (int h = 0; h < HEADS; h++) {
        adst[h]  = g_adst[n * HEADS + h];
        selfe[h] = lrelu(g_asrc[n * HEADS + h] + adst[h]);
    }

    __shared__ float s_red[4 * HEADS];
    __shared__ int   s_src[GCHUNK];
    __shared__ float s_al [GCHUNK * HEADS];

    float mx[HEADS];
#pragma unroll
    for (int h = 0; h < HEADS; h++) mx[h] = selfe[h];
    for (int i = start + tid; i < end; i += 128) {
        int s = g_col[i];
#pragma unroll
        for (int h = 0; h < HEADS; h++)
            mx[h] = fmaxf(mx[h], lrelu(g_asrc[s * HEADS + h] + adst[h]));
    }
#pragma unroll
    for (int h = 0; h < HEADS; h++)
#pragma unroll
        for (int o = 16; o; o >>= 1) mx[h] = fmaxf(mx[h], __shfl_xor_sync(0xffffffffu, mx[h], o));
    if (lane == 0)
#pragma unroll
        for (int h = 0; h < HEADS; h++) s_red[warp * HEADS + h] = mx[h];
    __syncthreads();
    float m[HEADS];
#pragma unroll
    for (int h = 0; h < HEADS; h++)
        m[h] = fmaxf(fmaxf(s_red[0 * HEADS + h], s_red[1 * HEADS + h]),
                     fmaxf(s_red[2 * HEADS + h], s_red[3 * HEADS + h]));
    __syncthreads();

    float zz[HEADS];
#pragma unroll
    for (int h = 0; h < HEADS; h++) zz[h] = (tid == 0) ? __expf(selfe[h] - m[h]) : 0.f;
    for (int i = start + tid; i < end; i += 128) {
        int s = g_col[i];
#pragma unroll
        for (int h = 0; h < HEADS; h++)
            zz[h] += __expf(lrelu(g_asrc[s * HEADS + h] + adst[h]) - m[h]);
    }
#pragma unroll
    for (int h = 0; h < HEADS; h++)
#pragma unroll
        for (int o = 16; o; o >>= 1) zz[h] += __shfl_xor_sync(0xffffffffu, zz[h], o);
    if (lane == 0)
#pragma unroll
        for (int h = 0; h < HEADS; h++) s_red[warp * HEADS + h] = zz[h];
    __syncthreads();
    float z[HEADS];
#pragma unroll
    for (int h = 0; h < HEADS; h++)
        z[h] = s_red[0 * HEADS + h] + s_red[1 * HEADS + h] + s_red[2 * HEADS + h] + s_red[3 * HEADS + h];
    __syncthreads();

    int c = tid * 4;
    int hc = c >> 7;
    float4 hv = *(const float4*)&g_h2[(size_t)n * C2 + c];
    float wself = __expf(selfe[hc] - m[hc]);
    float4 acc;
    acc.x = hv.x * wself; acc.y = hv.y * wself; acc.z = hv.z * wself; acc.w = hv.w * wself;

    for (int base = start; base < end; base += GCHUNK) {
        int cnt = min(GCHUNK, end - base);
        if (tid < cnt) {
            int s = g_col[base + tid];
            s_src[tid] = s;
#pragma unroll
            for (int h = 0; h < HEADS; h++)
                s_al[tid * HEADS + h] = __expf(lrelu(g_asrc[s * HEADS + h] + adst[h]) - m[h]);
        }
        __syncthreads();
        for (int j = 0; j < cnt; j++) {
            int s = s_src[j];
            float a = s_al[j * HEADS + hc];
            float4 v = *(const float4*)&g_h2[(size_t)s * C2 + c];
            acc.x += v.x * a; acc.y += v.y * a; acc.z += v.z * a; acc.w += v.w * a;
        }
        __syncthreads();
    }

    float rz = 1.0f / z[hc];
    float4 o;
    o.x = acc.x * rz + gat_b[c + 0];
    o.y = acc.y * rz + gat_b[c + 1];
    o.z = acc.z * rz + gat_b[c + 2];
    o.w = acc.w * rz + gat_b[c + 3];
    *(float4*)&g_gat[(size_t)n * C2 + c] = o;
}

// ---------------- LayerNorm --------------------------------------------------
__global__ void k_ln(int Xid, int Yid, const float* __restrict__ gw,
                     const float* __restrict__ bw, int C, int ldY, int doRelu)
{
    int n = blockIdx.x;
    const float* x = buf(Xid) + (size_t)n * C;
    float* y = buf(Yid) + (size_t)n * ldY;
    int tid = threadIdx.x, lane = tid & 31, warp = tid >> 5;

    float s = 0.f, s2 = 0.f;
    for (int c = tid; c < C; c += 128) {
        float v = x[c];
        s += v; s2 += v * v;
    }
#pragma unroll
    for (int o = 16; o; o >>= 1) {
        s  += __shfl_xor_sync(0xffffffffu, s, o);
        s2 += __shfl_xor_sync(0xffffffffu, s2, o);
    }
    __shared__ float shs[4], shs2[4], smu, sinv;
    if (lane == 0) { shs[warp] = s; shs2[warp] = s2; }
    __syncthreads();
    if (tid == 0) {
        float S = shs[0] + shs[1] + shs[2] + shs[3];
        float S2 = shs2[0] + shs2[1] + shs2[2] + shs2[3];
        float mu = S / C;
        float var = S2 / C - mu * mu;
        smu = mu;
        sinv = rsqrtf(var + 1e-5f);
    }
    __syncthreads();
    float mu = smu, inv = sinv;
    for (int c = tid; c < C; c += 128) {
        float v = (x[c] - mu) * inv * gw[c] + bw[c];
        if (doRelu) v = fmaxf(v, 0.f);
        y[c] = v;
    }
}

__global__ void k_catx(const float* __restrict__ x) {
    int idx = blockIdx.x * blockDim.x + threadIdx.x;
    if (idx >= NN * C1) return;
    int n = idx / C1, c = idx - n * C1;
    g_cat[(size_t)n * CCAT + C3 + c] = x[idx];
}

__global__ void k_out(const float* __restrict__ w2, const float* __restrict__ b2,
                      float* __restrict__ out)
{
    int gw = (blockIdx.x * blockDim.x + threadIdx.x) >> 5;
    int lane = threadIdx.x & 31;
    if (gw >= NN) return;
    const float* hp = &g_mh[(size_t)gw * CM];
    float a0 = 0.f, a1 = 0.f;
#pragma unroll
    for (int c = lane; c < CM; c += 32) {
        float v = hp[c];
        a0 += v * w2[c * 2];
        a1 += v * w2[c * 2 + 1];
    }
#pragma unroll
    for (int o = 16; o; o >>= 1) {
        a0 += __shfl_xor_sync(0xffffffffu, a0, o);
        a1 += __shfl_xor_sync(0xffffffffu, a1, o);
    }
    if (lane == 0) {
        out[gw * 2 + 0] = a0 + b2[0];
        out[gw * 2 + 1] = a1 + b2[1];
    }
}

// ---------------- launch -----------------------------------------------------
static inline int cdiv(int a, int b) { return (a + b - 1) / b; }

extern "C" void kernel_launch(void* const* d_in, const int* in_sizes, int n_in,
                              void* d_out, int out_size)
{
    (void)in_sizes; (void)n_in; (void)out_size;
    const float* x      = (const float*)d_in[0];
    const int*   ei     = (const int*)d_in[1];
    const float* gcn1_w = (const float*)d_in[2];
    const float* gcn1_b = (const float*)d_in[3];
    const float* gat_w  = (const float*)d_in[4];
    const float* att_s  = (const float*)d_in[5];
    const float* att_d  = (const float*)d_in[6];
    const float* gat_b  = (const float*)d_in[7];
    const float* n1_g   = (const float*)d_in[8];
    const float* n1_b   = (const float*)d_in[9];
    const float* gcn2_w = (const float*)d_in[10];
    const float* gcn2_b = (const float*)d_in[11];
    const float* n2_g   = (const float*)d_in[12];
    const float* n2_b   = (const float*)d_in[13];
    const float* mlp_w1 = (const float*)d_in[14];
    const float* mlp_b1 = (const float*)d_in[15];
    const float* mlp_w2 = (const float*)d_in[16];
    const float* mlp_b2 = (const float*)d_in[17];
    float* out = (float*)d_out;

    const int T = 256;
    int mblk = cdiv(NN, 128);

    // CSR build
    k_zero <<<cdiv(NN, T), T>>>();
    k_count<<<cdiv(EE, T), T>>>(ei);
    k_scan <<<1, 1024>>>();
    k_fill <<<cdiv(EE, T), T>>>(ei);

    // GCN1
    k_sgemm<<<dim3(1, mblk), T>>>(x, -1, gcn1_w, nullptr, ID_H1, NN, C1, C1, 0);
    k_gcn_gather<<<NN / 4, 128>>>(ID_H1, ID_G1, gcn1_b, C1, 1);

    // GAT
    k_sgemm<<<dim3(C2 / 128, mblk), T>>>(nullptr, ID_G1, gat_w, nullptr, ID_H2, NN, C2, C1, 0);
    k_att<<<cdiv(NN * HEADS * 32, T), T>>>(att_s, att_d);
    k_gat_fused<<<NN, 128>>>(gat_b);

    // LN1
    k_ln<<<NN, 128>>>(ID_GAT, ID_GAT, n1_g, n1_b, C2, C2, 0);

    // GCN2
    k_sgemm<<<dim3(C3 / 128, mblk), T>>>(nullptr, ID_GAT, gcn2_w, nullptr, ID_H3, NN, C3, C2, 0);
    k_gcn_gather<<<NN / 2, 128>>>(ID_H3, ID_G2, gcn2_b, C3, 0);

    // LN2 + concat
    k_ln<<<NN, 128>>>(ID_G2, ID_CAT, n2_g, n2_b, C3, CCAT, 1);
    k_catx<<<cdiv(NN * C1, T), T>>>(x);

    // MLP
    k_sgemm<<<dim3(CM / 128, mblk), T>>>(nullptr, ID_CAT, mlp_w1, mlp_b1, ID_MH, NN, CM, CCAT, 1);
    k_out<<<cdiv(NN * 32, T), T>>>(mlp_w2, mlp_b2, out);
}

// round 5
// speedup vs baseline: 3.4931x; 1.0919x over previous
#include <cuda_runtime.h>
#include <cstdint>

#define NN   50000
#define EE   800000
#define C1   128
#define C2   512
#define C3   256
#define CCAT 384
#define CM   128
#define HEADS 4

// ---------------- scratch (static device globals; no allocation) -------------
__device__ float    g_dinv[NN];
__device__ int      g_cnt[NN];
__device__ int      g_cursor[NN];
__device__ int      g_rowptr[NN + 1];
__device__ int      g_col[EE];          // src node per dst-sorted edge
__device__ float    g_h1 [NN*C1];
__device__ float    g_g1 [NN*C1];
__device__ float    g_h2 [NN*C2];
__device__ float    g_gat[NN*C2];
__device__ float    g_h3 [NN*C3];
__device__ float    g_g2 [NN*C3];
__device__ float    g_cat[NN*CCAT];
__device__ float    g_mh [NN*CM];
__device__ float    g_asrc[NN*HEADS];
__device__ float    g_adst[NN*HEADS];

#define ID_H1  0
#define ID_G1  1
#define ID_H2  2
#define ID_GAT 3
#define ID_H3  4
#define ID_G2  5
#define ID_CAT 6
#define ID_MH  7

__device__ __forceinline__ float* buf(int id) {
    switch (id) {
        case ID_H1:  return g_h1;
        case ID_G1:  return g_g1;
        case ID_H2:  return g_h2;
        case ID_GAT: return g_gat;
        case ID_H3:  return g_h3;
        case ID_G2:  return g_g2;
        case ID_CAT: return g_cat;
        default:     return g_mh;
    }
}

__device__ __forceinline__ float lrelu(float x) { return x >= 0.f ? x : 0.2f * x; }

__device__ __forceinline__ uint32_t tf32r(float f) {
    uint32_t u;
    asm("cvt.rna.tf32.f32 %0, %1;" : "=r"(u) : "f"(f));
    return u;
}

// ---------------- CSR build --------------------------------------------------
__global__ void k_zero() {
    int i = blockIdx.x * blockDim.x + threadIdx.x;
    if (i < NN) { g_cnt[i] = 0; g_cursor[i] = 0; }
}
__global__ void k_count(const int* __restrict__ ei) {
    int e = blockIdx.x * blockDim.x + threadIdx.x;
    if (e < EE) atomicAdd(&g_cnt[ei[EE + e]], 1);
}
__global__ void __launch_bounds__(1024) k_scan() {
    __shared__ int s[1024];
    __shared__ int carry;
    int tid = threadIdx.x;
    if (tid == 0) carry = 0;
    __syncthreads();
    for (int base = 0; base < NN; base += 1024) {
        int i = base + tid;
        int v = (i < NN) ? g_cnt[i] : 0;
        if (i < NN) g_dinv[i] = rsqrtf((float)(v + 1));
        s[tid] = v;
        __syncthreads();
#pragma unroll
        for (int off = 1; off < 1024; off <<= 1) {
            int t = (tid >= off) ? s[tid - off] : 0;
            __syncthreads();
            s[tid] += t;
            __syncthreads();
        }
        int c0 = carry;
        if (i < NN) g_rowptr[i] = c0 + s[tid] - v;
        int total = s[1023];
        __syncthreads();
        if (tid == 0) carry = c0 + total;
        __syncthreads();
    }
    if (tid == 0) g_rowptr[NN] = carry;
}
__global__ void k_fill(const int* __restrict__ ei) {
    int e = blockIdx.x * blockDim.x + threadIdx.x;
    if (e >= EE) return;
    int d = ei[EE + e];
    int pos = atomicAdd(&g_cursor[d], 1);
    g_col[g_rowptr[d] + pos] = ei[e];
}

// ---------------- TF32 tensor-core GEMM with register double-buffering -------
// block tile 128x128x16, 8 warps, warp tile 64x32 via m16n8k8 mma
#define SROW 136   // smem row stride: 136 mod 32 = 8 -> conflict-free frag loads
__global__ void __launch_bounds__(256) k_sgemm(
    const float* __restrict__ Aext, int Aid,
    const float* __restrict__ B, const float* __restrict__ bias,
    int Cid, int M, int Nc, int K, int doRelu)
{
    __shared__ float As[16][SROW];   // [k][m], tf32-rounded
    __shared__ float Bs[16][SROW];   // [k][n], tf32-rounded
    const float* A = Aext ? Aext : buf(Aid);
    float* C = buf(Cid);

    int tid  = threadIdx.x;
    int lane = tid & 31;
    int w    = tid >> 5;
    int wm   = w >> 2;        // 0..1
    int wn   = w & 3;         // 0..3
    int m0   = wm * 64;
    int n0   = wn * 32;
    int brow = blockIdx.y * 128;
    int bcol = blockIdx.x * 128;

    int arow = tid >> 2;            // 0..63
    int acol = (tid & 3) * 4;
    int brw  = tid >> 5;            // 0..7
    int bcl  = (tid & 31) * 4;

    float acc[4][4][4];
#pragma unroll
    for (int i = 0; i < 4; i++)
#pragma unroll
        for (int j = 0; j < 4; j++)
#pragma unroll
            for (int r = 0; r < 4; r++) acc[i][j][r] = 0.f;

    int r  = lane >> 2;     // 0..7
    int cA = lane & 3;      // 0..3

    bool rowOk0 = (brow + arow < M);
    bool rowOk1 = (brow + arow + 64 < M);
    const float* Ap0 = &A[(size_t)(brow + arow) * K + acol];
    const float* Ap1 = &A[(size_t)(brow + arow + 64) * K + acol];
    const float* Bp0 = &B[(size_t)brw * Nc + bcol + bcl];
    const float* Bp1 = &B[(size_t)(brw + 8) * Nc + bcol + bcl];

    // prologue: load first tile into regs
    float4 pa0 = make_float4(0, 0, 0, 0), pa1 = pa0;
    if (rowOk0) pa0 = *(const float4*)&Ap0[0];
    if (rowOk1) pa1 = *(const float4*)&Ap1[0];
    float4 pb0 = *(const float4*)&Bp0[0];
    float4 pb1 = *(const float4*)&Bp1[(size_t)0];

    for (int k0 = 0; k0 < K; k0 += 16) {
        // commit regs -> smem (tf32 round)
        As[acol + 0][arow] = __uint_as_float(tf32r(pa0.x));
        As[acol + 1][arow] = __uint_as_float(tf32r(pa0.y));
        As[acol + 2][arow] = __uint_as_float(tf32r(pa0.z));
        As[acol + 3][arow] = __uint_as_float(tf32r(pa0.w));
        As[acol + 0][arow + 64] = __uint_as_float(tf32r(pa1.x));
        As[acol + 1][arow + 64] = __uint_as_float(tf32r(pa1.y));
        As[acol + 2][arow + 64] = __uint_as_float(tf32r(pa1.z));
        As[acol + 3][arow + 64] = __uint_as_float(tf32r(pa1.w));
        Bs[brw][bcl + 0] = __uint_as_float(tf32r(pb0.x));
        Bs[brw][bcl + 1] = __uint_as_float(tf32r(pb0.y));
        Bs[brw][bcl + 2] = __uint_as_float(tf32r(pb0.z));
        Bs[brw][bcl + 3] = __uint_as_float(tf32r(pb0.w));
        Bs[brw + 8][bcl + 0] = __uint_as_float(tf32r(pb1.x));
        Bs[brw + 8][bcl + 1] = __uint_as_float(tf32r(pb1.y));
        Bs[brw + 8][bcl + 2] = __uint_as_float(tf32r(pb1.z));
        Bs[brw + 8][bcl + 3] = __uint_as_float(tf32r(pb1.w));
        __syncthreads();

        // issue next tile's global loads (in flight during compute)
        int kn = k0 + 16;
        if (kn < K) {
            pa0 = make_float4(0, 0, 0, 0); pa1 = pa0;
            if (rowOk0) pa0 = *(const float4*)&Ap0[kn];
            if (rowOk1) pa1 = *(const float4*)&Ap1[kn];
            pb0 = *(const float4*)&Bp0[(size_t)kn * Nc];
            pb1 = *(const float4*)&Bp1[(size_t)kn * Nc];
        }

#pragma unroll
        for (int ks = 0; ks < 16; ks += 8) {
            uint32_t af[4][4];
#pragma unroll
            for (int mi = 0; mi < 4; mi++) {
                int mrow = m0 + mi * 16 + r;
                af[mi][0] = __float_as_uint(As[ks + cA][mrow]);
                af[mi][1] = __float_as_uint(As[ks + cA][mrow + 8]);
                af[mi][2] = __float_as_uint(As[ks + cA + 4][mrow]);
                af[mi][3] = __float_as_uint(As[ks + cA + 4][mrow + 8]);
            }
            uint32_t bf[4][2];
#pragma unroll
            for (int ni = 0; ni < 4; ni++) {
                int ncol = n0 + ni * 8 + r;
                bf[ni][0] = __float_as_uint(Bs[ks + cA][ncol]);
                bf[ni][1] = __float_as_uint(Bs[ks + cA + 4][ncol]);
            }
#pragma unroll
            for (int mi = 0; mi < 4; mi++)
#pragma unroll
                for (int ni = 0; ni < 4; ni++) {
                    asm volatile(
                        "mma.sync.aligned.m16n8k8.row.col.f32.tf32.tf32.f32 "
                        "{%0,%1,%2,%3}, {%4,%5,%6,%7}, {%8,%9}, {%0,%1,%2,%3};"
                        : "+f"(acc[mi][ni][0]), "+f"(acc[mi][ni][1]),
                          "+f"(acc[mi][ni][2]), "+f"(acc[mi][ni][3])
                        : "r"(af[mi][0]), "r"(af[mi][1]), "r"(af[mi][2]), "r"(af[mi][3]),
                          "r"(bf[ni][0]), "r"(bf[ni][1]));
                }
        }
        __syncthreads();
    }

    // epilogue
#pragma unroll
    for (int mi = 0; mi < 4; mi++) {
        int row0 = brow + m0 + mi * 16 + (lane >> 2);
#pragma unroll
        for (int ni = 0; ni < 4; ni++) {
            int col = bcol + n0 + ni * 8 + 2 * (lane & 3);
            float bx = bias ? bias[col]     : 0.f;
            float by = bias ? bias[col + 1] : 0.f;
            float v0 = acc[mi][ni][0] + bx;
            float v1 = acc[mi][ni][1] + by;
            float v2 = acc[mi][ni][2] + bx;
            float v3 = acc[mi][ni][3] + by;
            if (doRelu) {
                v0 = fmaxf(v0, 0.f); v1 = fmaxf(v1, 0.f);
                v2 = fmaxf(v2, 0.f); v3 = fmaxf(v3, 0.f);
            }
            if (row0 < M) {
                C[(size_t)row0 * Nc + col]     = v0;
                C[(size_t)row0 * Nc + col + 1] = v1;
            }
            if (row0 + 8 < M) {
                C[(size_t)(row0 + 8) * Nc + col]     = v2;
                C[(size_t)(row0 + 8) * Nc + col + 1] = v3;
            }
        }
    }
}

// ---------------- GCN gather (CSR) ------------------------------------------
__global__ void __launch_bounds__(128) k_gcn_gather(
    int Hid, int Oid, const float* __restrict__ bias, int C, int doRelu)
{
    int tpn = C >> 2;
    int npb = 128 / tpn;
    int local = threadIdx.x / tpn;
    int lane  = threadIdx.x - local * tpn;
    int n = blockIdx.x * npb + local;
    if (n >= NN) return;
    int c = lane * 4;
    const float* H = buf(Hid);
    float* O = buf(Oid);

    float4 hv = *(const float4*)&H[(size_t)n * C + c];
    float dn = g_dinv[n];
    float4 acc;
    acc.x = hv.x * dn; acc.y = hv.y * dn; acc.z = hv.z * dn; acc.w = hv.w * dn;

    int start = g_rowptr[n], end = g_rowptr[n + 1];
    for (int i = start; i < end; i++) {
        int s = g_col[i];
        float wgt = g_dinv[s];
        float4 v = *(const float4*)&H[(size_t)s * C + c];
        acc.x += v.x * wgt; acc.y += v.y * wgt; acc.z += v.z * wgt; acc.w += v.w * wgt;
    }
    float4 o;
    o.x = acc.x * dn + bias[c + 0];
    o.y = acc.y * dn + bias[c + 1];
    o.z = acc.z * dn + bias[c + 2];
    o.w = acc.w * dn + bias[c + 3];
    if (doRelu) {
        o.x = fmaxf(o.x, 0.f); o.y = fmaxf(o.y, 0.f);
        o.z = fmaxf(o.z, 0.f); o.w = fmaxf(o.w, 0.f);
    }
    *(float4*)&O[(size_t)n * C + c] = o;
}

// ---------------- GAT --------------------------------------------------------
__global__ void k_att(const float* __restrict__ attS, const float* __restrict__ attD) {
    int gw = (blockIdx.x * blockDim.x + threadIdx.x) >> 5;
    int lane = threadIdx.x & 31;
    if (gw >= NN * HEADS) return;
    int n = gw / HEADS, h = gw - n * HEADS;
    const float* hp = &g_h2[(size_t)n * C2 + h * 128];
    const float* as = &attS[h * 128];
    const float* ad = &attD[h * 128];
    float ss = 0.f, sd = 0.f;
#pragma unroll
    for (int c = lane; c < 128; c += 32) {
        float v = hp[c];
        ss += v * as[c];
        sd += v * ad[c];
    }
#pragma unroll
    for (int o = 16; o; o >>= 1) {
        ss += __shfl_xor_sync(0xffffffffu, ss, o);
        sd += __shfl_xor_sync(0xffffffffu, sd, o);
    }
    if (lane == 0) {
        g_asrc[gw] = ss;
        g_adst[gw] = sd;
    }
}

#define GCHUNK 64
__global__ void __launch_bounds__(128) k_gat_fused(const float* __restrict__ gat_b) {
    int n = blockIdx.x;
    int tid = threadIdx.x;
    int lane = tid & 31, warp = tid >> 5;
    int start = g_rowptr[n], end = g_rowptr[n + 1];

    float adst[HEADS], selfe[HEADS];
#pragma unroll
    for (int h = 0; h < HEADS; h++) {
        adst[h]  = g_adst[n * HEADS + h];
        selfe[h] = lrelu(g_asrc[n * HEADS + h] + adst[h]);
    }

    __shared__ float s_red[4 * HEADS];
    __shared__ int   s_src[GCHUNK];
    __shared__ float s_al [GCHUNK * HEADS];

    float mx[HEADS];
#pragma unroll
    for (int h = 0; h < HEADS; h++) mx[h] = selfe[h];
    for (int i = start + tid; i < end; i += 128) {
        int s = g_col[i];
#pragma unroll
        for (int h = 0; h < HEADS; h++)
            mx[h] = fmaxf(mx[h], lrelu(g_asrc[s * HEADS + h] + adst[h]));
    }
#pragma unroll
    for (int h = 0; h < HEADS; h++)
#pragma unroll
        for (int o = 16; o; o >>= 1) mx[h] = fmaxf(mx[h], __shfl_xor_sync(0xffffffffu, mx[h], o));
    if (lane == 0)
#pragma unroll
        for (int h = 0; h < HEADS; h++) s_red[warp * HEADS + h] = mx[h];
    __syncthreads();
    float m[HEADS];
#pragma unroll
    for (int h = 0; h < HEADS; h++)
        m[h] = fmaxf(fmaxf(s_red[0 * HEADS + h], s_red[1 * HEADS + h]),
                     fmaxf(s_red[2 * HEADS + h], s_red[3 * HEADS + h]));
    __syncthreads();

    float zz[HEADS];
#pragma unroll
    for (int h = 0; h < HEADS; h++) zz[h] = (tid == 0) ? __expf(selfe[h] - m[h]) : 0.f;
    for (int i = start + tid; i < end; i += 128) {
        int s = g_col[i];
#pragma unroll
        for (int h = 0; h < HEADS; h++)
            zz[h] += __expf(lrelu(g_asrc[s * HEADS + h] + adst[h]) - m[h]);
    }
#pragma unroll
    for (int h = 0; h < HEADS; h++)
#pragma unroll
        for (int o = 16; o; o >>= 1) zz[h] += __shfl_xor_sync(0xffffffffu, zz[h], o);
    if (lane == 0)
#pragma unroll
        for (int h = 0; h < HEADS; h++) s_red[warp * HEADS + h] = zz[h];
    __syncthreads();
    float z[HEADS];
#pragma unroll
    for (int h = 0; h < HEADS; h++)
        z[h] = s_red[0 * HEADS + h] + s_red[1 * HEADS + h] + s_red[2 * HEADS + h] + s_red[3 * HEADS + h];
    __syncthreads();

    int c = tid * 4;
    int hc = c >> 7;
    float4 hv = *(const float4*)&g_h2[(size_t)n * C2 + c];
    float wself = __expf(selfe[hc] - m[hc]);
    float4 acc;
    acc.x = hv.x * wself; acc.y = hv.y * wself; acc.z = hv.z * wself; acc.w = hv.w * wself;

    for (int base = start; base < end; base += GCHUNK) {
        int cnt = min(GCHUNK, end - base);
        if (tid < cnt) {
            int s = g_col[base + tid];
            s_src[tid] = s;
#pragma unroll
            for (int h = 0; h < HEADS; h++)
                s_al[tid * HEADS + h] = __expf(lrelu(g_asrc[s * HEADS + h] + adst[h]) - m[h]);
        }
        __syncthreads();
        for (int j = 0; j < cnt; j++) {
            int s = s_src[j];
            float a = s_al[j * HEADS + hc];
            float4 v = *(const float4*)&g_h2[(size_t)s * C2 + c];
            acc.x += v.x * a; acc.y += v.y * a; acc.z += v.z * a; acc.w += v.w * a;
        }
        __syncthreads();
    }

    float rz = 1.0f / z[hc];
    float4 o;
    o.x = acc.x * rz + gat_b[c + 0];
    o.y = acc.y * rz + gat_b[c + 1];
    o.z = acc.z * rz + gat_b[c + 2];
    o.w = acc.w * rz + gat_b[c + 3];
    *(float4*)&g_gat[(size_t)n * C2 + c] = o;
}

// ---------------- LayerNorm --------------------------------------------------
__global__ void k_ln(int Xid, int Yid, const float* __restrict__ gw,
                     const float* __restrict__ bw, int C, int ldY, int doRelu)
{
    int n = blockIdx.x;
    const float* x = buf(Xid) + (size_t)n * C;
    float* y = buf(Yid) + (size_t)n * ldY;
    int tid = threadIdx.x, lane = tid & 31, warp = tid >> 5;

    float s = 0.f, s2 = 0.f;
    for (int c = tid; c < C; c += 128) {
        float v = x[c];
        s += v; s2 += v * v;
    }
#pragma unroll
    for (int o = 16; o; o >>= 1) {
        s  += __shfl_xor_sync(0xffffffffu, s, o);
        s2 += __shfl_xor_sync(0xffffffffu, s2, o);
    }
    __shared__ float shs[4], shs2[4], smu, sinv;
    if (lane == 0) { shs[warp] = s; shs2[warp] = s2; }
    __syncthreads();
    if (tid == 0) {
        float S = shs[0] + shs[1] + shs[2] + shs[3];
        float S2 = shs2[0] + shs2[1] + shs2[2] + shs2[3];
        float mu = S / C;
        float var = S2 / C - mu * mu;
        smu = mu;
        sinv = rsqrtf(var + 1e-5f);
    }
    __syncthreads();
    float mu = smu, inv = sinv;
    for (int c = tid; c < C; c += 128) {
        float v = (x[c] - mu) * inv * gw[c] + bw[c];
        if (doRelu) v = fmaxf(v, 0.f);
        y[c] = v;
    }
}

__global__ void k_catx(const float* __restrict__ x) {
    int idx = blockIdx.x * blockDim.x + threadIdx.x;
    if (idx >= NN * C1) return;
    int n = idx / C1, c = idx - n * C1;
    g_cat[(size_t)n * CCAT + C3 + c] = x[idx];
}

__global__ void k_out(const float* __restrict__ w2, const float* __restrict__ b2,
                      float* __restrict__ out)
{
    int gw = (blockIdx.x * blockDim.x + threadIdx.x) >> 5;
    int lane = threadIdx.x & 31;
    if (gw >= NN) return;
    const float* hp = &g_mh[(size_t)gw * CM];
    float a0 = 0.f, a1 = 0.f;
#pragma unroll
    for (int c = lane; c < CM; c += 32) {
        float v = hp[c];
        a0 += v * w2[c * 2];
        a1 += v * w2[c * 2 + 1];
    }
#pragma unroll
    for (int o = 16; o; o >>= 1) {
        a0 += __shfl_xor_sync(0xffffffffu, a0, o);
        a1 += __shfl_xor_sync(0xffffffffu, a1, o);
    }
    if (lane == 0) {
        out[gw * 2 + 0] = a0 + b2[0];
        out[gw * 2 + 1] = a1 + b2[1];
    }
}

// ---------------- launch -----------------------------------------------------
static inline int cdiv(int a, int b) { return (a + b - 1) / b; }

extern "C" void kernel_launch(void* const* d_in, const int* in_sizes, int n_in,
                              void* d_out, int out_size)
{
    (void)in_sizes; (void)n_in; (void)out_size;
    const float* x      = (const float*)d_in[0];
    const int*   ei     = (const int*)d_in[1];
    const float* gcn1_w = (const float*)d_in[2];
    const float* gcn1_b = (const float*)d_in[3];
    const float* gat_w  = (const float*)d_in[4];
    const float* att_s  = (const float*)d_in[5];
    const float* att_d  = (const float*)d_in[6];
    const float* gat_b  = (const float*)d_in[7];
    const float* n1_g   = (const float*)d_in[8];
    const float* n1_b   = (const float*)d_in[9];
    const float* gcn2_w = (const float*)d_in[10];
    const float* gcn2_b = (const float*)d_in[11];
    const float* n2_g   = (const float*)d_in[12];
    const float* n2_b   = (const float*)d_in[13];
    const float* mlp_w1 = (const float*)d_in[14];
    const float* mlp_b1 = (const float*)d_in[15];
    const float* mlp_w2 = (const float*)d_in[16];
    const float* mlp_b2 = (const float*)d_in[17];
    float* out = (float*)d_out;

    const int T = 256;
    int mblk = cdiv(NN, 128);

    // CSR build
    k_zero <<<cdiv(NN, T), T>>>();
    k_count<<<cdiv(EE, T), T>>>(ei);
    k_scan <<<1, 1024>>>();
    k_fill <<<cdiv(EE, T), T>>>(ei);

    // GCN1
    k_sgemm<<<dim3(1, mblk), T>>>(x, -1, gcn1_w, nullptr, ID_H1, NN, C1, C1, 0);
    k_gcn_gather<<<NN / 4, 128>>>(ID_H1, ID_G1, gcn1_b, C1, 1);

    // GAT
    k_sgemm<<<dim3(C2 / 128, mblk), T>>>(nullptr, ID_G1, gat_w, nullptr, ID_H2, NN, C2, C1, 0);
    k_att<<<cdiv(NN * HEADS * 32, T), T>>>(att_s, att_d);
    k_gat_fused<<<NN, 128>>>(gat_b);

    // LN1
    k_ln<<<NN, 128>>>(ID_GAT, ID_GAT, n1_g, n1_b, C2, C2, 0);

    // GCN2
    k_sgemm<<<dim3(C3 / 128, mblk), T>>>(nullptr, ID_GAT, gcn2_w, nullptr, ID_H3, NN, C3, C2, 0);
    k_gcn_gather<<<NN / 2, 128>>>(ID_H3, ID_G2, gcn2_b, C3, 0);

    // LN2 + concat
    k_ln<<<NN, 128>>>(ID_G2, ID_CAT, n2_g, n2_b, C3, CCAT, 1);
    k_catx<<<cdiv(NN * C1, T), T>>>(x);

    // MLP
    k_sgemm<<<dim3(CM / 128, mblk), T>>>(nullptr, ID_CAT, mlp_w1, mlp_b1, ID_MH, NN, CM, CCAT, 1);
    k_out<<<cdiv(NN * 32, T), T>>>(mlp_w2, mlp_b2, out);
}

// round 6
// speedup vs baseline: 3.5626x; 1.0199x over previous
#include <cuda_runtime.h>
#include <cstdint>

#define NN   50000
#define EE   800000
#define C1   128
#define C2   512
#define C3   256
#define CCAT 384
#define CM   128
#define HEADS 4

// ---------------- scratch (static device globals; no allocation) -------------
__device__ float    g_dinv[NN];
__device__ int      g_cnt[NN];
__device__ int      g_cursor[NN];
__device__ int      g_rowptr[NN + 1];
__device__ int      g_col[EE];          // src node per dst-sorted edge
__device__ float    g_h1 [NN*C1];
__device__ float    g_g1 [NN*C1];
__device__ float    g_h2 [NN*C2];
__device__ float    g_gat[NN*C2];
__device__ float    g_h3 [NN*C3];
__device__ float    g_g2 [NN*C3];
__device__ float    g_cat[NN*CCAT];
__device__ float    g_mh [NN*CM];
__device__ float    g_asrc[NN*HEADS];
__device__ float    g_adst[NN*HEADS];

#define ID_H1  0
#define ID_G1  1
#define ID_H2  2
#define ID_GAT 3
#define ID_H3  4
#define ID_G2  5
#define ID_CAT 6
#define ID_MH  7

__device__ __forceinline__ float* buf(int id) {
    switch (id) {
        case ID_H1:  return g_h1;
        case ID_G1:  return g_g1;
        case ID_H2:  return g_h2;
        case ID_GAT: return g_gat;
        case ID_H3:  return g_h3;
        case ID_G2:  return g_g2;
        case ID_CAT: return g_cat;
        default:     return g_mh;
    }
}

__device__ __forceinline__ float lrelu(float x) { return x >= 0.f ? x : 0.2f * x; }

__device__ __forceinline__ uint32_t tf32r(float f) {
    uint32_t u;
    asm("cvt.rna.tf32.f32 %0, %1;" : "=r"(u) : "f"(f));
    return u;
}

__device__ __forceinline__ void cpasync16(uint32_t dst, const void* src, int sz) {
    asm volatile("cp.async.cg.shared.global [%0], [%1], 16, %2;\n"
                 :: "r"(dst), "l"(src), "r"(sz));
}

// ---------------- CSR build --------------------------------------------------
__global__ void k_zero() {
    int i = blockIdx.x * blockDim.x + threadIdx.x;
    if (i < NN) { g_cnt[i] = 0; g_cursor[i] = 0; }
}
__global__ void k_count(const int* __restrict__ ei) {
    int e = blockIdx.x * blockDim.x + threadIdx.x;
    if (e < EE) atomicAdd(&g_cnt[ei[EE + e]], 1);
}
__global__ void __launch_bounds__(1024) k_scan() {
    __shared__ int s[1024];
    __shared__ int carry;
    int tid = threadIdx.x;
    if (tid == 0) carry = 0;
    __syncthreads();
    for (int base = 0; base < NN; base += 1024) {
        int i = base + tid;
        int v = (i < NN) ? g_cnt[i] : 0;
        if (i < NN) g_dinv[i] = rsqrtf((float)(v + 1));
        s[tid] = v;
        __syncthreads();
#pragma unroll
        for (int off = 1; off < 1024; off <<= 1) {
            int t = (tid >= off) ? s[tid - off] : 0;
            __syncthreads();
            s[tid] += t;
            __syncthreads();
        }
        int c0 = carry;
        if (i < NN) g_rowptr[i] = c0 + s[tid] - v;
        int total = s[1023];
        __syncthreads();
        if (tid == 0) carry = c0 + total;
        __syncthreads();
    }
    if (tid == 0) g_rowptr[NN] = carry;
}
__global__ void k_fill(const int* __restrict__ ei) {
    int e = blockIdx.x * blockDim.x + threadIdx.x;
    if (e >= EE) return;
    int d = ei[EE + e];
    int pos = atomicAdd(&g_cursor[d], 1);
    g_col[g_rowptr[d] + pos] = ei[e];
}

// ---------------- TF32 tensor-core GEMM, 3-stage cp.async pipeline -----------
// block tile 128x128x16, 8 warps, warp tile 64x32 via m16n8k8 mma
#define STAGES 3
#define AST 20    // A stage row stride (floats): [m][k], 20r+cA -> 32 distinct banks
#define BST 132   // B stage row stride (floats): [k][n], 4cA+r  -> 32 distinct banks
#define SGEMM_SMEM ((STAGES * 128 * AST + STAGES * 16 * BST) * 4)

__global__ void __launch_bounds__(256) k_sgemm(
    const float* __restrict__ Aext, int Aid,
    const float* __restrict__ B, const float* __restrict__ bias,
    int Cid, int M, int Nc, int K, int doRelu)
{
    extern __shared__ float dsm[];
    float (*Asm)[128][AST] = (float (*)[128][AST])dsm;
    float (*Bsm)[16][BST]  = (float (*)[16][BST])(dsm + STAGES * 128 * AST);

    const float* A = Aext ? Aext : buf(Aid);
    float* C = buf(Cid);

    int tid  = threadIdx.x;
    int lane = tid & 31;
    int w    = tid >> 5;
    int wm   = w >> 2;        // 0..1
    int wn   = w & 3;         // 0..3
    int m0   = wm * 64;
    int n0   = wn * 32;
    int brow = blockIdx.y * 128;
    int bcol = blockIdx.x * 128;

    int r  = lane >> 2;     // 0..7
    int cA = lane & 3;      // 0..3

    // loader geometry: 512 chunks of 16B per tile per matrix; 2 chunks/thread
    int am0 = tid >> 1;                 // chunk = tid + i*256 -> m = chunk>>2... compute per-i below
    (void)am0;

    float acc[4][4][4];
#pragma unroll
    for (int i = 0; i < 4; i++)
#pragma unroll
        for (int j = 0; j < 4; j++)
#pragma unroll
            for (int q = 0; q < 4; q++) acc[i][j][q] = 0.f;

    // precomputed loader indices
    int amr[2], amk[2], aok[2];
    int bkr[2], bnn[2];
#pragma unroll
    for (int i = 0; i < 2; i++) {
        int chunk = tid + i * 256;
        amr[i] = chunk >> 2;             // 0..127
        amk[i] = (chunk & 3) * 4;        // 0,4,8,12
        aok[i] = (brow + amr[i] < M) ? 16 : 0;
        bkr[i] = chunk >> 5;             // 0..15
        bnn[i] = (chunk & 31) * 4;       // 0..124
    }

    int ktiles = K >> 4;

    // prologue: issue loads for stages 0..STAGES-2
#pragma unroll
    for (int s = 0; s < STAGES - 1; s++) {
        int kt = s << 4;
#pragma unroll
        for (int i = 0; i < 2; i++) {
            uint32_t ad = (uint32_t)__cvta_generic_to_shared(&Asm[s][amr[i]][amk[i]]);
            cpasync16(ad, &A[(size_t)(brow + amr[i]) * K + kt + amk[i]], aok[i]);
        }
#pragma unroll
        for (int i = 0; i < 2; i++) {
            uint32_t bd = (uint32_t)__cvta_generic_to_shared(&Bsm[s][bkr[i]][bnn[i]]);
            cpasync16(bd, &B[(size_t)(kt + bkr[i]) * Nc + bcol + bnn[i]], 16);
        }
        asm volatile("cp.async.commit_group;\n" ::);
    }

    for (int t = 0; t < ktiles; t++) {
        asm volatile("cp.async.wait_group %0;\n" :: "n"(STAGES - 2));
        __syncthreads();

        // issue load for tile t+STAGES-1 (overwrites stage consumed at t-1; safe post-sync)
        int tn = t + STAGES - 1;
        if (tn < ktiles) {
            int s = tn % STAGES;
            int kt = tn << 4;
#pragma unroll
            for (int i = 0; i < 2; i++) {
                uint32_t ad = (uint32_t)__cvta_generic_to_shared(&Asm[s][amr[i]][amk[i]]);
                cpasync16(ad, &A[(size_t)(brow + amr[i]) * K + kt + amk[i]], aok[i]);
            }
#pragma unroll
            for (int i = 0; i < 2; i++) {
                uint32_t bd = (uint32_t)__cvta_generic_to_shared(&Bsm[s][bkr[i]][bnn[i]]);
                cpasync16(bd, &B[(size_t)(kt + bkr[i]) * Nc + bcol + bnn[i]], 16);
            }
        }
        asm volatile("cp.async.commit_group;\n" ::);   // uniform group count

        const float (*As)[AST] = Asm[t % STAGES];
        const float (*Bs)[BST] = Bsm[t % STAGES];

#pragma unroll
        for (int ks = 0; ks < 16; ks += 8) {
            uint32_t af[4][4];
#pragma unroll
            for (int mi = 0; mi < 4; mi++) {
                int mrow = m0 + mi * 16 + r;
                af[mi][0] = tf32r(As[mrow][ks + cA]);
                af[mi][1] = tf32r(As[mrow + 8][ks + cA]);
                af[mi][2] = tf32r(As[mrow][ks + cA + 4]);
                af[mi][3] = tf32r(As[mrow + 8][ks + cA + 4]);
            }
            uint32_t bf[4][2];
#pragma unroll
            for (int ni = 0; ni < 4; ni++) {
                int ncol = n0 + ni * 8 + r;
                bf[ni][0] = tf32r(Bs[ks + cA][ncol]);
                bf[ni][1] = tf32r(Bs[ks + cA + 4][ncol]);
            }
#pragma unroll
            for (int mi = 0; mi < 4; mi++)
#pragma unroll
                for (int ni = 0; ni < 4; ni++) {
                    asm volatile(
                        "mma.sync.aligned.m16n8k8.row.col.f32.tf32.tf32.f32 "
                        "{%0,%1,%2,%3}, {%4,%5,%6,%7}, {%8,%9}, {%0,%1,%2,%3};"
                        : "+f"(acc[mi][ni][0]), "+f"(acc[mi][ni][1]),
                          "+f"(acc[mi][ni][2]), "+f"(acc[mi][ni][3])
                        : "r"(af[mi][0]), "r"(af[mi][1]), "r"(af[mi][2]), "r"(af[mi][3]),
                          "r"(bf[ni][0]), "r"(bf[ni][1]));
                }
        }
        __syncthreads();
    }

    // epilogue
#pragma unroll
    for (int mi = 0; mi < 4; mi++) {
        int row0 = brow + m0 + mi * 16 + (lane >> 2);
#pragma unroll
        for (int ni = 0; ni < 4; ni++) {
            int col = bcol + n0 + ni * 8 + 2 * (lane & 3);
            float bx = bias ? bias[col]     : 0.f;
            float by = bias ? bias[col + 1] : 0.f;
            float v0 = acc[mi][ni][0] + bx;
            float v1 = acc[mi][ni][1] + by;
            float v2 = acc[mi][ni][2] + bx;
            float v3 = acc[mi][ni][3] + by;
            if (doRelu) {
                v0 = fmaxf(v0, 0.f); v1 = fmaxf(v1, 0.f);
                v2 = fmaxf(v2, 0.f); v3 = fmaxf(v3, 0.f);
            }
            if (row0 < M) {
                C[(size_t)row0 * Nc + col]     = v0;
                C[(size_t)row0 * Nc + col + 1] = v1;
            }
            if (row0 + 8 < M) {
                C[(size_t)(row0 + 8) * Nc + col]     = v2;
                C[(size_t)(row0 + 8) * Nc + col + 1] = v3;
            }
        }
    }
}

// ---------------- GCN gather (CSR) ------------------------------------------
__global__ void __launch_bounds__(128) k_gcn_gather(
    int Hid, int Oid, const float* __restrict__ bias, int C, int doRelu)
{
    int tpn = C >> 2;
    int npb = 128 / tpn;
    int local = threadIdx.x / tpn;
    int lane  = threadIdx.x - local * tpn;
    int n = blockIdx.x * npb + local;
    if (n >= NN) return;
    int c = lane * 4;
    const float* H = buf(Hid);
    float* O = buf(Oid);

    float4 hv = *(const float4*)&H[(size_t)n * C + c];
    float dn = g_dinv[n];
    float4 acc;
    acc.x = hv.x * dn; acc.y = hv.y * dn; acc.z = hv.z * dn; acc.w = hv.w * dn;

    int start = g_rowptr[n], end = g_rowptr[n + 1];
    for (int i = start; i < end; i++) {
        int s = g_col[i];
        float wgt = g_dinv[s];
        float4 v = *(const float4*)&H[(size_t)s * C + c];
        acc.x += v.x * wgt; acc.y += v.y * wgt; acc.z += v.z * wgt; acc.w += v.w * wgt;
    }
    float4 o;
    o.x = acc.x * dn + bias[c + 0];
    o.y = acc.y * dn + bias[c + 1];
    o.z = acc.z * dn + bias[c + 2];
    o.w = acc.w * dn + bias[c + 3];
    if (doRelu) {
        o.x = fmaxf(o.x, 0.f); o.y = fmaxf(o.y, 0.f);
        o.z = fmaxf(o.z, 0.f); o.w = fmaxf(o.w, 0.f);
    }
    *(float4*)&O[(size_t)n * C + c] = o;
}

// ---------------- GAT --------------------------------------------------------
__global__ void k_att(const float* __restrict__ attS, const float* __restrict__ attD) {
    int gw = (blockIdx.x * blockDim.x + threadIdx.x) >> 5;
    int lane = threadIdx.x & 31;
    if (gw >= NN * HEADS) return;
    int n = gw / HEADS, h = gw - n * HEADS;
    const float* hp = &g_h2[(size_t)n * C2 + h * 128];
    const float* as = &attS[h * 128];
    const float* ad = &attD[h * 128];
    float ss = 0.f, sd = 0.f;
#pragma unroll
    for (int c = lane; c < 128; c += 32) {
        float v = hp[c];
        ss += v * as[c];
        sd += v * ad[c];
    }
#pragma unroll
    for (int o = 16; o; o >>= 1) {
        ss += __shfl_xor_sync(0xffffffffu, ss, o);
        sd += __shfl_xor_sync(0xffffffffu, sd, o);
    }
    if (lane == 0) {
        g_asrc[gw] = ss;
        g_adst[gw] = sd;
    }
}

#define GCHUNK 64
__global__ void __launch_bounds__(128) k_gat_fused(const float* __restrict__ gat_b) {
    int n = blockIdx.x;
    int tid = threadIdx.x;
    int lane = tid & 31, warp = tid >> 5;
    int start = g_rowptr[n], end = g_rowptr[n + 1];

    float adst[HEADS], selfe[HEADS];
#pragma unroll
    for (int h = 0; h < HEADS; h++) {
        adst[h]  = g_adst[n * HEADS + h];
        selfe[h] = lrelu(g_asrc[n * HEADS + h] + adst[h]);
    }

    __shared__ float s_red[4 * HEADS];
    __shared__ int   s_src[GCHUNK];
    __shared__ float s_al [GCHUNK * HEADS];

    float mx[HEADS];
#pragma unroll
    for (int h = 0; h < HEADS; h++) mx[h] = selfe[h];
    for (int i = start + tid; i < end; i += 128) {
        int s = g_col[i];
#pragma unroll
        for (int h = 0; h < HEADS; h++)
            mx[h] = fmaxf(mx[h], lrelu(g_asrc[s * HEADS + h] + adst[h]));
    }
#pragma unroll
    for (int h = 0; h < HEADS; h++)
#pragma unroll
        for (int o = 16; o; o >>= 1) mx[h] = fmaxf(mx[h], __shfl_xor_sync(0xffffffffu, mx[h], o));
    if (lane == 0)
#pragma unroll
        for (int h = 0; h < HEADS; h++) s_red[warp * HEADS + h] = mx[h];
    __syncthreads();
    float m[HEADS];
#pragma unroll
    for (int h = 0; h < HEADS; h++)
        m[h] = fmaxf(fmaxf(s_red[0 * HEADS + h], s_red[1 * HEADS + h]),
                     fmaxf(s_red[2 * HEADS + h], s_red[3 * HEADS + h]));
    __syncthreads();

    float zz[HEADS];
#pragma unroll
    for (int h = 0; h < HEADS; h++) zz[h] = (tid == 0) ? __expf(selfe[h] - m[h]) : 0.f;
    for (int i = start + tid; i < end; i += 128) {
        int s = g_col[i];
#pragma unroll
        for (int h = 0; h < HEADS; h++)
            zz[h] += __expf(lrelu(g_asrc[s * HEADS + h] + adst[h]) - m[h]);
    }
#pragma unroll
    for (int h = 0; h < HEADS; h++)
#pragma unroll
        for (int o = 16; o; o >>= 1) zz[h] += __shfl_xor_sync(0xffffffffu, zz[h], o);
    if (lane == 0)
#pragma unroll
        for (int h = 0; h < HEADS; h++) s_red[warp * HEADS + h] = zz[h];
    __syncthreads();
    float z[HEADS];
#pragma unroll
    for (int h = 0; h < HEADS; h++)
        z[h] = s_red[0 * HEADS + h] + s_red[1 * HEADS + h] + s_red[2 * HEADS + h] + s_red[3 * HEADS + h];
    __syncthreads();

    int c = tid * 4;
    int hc = c >> 7;
    float4 hv = *(const float4*)&g_h2[(size_t)n * C2 + c];
    float wself = __expf(selfe[hc] - m[hc]);
    float4 acc;
    acc.x = hv.x * wself; acc.y = hv.y * wself; acc.z = hv.z * wself; acc.w = hv.w * wself;

    for (int base = start; base < end; base += GCHUNK) {
        int cnt = min(GCHUNK, end - base);
        if (tid < cnt) {
            int s = g_col[base + tid];
            s_src[tid] = s;
#pragma unroll
            for (int h = 0; h < HEADS; h++)
                s_al[tid * HEADS + h] = __expf(lrelu(g_asrc[s * HEADS + h] + adst[h]) - m[h]);
        }
        __syncthreads();
        for (int j = 0; j < cnt; j++) {
            int s = s_src[j];
            float a = s_al[j * HEADS + hc];
            float4 v = *(const float4*)&g_h2[(size_t)s * C2 + c];
            acc.x += v.x * a; acc.y += v.y * a; acc.z += v.z * a; acc.w += v.w * a;
        }
        __syncthreads();
    }

    float rz = 1.0f / z[hc];
    float4 o;
    o.x = acc.x * rz + gat_b[c + 0];
    o.y = acc.y * rz + gat_b[c + 1];
    o.z = acc.z * rz + gat_b[c + 2];
    o.w = acc.w * rz + gat_b[c + 3];
    *(float4*)&g_gat[(size_t)n * C2 + c] = o;
}

// ---------------- LayerNorm --------------------------------------------------
__global__ void k_ln(int Xid, int Yid, const float* __restrict__ gw,
                     const float* __restrict__ bw, int C, int ldY, int doRelu)
{
    int n = blockIdx.x;
    const float* x = buf(Xid) + (size_t)n * C;
    float* y = buf(Yid) + (size_t)n * ldY;
    int tid = threadIdx.x, lane = tid & 31, warp = tid >> 5;

    float s = 0.f, s2 = 0.f;
    for (int c = tid; c < C; c += 128) {
        float v = x[c];
        s += v; s2 += v * v;
    }
#pragma unroll
    for (int o = 16; o; o >>= 1) {
        s  += __shfl_xor_sync(0xffffffffu, s, o);
        s2 += __shfl_xor_sync(0xffffffffu, s2, o);
    }
    __shared__ float shs[4], shs2[4], smu, sinv;
    if (lane == 0) { shs[warp] = s; shs2[warp] = s2; }
    __syncthreads();
    if (tid == 0) {
        float S = shs[0] + shs[1] + shs[2] + shs[3];
        float S2 = shs2[0] + shs2[1] + shs2[2] + shs2[3];
        float mu = S / C;
        float var = S2 / C - mu * mu;
        smu = mu;
        sinv = rsqrtf(var + 1e-5f);
    }
    __syncthreads();
    float mu = smu, inv = sinv;
    for (int c = tid; c < C; c += 128) {
        float v = (x[c] - mu) * inv * gw[c] + bw[c];
        if (doRelu) v = fmaxf(v, 0.f);
        y[c] = v;
    }
}

__global__ void k_catx(const float* __restrict__ x) {
    int idx = blockIdx.x * blockDim.x + threadIdx.x;
    if (idx >= NN * C1) return;
    int n = idx / C1, c = idx - n * C1;
    g_cat[(size_t)n * CCAT + C3 + c] = x[idx];
}

__global__ void k_out(const float* __restrict__ w2, const float* __restrict__ b2,
                      float* __restrict__ out)
{
    int gw = (blockIdx.x * blockDim.x + threadIdx.x) >> 5;
    int lane = threadIdx.x & 31;
    if (gw >= NN) return;
    const float* hp = &g_mh[(size_t)gw * CM];
    float a0 = 0.f, a1 = 0.f;
#pragma unroll
    for (int c = lane; c < CM; c += 32) {
        float v = hp[c];
        a0 += v * w2[c * 2];
        a1 += v * w2[c * 2 + 1];
    }
#pragma unroll
    for (int o = 16; o; o >>= 1) {
        a0 += __shfl_xor_sync(0xffffffffu, a0, o);
        a1 += __shfl_xor_sync(0xffffffffu, a1, o);
    }
    if (lane == 0) {
        out[gw * 2 + 0] = a0 + b2[0];
        out[gw * 2 + 1] = a1 + b2[1];
    }
}

// ---------------- launch -----------------------------------------------------
static inline int cdiv(int a, int b) { return (a + b - 1) / b; }

extern "C" void kernel_launch(void* const* d_in, const int* in_sizes, int n_in,
                              void* d_out, int out_size)
{
    (void)in_sizes; (void)n_in; (void)out_size;
    const float* x      = (const float*)d_in[0];
    const int*   ei     = (const int*)d_in[1];
    const float* gcn1_w = (const float*)d_in[2];
    const float* gcn1_b = (const float*)d_in[3];
    const float* gat_w  = (const float*)d_in[4];
    const float* att_s  = (const float*)d_in[5];
    const float* att_d  = (const float*)d_in[6];
    const float* gat_b  = (const float*)d_in[7];
    const float* n1_g   = (const float*)d_in[8];
    const float* n1_b   = (const float*)d_in[9];
    const float* gcn2_w = (const float*)d_in[10];
    const float* gcn2_b = (const float*)d_in[11];
    const float* n2_g   = (const float*)d_in[12];
    const float* n2_b   = (const float*)d_in[13];
    const float* mlp_w1 = (const float*)d_in[14];
    const float* mlp_b1 = (const float*)d_in[15];
    const float* mlp_w2 = (const float*)d_in[16];
    const float* mlp_b2 = (const float*)d_in[17];
    float* out = (float*)d_out;

    const int T = 256;
    int mblk = cdiv(NN, 128);

    cudaFuncSetAttribute(k_sgemm, cudaFuncAttributeMaxDynamicSharedMemorySize, SGEMM_SMEM);

    // CSR build
    k_zero <<<cdiv(NN, T), T>>>();
    k_count<<<cdiv(EE, T), T>>>(ei);
    k_scan <<<1, 1024>>>();
    k_fill <<<cdiv(EE, T), T>>>(ei);

    // GCN1
    k_sgemm<<<dim3(1, mblk), T, SGEMM_SMEM>>>(x, -1, gcn1_w, nullptr, ID_H1, NN, C1, C1, 0);
    k_gcn_gather<<<NN / 4, 128>>>(ID_H1, ID_G1, gcn1_b, C1, 1);

    // GAT
    k_sgemm<<<dim3(C2 / 128, mblk), T, SGEMM_SMEM>>>(nullptr, ID_G1, gat_w, nullptr, ID_H2, NN, C2, C1, 0);
    k_att<<<cdiv(NN * HEADS * 32, T), T>>>(att_s, att_d);
    k_gat_fused<<<NN, 128>>>(gat_b);

    // LN1
    k_ln<<<NN, 128>>>(ID_GAT, ID_GAT, n1_g, n1_b, C2, C2, 0);

    // GCN2
    k_sgemm<<<dim3(C3 / 128, mblk), T, SGEMM_SMEM>>>(nullptr, ID_GAT, gcn2_w, nullptr, ID_H3, NN, C3, C2, 0);
    k_gcn_gather<<<NN / 2, 128>>>(ID_H3, ID_G2, gcn2_b, C3, 0);

    // LN2 + concat
    k_ln<<<NN, 128>>>(ID_G2, ID_CAT, n2_g, n2_b, C3, CCAT, 1);
    k_catx<<<cdiv(NN * C1, T), T>>>(x);

    // MLP
    k_sgemm<<<dim3(CM / 128, mblk), T, SGEMM_SMEM>>>(nullptr, ID_CAT, mlp_w1, mlp_b1, ID_MH, NN, CM, CCAT, 1);
    k_out<<<cdiv(NN * 32, T), T>>>(mlp_w2, mlp_b2, out);
}

// round 7
// speedup vs baseline: 3.8720x; 1.0868x over previous
#include <cuda_runtime.h>
#include <cstdint>

#define NN   50000
#define EE   800000
#define C1   128
#define C2   512
#define C3   256
#define CCAT 384
#define CM   128
#define HEADS 4

// ---------------- scratch (static device globals; no allocation) -------------
__device__ float    g_dinv[NN];
__device__ int      g_cnt[NN];
__device__ int      g_cursor[NN];
__device__ int      g_rowptr[NN + 1];
__device__ int      g_col[EE];          // src node per dst-sorted edge
__device__ float    g_h1 [NN*C1];
__device__ float    g_g1 [NN*C1];
__device__ float    g_h2 [NN*C2];
__device__ float    g_gat[NN*C2];
__device__ float    g_h3 [NN*C3];
__device__ float    g_g2 [NN*C3];
__device__ float    g_cat[NN*CCAT];
__device__ float    g_mh [NN*CM];
__device__ float    g_asrc[NN*HEADS];
__device__ float    g_adst[NN*HEADS];
__device__ float    g_aself[NN*HEADS];
__device__ float    g_alpha[(size_t)EE*HEADS];

#define ID_H1  0
#define ID_G1  1
#define ID_H2  2
#define ID_GAT 3
#define ID_H3  4
#define ID_G2  5
#define ID_CAT 6
#define ID_MH  7

__device__ __forceinline__ float* buf(int id) {
    switch (id) {
        case ID_H1:  return g_h1;
        case ID_G1:  return g_g1;
        case ID_H2:  return g_h2;
        case ID_GAT: return g_gat;
        case ID_H3:  return g_h3;
        case ID_G2:  return g_g2;
        case ID_CAT: return g_cat;
        default:     return g_mh;
    }
}

__device__ __forceinline__ float lrelu(float x) { return x >= 0.f ? x : 0.2f * x; }

__device__ __forceinline__ uint32_t tf32r(float f) {
    uint32_t u;
    asm("cvt.rna.tf32.f32 %0, %1;" : "=r"(u) : "f"(f));
    return u;
}

__device__ __forceinline__ void cpasync16(uint32_t dst, const void* src, int sz) {
    asm volatile("cp.async.cg.shared.global [%0], [%1], 16, %2;\n"
                 :: "r"(dst), "l"(src), "r"(sz));
}

// ---------------- CSR build --------------------------------------------------
__global__ void k_zero() {
    int i = blockIdx.x * blockDim.x + threadIdx.x;
    if (i < NN) { g_cnt[i] = 0; g_cursor[i] = 0; }
}
__global__ void k_count(const int* __restrict__ ei) {
    int e = blockIdx.x * blockDim.x + threadIdx.x;
    if (e < EE) atomicAdd(&g_cnt[ei[EE + e]], 1);
}
// single-block scan, warp-shfl based (2 syncthreads per 1024-chunk)
__global__ void __launch_bounds__(1024) k_scan() {
    __shared__ int s_w[32];
    __shared__ int s_carry;
    int tid = threadIdx.x, lane = tid & 31, wid = tid >> 5;
    if (tid == 0) s_carry = 0;
    __syncthreads();
    for (int base = 0; base < NN; base += 1024) {
        int i = base + tid;
        int v = (i < NN) ? g_cnt[i] : 0;
        if (i < NN) g_dinv[i] = rsqrtf((float)(v + 1));
        // warp inclusive scan
        int x = v;
#pragma unroll
        for (int o = 1; o < 32; o <<= 1) {
            int t = __shfl_up_sync(0xffffffffu, x, o);
            if (lane >= o) x += t;
        }
        if (lane == 31) s_w[wid] = x;
        __syncthreads();
        if (wid == 0) {
            int y = s_w[lane];
#pragma unroll
            for (int o = 1; o < 32; o <<= 1) {
                int t = __shfl_up_sync(0xffffffffu, y, o);
                if (lane >= o) y += t;
            }
            s_w[lane] = y;
        }
        __syncthreads();
        int woff = (wid > 0) ? s_w[wid - 1] : 0;
        int incl = x + woff;
        int c0 = s_carry;
        if (i < NN) g_rowptr[i] = c0 + incl - v;
        int tot = s_w[31];
        __syncthreads();
        if (tid == 0) s_carry = c0 + tot;
        __syncthreads();
    }
    if (tid == 0) g_rowptr[NN] = s_carry;
}
__global__ void k_fill(const int* __restrict__ ei) {
    int e = blockIdx.x * blockDim.x + threadIdx.x;
    if (e >= EE) return;
    int d = ei[EE + e];
    int pos = atomicAdd(&g_cursor[d], 1);
    g_col[g_rowptr[d] + pos] = ei[e];
}

// ---------------- TF32 tensor-core GEMM, 3-stage cp.async pipeline -----------
#define STAGES 3
#define AST 20
#define BST 132
#define SGEMM_SMEM ((STAGES * 128 * AST + STAGES * 16 * BST) * 4)

__global__ void __launch_bounds__(256) k_sgemm(
    const float* __restrict__ Aext, int Aid,
    const float* __restrict__ B, const float* __restrict__ bias,
    int Cid, int M, int Nc, int K, int doRelu)
{
    extern __shared__ float dsm[];
    float (*Asm)[128][AST] = (float (*)[128][AST])dsm;
    float (*Bsm)[16][BST]  = (float (*)[16][BST])(dsm + STAGES * 128 * AST);

    const float* A = Aext ? Aext : buf(Aid);
    float* C = buf(Cid);

    int tid  = threadIdx.x;
    int lane = tid & 31;
    int w    = tid >> 5;
    int wm   = w >> 2;
    int wn   = w & 3;
    int m0   = wm * 64;
    int n0   = wn * 32;
    int brow = blockIdx.y * 128;
    int bcol = blockIdx.x * 128;

    int r  = lane >> 2;
    int cA = lane & 3;

    float acc[4][4][4];
#pragma unroll
    for (int i = 0; i < 4; i++)
#pragma unroll
        for (int j = 0; j < 4; j++)
#pragma unroll
            for (int q = 0; q < 4; q++) acc[i][j][q] = 0.f;

    int amr[2], amk[2], aok[2];
    int bkr[2], bnn[2];
#pragma unroll
    for (int i = 0; i < 2; i++) {
        int chunk = tid + i * 256;
        amr[i] = chunk >> 2;
        amk[i] = (chunk & 3) * 4;
        aok[i] = (brow + amr[i] < M) ? 16 : 0;
        bkr[i] = chunk >> 5;
        bnn[i] = (chunk & 31) * 4;
    }

    int ktiles = K >> 4;

#pragma unroll
    for (int s = 0; s < STAGES - 1; s++) {
        int kt = s << 4;
#pragma unroll
        for (int i = 0; i < 2; i++) {
            uint32_t ad = (uint32_t)__cvta_generic_to_shared(&Asm[s][amr[i]][amk[i]]);
            cpasync16(ad, &A[(size_t)(brow + amr[i]) * K + kt + amk[i]], aok[i]);
        }
#pragma unroll
        for (int i = 0; i < 2; i++) {
            uint32_t bd = (uint32_t)__cvta_generic_to_shared(&Bsm[s][bkr[i]][bnn[i]]);
            cpasync16(bd, &B[(size_t)(kt + bkr[i]) * Nc + bcol + bnn[i]], 16);
        }
        asm volatile("cp.async.commit_group;\n" ::);
    }

    for (int t = 0; t < ktiles; t++) {
        asm volatile("cp.async.wait_group %0;\n" :: "n"(STAGES - 2));
        __syncthreads();

        int tn = t + STAGES - 1;
        if (tn < ktiles) {
            int s = tn % STAGES;
            int kt = tn << 4;
#pragma unroll
            for (int i = 0; i < 2; i++) {
                uint32_t ad = (uint32_t)__cvta_generic_to_shared(&Asm[s][amr[i]][amk[i]]);
                cpasync16(ad, &A[(size_t)(brow + amr[i]) * K + kt + amk[i]], aok[i]);
            }
#pragma unroll
            for (int i = 0; i < 2; i++) {
                uint32_t bd = (uint32_t)__cvta_generic_to_shared(&Bsm[s][bkr[i]][bnn[i]]);
                cpasync16(bd, &B[(size_t)(kt + bkr[i]) * Nc + bcol + bnn[i]], 16);
            }
        }
        asm volatile("cp.async.commit_group;\n" ::);

        const float (*As)[AST] = Asm[t % STAGES];
        const float (*Bs)[BST] = Bsm[t % STAGES];

#pragma unroll
        for (int ks = 0; ks < 16; ks += 8) {
            uint32_t af[4][4];
#pragma unroll
            for (int mi = 0; mi < 4; mi++) {
                int mrow = m0 + mi * 16 + r;
                af[mi][0] = tf32r(As[mrow][ks + cA]);
                af[mi][1] = tf32r(As[mrow + 8][ks + cA]);
                af[mi][2] = tf32r(As[mrow][ks + cA + 4]);
                af[mi][3] = tf32r(As[mrow + 8][ks + cA + 4]);
            }
            uint32_t bf[4][2];
#pragma unroll
            for (int ni = 0; ni < 4; ni++) {
                int ncol = n0 + ni * 8 + r;
                bf[ni][0] = tf32r(Bs[ks + cA][ncol]);
                bf[ni][1] = tf32r(Bs[ks + cA + 4][ncol]);
            }
#pragma unroll
            for (int mi = 0; mi < 4; mi++)
#pragma unroll
                for (int ni = 0; ni < 4; ni++) {
                    asm volatile(
                        "mma.sync.aligned.m16n8k8.row.col.f32.tf32.tf32.f32 "
                        "{%0,%1,%2,%3}, {%4,%5,%6,%7}, {%8,%9}, {%0,%1,%2,%3};"
                        : "+f"(acc[mi][ni][0]), "+f"(acc[mi][ni][1]),
                          "+f"(acc[mi][ni][2]), "+f"(acc[mi][ni][3])
                        : "r"(af[mi][0]), "r"(af[mi][1]), "r"(af[mi][2]), "r"(af[mi][3]),
                          "r"(bf[ni][0]), "r"(bf[ni][1]));
                }
        }
        __syncthreads();
    }

#pragma unroll
    for (int mi = 0; mi < 4; mi++) {
        int row0 = brow + m0 + mi * 16 + (lane >> 2);
#pragma unroll
        for (int ni = 0; ni < 4; ni++) {
            int col = bcol + n0 + ni * 8 + 2 * (lane & 3);
            float bx = bias ? bias[col]     : 0.f;
            float by = bias ? bias[col + 1] : 0.f;
            float v0 = acc[mi][ni][0] + bx;
            float v1 = acc[mi][ni][1] + by;
            float v2 = acc[mi][ni][2] + bx;
            float v3 = acc[mi][ni][3] + by;
            if (doRelu) {
                v0 = fmaxf(v0, 0.f); v1 = fmaxf(v1, 0.f);
                v2 = fmaxf(v2, 0.f); v3 = fmaxf(v3, 0.f);
            }
            if (row0 < M) {
                C[(size_t)row0 * Nc + col]     = v0;
                C[(size_t)row0 * Nc + col + 1] = v1;
            }
            if (row0 + 8 < M) {
                C[(size_t)(row0 + 8) * Nc + col]     = v2;
                C[(size_t)(row0 + 8) * Nc + col + 1] = v3;
            }
        }
    }
}

// ---------------- GCN gather (CSR) ------------------------------------------
__global__ void __launch_bounds__(128) k_gcn_gather(
    int Hid, int Oid, const float* __restrict__ bias, int C, int doRelu)
{
    int tpn = C >> 2;
    int npb = 128 / tpn;
    int local = threadIdx.x / tpn;
    int lane  = threadIdx.x - local * tpn;
    int n = blockIdx.x * npb + local;
    if (n >= NN) return;
    int c = lane * 4;
    const float* H = buf(Hid);
    float* O = buf(Oid);

    float4 hv = *(const float4*)&H[(size_t)n * C + c];
    float dn = g_dinv[n];
    float4 acc;
    acc.x = hv.x * dn; acc.y = hv.y * dn; acc.z = hv.z * dn; acc.w = hv.w * dn;

    int start = g_rowptr[n], end = g_rowptr[n + 1];
    for (int i = start; i < end; i++) {
        int s = g_col[i];
        float wgt = g_dinv[s];
        float4 v = *(const float4*)&H[(size_t)s * C + c];
        acc.x += v.x * wgt; acc.y += v.y * wgt; acc.z += v.z * wgt; acc.w += v.w * wgt;
    }
    float4 o;
    o.x = acc.x * dn + bias[c + 0];
    o.y = acc.y * dn + bias[c + 1];
    o.z = acc.z * dn + bias[c + 2];
    o.w = acc.w * dn + bias[c + 3];
    if (doRelu) {
        o.x = fmaxf(o.x, 0.f); o.y = fmaxf(o.y, 0.f);
        o.z = fmaxf(o.z, 0.f); o.w = fmaxf(o.w, 0.f);
    }
    *(float4*)&O[(size_t)n * C + c] = o;
}

// ---------------- GAT --------------------------------------------------------
__global__ void k_att(const float* __restrict__ attS, const float* __restrict__ attD) {
    int gw = (blockIdx.x * blockDim.x + threadIdx.x) >> 5;
    int lane = threadIdx.x & 31;
    if (gw >= NN * HEADS) return;
    int n = gw / HEADS, h = gw - n * HEADS;
    const float* hp = &g_h2[(size_t)n * C2 + h * 128];
    const float* as = &attS[h * 128];
    const float* ad = &attD[h * 128];
    float ss = 0.f, sd = 0.f;
#pragma unroll
    for (int c = lane; c < 128; c += 32) {
        float v = hp[c];
        ss += v * as[c];
        sd += v * ad[c];
    }
#pragma unroll
    for (int o = 16; o; o >>= 1) {
        ss += __shfl_xor_sync(0xffffffffu, ss, o);
        sd += __shfl_xor_sync(0xffffffffu, sd, o);
    }
    if (lane == 0) {
        g_asrc[gw] = ss;
        g_adst[gw] = sd;
    }
}

// softmax per dst node: one warp per node; writes normalized alpha + aself
__global__ void k_gat_softmax() {
    int n = (blockIdx.x * blockDim.x + threadIdx.x) >> 5;
    int lane = threadIdx.x & 31;
    if (n >= NN) return;
    int start = g_rowptr[n], end = g_rowptr[n + 1];

    float adst[HEADS], selfe[HEADS];
#pragma unroll
    for (int h = 0; h < HEADS; h++) {
        adst[h]  = g_adst[n * HEADS + h];
        selfe[h] = lrelu(g_asrc[n * HEADS + h] + adst[h]);
    }

    // pass 1: max
    float mx[HEADS];
#pragma unroll
    for (int h = 0; h < HEADS; h++) mx[h] = selfe[h];
    for (int i = start + lane; i < end; i += 32) {
        int s = g_col[i];
#pragma unroll
        for (int h = 0; h < HEADS; h++)
            mx[h] = fmaxf(mx[h], lrelu(g_asrc[s * HEADS + h] + adst[h]));
    }
#pragma unroll
    for (int h = 0; h < HEADS; h++)
#pragma unroll
        for (int o = 16; o; o >>= 1)
            mx[h] = fmaxf(mx[h], __shfl_xor_sync(0xffffffffu, mx[h], o));

    // pass 2: exp + z, store unnormalized alpha
    float zz[HEADS];
#pragma unroll
    for (int h = 0; h < HEADS; h++) zz[h] = (lane == 0) ? __expf(selfe[h] - mx[h]) : 0.f;
    for (int i = start + lane; i < end; i += 32) {
        int s = g_col[i];
        float4 ev;
        ev.x = __expf(lrelu(g_asrc[s * HEADS + 0] + adst[0]) - mx[0]);
        ev.y = __expf(lrelu(g_asrc[s * HEADS + 1] + adst[1]) - mx[1]);
        ev.z = __expf(lrelu(g_asrc[s * HEADS + 2] + adst[2]) - mx[2]);
        ev.w = __expf(lrelu(g_asrc[s * HEADS + 3] + adst[3]) - mx[3]);
        *(float4*)&g_alpha[(size_t)i * HEADS] = ev;
        zz[0] += ev.x; zz[1] += ev.y; zz[2] += ev.z; zz[3] += ev.w;
    }
#pragma unroll
    for (int h = 0; h < HEADS; h++)
#pragma unroll
        for (int o = 16; o; o >>= 1)
            zz[h] += __shfl_xor_sync(0xffffffffu, zz[h], o);

    float rz[HEADS];
#pragma unroll
    for (int h = 0; h < HEADS; h++) rz[h] = 1.0f / zz[h];

    // pass 3: normalize
    for (int i = start + lane; i < end; i += 32) {
        float4 a = *(float4*)&g_alpha[(size_t)i * HEADS];
        a.x *= rz[0]; a.y *= rz[1]; a.z *= rz[2]; a.w *= rz[3];
        *(float4*)&g_alpha[(size_t)i * HEADS] = a;
    }
    if (lane == 0) {
#pragma unroll
        for (int h = 0; h < HEADS; h++)
            g_aself[n * HEADS + h] = __expf(selfe[h] - mx[h]) * rz[h];
    }
}

// aggregation: block per node; no reductions, no exps
#define GCHUNK 64
__global__ void __launch_bounds__(128) k_gat_agg(const float* __restrict__ gat_b) {
    int n = blockIdx.x;
    int tid = threadIdx.x;
    int start = g_rowptr[n], end = g_rowptr[n + 1];

    __shared__ int   s_src[GCHUNK];
    __shared__ float s_al [GCHUNK * HEADS];

    int c = tid * 4;
    int hc = c >> 7;
    float4 hv = *(const float4*)&g_h2[(size_t)n * C2 + c];
    float wself = g_aself[n * HEADS + hc];
    float4 acc;
    acc.x = hv.x * wself; acc.y = hv.y * wself; acc.z = hv.z * wself; acc.w = hv.w * wself;

    for (int base = start; base < end; base += GCHUNK) {
        int cnt = min(GCHUNK, end - base);
        if (tid < cnt) {
            s_src[tid] = g_col[base + tid];
            *(float4*)&s_al[tid * HEADS] = *(const float4*)&g_alpha[(size_t)(base + tid) * HEADS];
        }
        __syncthreads();
        for (int j = 0; j < cnt; j++) {
            int s = s_src[j];
            float a = s_al[j * HEADS + hc];
            float4 v = *(const float4*)&g_h2[(size_t)s * C2 + c];
            acc.x += v.x * a; acc.y += v.y * a; acc.z += v.z * a; acc.w += v.w * a;
        }
        __syncthreads();
    }

    float4 o;
    o.x = acc.x + gat_b[c + 0];
    o.y = acc.y + gat_b[c + 1];
    o.z = acc.z + gat_b[c + 2];
    o.w = acc.w + gat_b[c + 3];
    *(float4*)&g_gat[(size_t)n * C2 + c] = o;
}

// ---------------- LayerNorm --------------------------------------------------
__global__ void k_ln(int Xid, int Yid, const float* __restrict__ gw,
                     const float* __restrict__ bw, int C, int ldY, int doRelu)
{
    int n = blockIdx.x;
    const float* x = buf(Xid) + (size_t)n * C;
    float* y = buf(Yid) + (size_t)n * ldY;
    int tid = threadIdx.x, lane = tid & 31, warp = tid >> 5;

    float s = 0.f, s2 = 0.f;
    for (int c = tid; c < C; c += 128) {
        float v = x[c];
        s += v; s2 += v * v;
    }
#pragma unroll
    for (int o = 16; o; o >>= 1) {
        s  += __shfl_xor_sync(0xffffffffu, s, o);
        s2 += __shfl_xor_sync(0xffffffffu, s2, o);
    }
    __shared__ float shs[4], shs2[4], smu, sinv;
    if (lane == 0) { shs[warp] = s; shs2[warp] = s2; }
    __syncthreads();
    if (tid == 0) {
        float S = shs[0] + shs[1] + shs[2] + shs[3];
        float S2 = shs2[0] + shs2[1] + shs2[2] + shs2[3];
        float mu = S / C;
        float var = S2 / C - mu * mu;
        smu = mu;
        sinv = rsqrtf(var + 1e-5f);
    }
    __syncthreads();
    float mu = smu, inv = sinv;
    for (int c = tid; c < C; c += 128) {
        float v = (x[c] - mu) * inv * gw[c] + bw[c];
        if (doRelu) v = fmaxf(v, 0.f);
        y[c] = v;
    }
}

__global__ void k_catx(const float* __restrict__ x) {
    int idx = blockIdx.x * blockDim.x + threadIdx.x;
    if (idx >= NN * C1) return;
    int n = idx / C1, c = idx - n * C1;
    g_cat[(size_t)n * CCAT + C3 + c] = x[idx];
}

__global__ void k_out(const float* __restrict__ w2, const float* __restrict__ b2,
                      float* __restrict__ out)
{
    int gw = (blockIdx.x * blockDim.x + threadIdx.x) >> 5;
    int lane = threadIdx.x & 31;
    if (gw >= NN) return;
    const float* hp = &g_mh[(size_t)gw * CM];
    float a0 = 0.f, a1 = 0.f;
#pragma unroll
    for (int c = lane; c < CM; c += 32) {
        float v = hp[c];
        a0 += v * w2[c * 2];
        a1 += v * w2[c * 2 + 1];
    }
#pragma unroll
    for (int o = 16; o; o >>= 1) {
        a0 += __shfl_xor_sync(0xffffffffu, a0, o);
        a1 += __shfl_xor_sync(0xffffffffu, a1, o);
    }
    if (lane == 0) {
        out[gw * 2 + 0] = a0 + b2[0];
        out[gw * 2 + 1] = a1 + b2[1];
    }
}

// ---------------- launch -----------------------------------------------------
static inline int cdiv(int a, int b) { return (a + b - 1) / b; }

extern "C" void kernel_launch(void* const* d_in, const int* in_sizes, int n_in,
                              void* d_out, int out_size)
{
    (void)in_sizes; (void)n_in; (void)out_size;
    const float* x      = (const float*)d_in[0];
    const int*   ei     = (const int*)d_in[1];
    const float* gcn1_w = (const float*)d_in[2];
    const float* gcn1_b = (const float*)d_in[3];
    const float* gat_w  = (const float*)d_in[4];
    const float* att_s  = (const float*)d_in[5];
    const float* att_d  = (const float*)d_in[6];
    const float* gat_b  = (const float*)d_in[7];
    const float* n1_g   = (const float*)d_in[8];
    const float* n1_b   = (const float*)d_in[9];
    const float* gcn2_w = (const float*)d_in[10];
    const float* gcn2_b = (const float*)d_in[11];
    const float* n2_g   = (const float*)d_in[12];
    const float* n2_b   = (const float*)d_in[13];
    const float* mlp_w1 = (const float*)d_in[14];
    const float* mlp_b1 = (const float*)d_in[15];
    const float* mlp_w2 = (const float*)d_in[16];
    const float* mlp_b2 = (const float*)d_in[17];
    float* out = (float*)d_out;

    const int T = 256;
    int mblk = cdiv(NN, 128);

    cudaFuncSetAttribute(k_sgemm, cudaFuncAttributeMaxDynamicSharedMemorySize, SGEMM_SMEM);

    // CSR build
    k_zero <<<cdiv(NN, T), T>>>();
    k_count<<<cdiv(EE, T), T>>>(ei);
    k_scan <<<1, 1024>>>();
    k_fill <<<cdiv(EE, T), T>>>(ei);

    // GCN1
    k_sgemm<<<dim3(1, mblk), T, SGEMM_SMEM>>>(x, -1, gcn1_w, nullptr, ID_H1, NN, C1, C1, 0);
    k_gcn_gather<<<NN / 4, 128>>>(ID_H1, ID_G1, gcn1_b, C1, 1);

    // GAT
    k_sgemm<<<dim3(C2 / 128, mblk), T, SGEMM_SMEM>>>(nullptr, ID_G1, gat_w, nullptr, ID_H2, NN, C2, C1, 0);
    k_att<<<cdiv(NN * HEADS * 32, T), T>>>(att_s, att_d);
    k_gat_softmax<<<cdiv(NN * 32, T), T>>>();
    k_gat_agg<<<NN, 128>>>(gat_b);

    // LN1
    k_ln<<<NN, 128>>>(ID_GAT, ID_GAT, n1_g, n1_b, C2, C2, 0);

    // GCN2
    k_sgemm<<<dim3(C3 / 128, mblk), T, SGEMM_SMEM>>>(nullptr, ID_GAT, gcn2_w, nullptr, ID_H3, NN, C3, C2, 0);
    k_gcn_gather<<<NN / 2, 128>>>(ID_H3, ID_G2, gcn2_b, C3, 0);

    // LN2 + concat
    k_ln<<<NN, 128>>>(ID_G2, ID_CAT, n2_g, n2_b, C3, CCAT, 1);
    k_catx<<<cdiv(NN * C1, T), T>>>(x);

    // MLP
    k_sgemm<<<dim3(CM / 128, mblk), T, SGEMM_SMEM>>>(nullptr, ID_CAT, mlp_w1, mlp_b1, ID_MH, NN, CM, CCAT, 1);
    k_out<<<cdiv(NN * 32, T), T>>>(mlp_w2, mlp_b2, out);
}

// round 9
// speedup vs baseline: 4.1443x; 1.0703x over previous
#include <cuda_runtime.h>
#include <cstdint>

#define NN   50000
#define EE   800000
#define C1   128
#define C2   512
#define C3   256
#define CCAT 384
#define CM   128
#define HEADS 4

// ---------------- scratch (static device globals; no allocation) -------------
__device__ float    g_dinv[NN];
__device__ int      g_cnt[NN];
__device__ int      g_cursor[NN];
__device__ int      g_rowptr[NN + 1];
__device__ int      g_col[EE];          // src node per dst-sorted edge
__device__ float    g_h1 [NN*C1];
__device__ float    g_g1 [NN*C1];
__device__ float    g_h2 [NN*C2];      // reused as p[n][h][128]
__device__ float    g_gat[NN*C2];
__device__ float    g_h3 [NN*C3];
__device__ float    g_g2 [NN*C3];
__device__ float    g_cat[NN*CCAT];
__device__ float    g_mh [NN*CM];
__device__ float    g_asrc[NN*HEADS];
__device__ float    g_adst[NN*HEADS];
__device__ float    g_aself[NN*HEADS];
__device__ float    g_alpha[(size_t)EE*HEADS];
__device__ float    g_wtilS[HEADS*C1];  // [h][c]
__device__ float    g_wtilD[HEADS*C1];

#define ID_H1  0
#define ID_G1  1
#define ID_H2  2
#define ID_GAT 3
#define ID_H3  4
#define ID_G2  5
#define ID_CAT 6
#define ID_MH  7

__device__ __forceinline__ float* buf(int id) {
    switch (id) {
        case ID_H1:  return g_h1;
        case ID_G1:  return g_g1;
        case ID_H2:  return g_h2;
        case ID_GAT: return g_gat;
        case ID_H3:  return g_h3;
        case ID_G2:  return g_g2;
        case ID_CAT: return g_cat;
        default:     return g_mh;
    }
}

__device__ __forceinline__ float lrelu(float x) { return x >= 0.f ? x : 0.2f * x; }

__device__ __forceinline__ uint32_t tf32r(float f) {
    uint32_t u;
    asm("cvt.rna.tf32.f32 %0, %1;" : "=r"(u) : "f"(f));
    return u;
}

__device__ __forceinline__ void cpasync16(uint32_t dst, const void* src, int sz) {
    asm volatile("cp.async.cg.shared.global [%0], [%1], 16, %2;\n"
                 :: "r"(dst), "l"(src), "r"(sz));
}

// ---------------- CSR build --------------------------------------------------
__global__ void k_zero() {
    int i = blockIdx.x * blockDim.x + threadIdx.x;
    if (i < NN) { g_cnt[i] = 0; g_cursor[i] = 0; }
}
__global__ void k_count(const int* __restrict__ ei) {
    int e = blockIdx.x * blockDim.x + threadIdx.x;
    if (e < EE) atomicAdd(&g_cnt[ei[EE + e]], 1);
}
__global__ void __launch_bounds__(1024) k_scan() {
    __shared__ int s_w[32];
    __shared__ int s_carry;
    int tid = threadIdx.x, lane = tid & 31, wid = tid >> 5;
    if (tid == 0) s_carry = 0;
    __syncthreads();
    for (int base = 0; base < NN; base += 1024) {
        int i = base + tid;
        int v = (i < NN) ? g_cnt[i] : 0;
        if (i < NN) g_dinv[i] = rsqrtf((float)(v + 1));
        int x = v;
#pragma unroll
        for (int o = 1; o < 32; o <<= 1) {
            int t = __shfl_up_sync(0xffffffffu, x, o);
            if (lane >= o) x += t;
        }
        if (lane == 31) s_w[wid] = x;
        __syncthreads();
        if (wid == 0) {
            int y = s_w[lane];
#pragma unroll
            for (int o = 1; o < 32; o <<= 1) {
                int t = __shfl_up_sync(0xffffffffu, y, o);
                if (lane >= o) y += t;
            }
            s_w[lane] = y;
        }
        __syncthreads();
        int woff = (wid > 0) ? s_w[wid - 1] : 0;
        int incl = x + woff;
        int c0 = s_carry;
        if (i < NN) g_rowptr[i] = c0 + incl - v;
        int tot = s_w[31];
        __syncthreads();
        if (tid == 0) s_carry = c0 + tot;
        __syncthreads();
    }
    if (tid == 0) g_rowptr[NN] = s_carry;
}
__global__ void k_fill(const int* __restrict__ ei) {
    int e = blockIdx.x * blockDim.x + threadIdx.x;
    if (e >= EE) return;
    int d = ei[EE + e];
    int pos = atomicAdd(&g_cursor[d], 1);
    g_col[g_rowptr[d] + pos] = ei[e];
}

// ---------------- TF32 tensor-core GEMM, 3-stage cp.async pipeline -----------
// hmode: A column block follows the output column block (per-head GEMM)
#define STAGES 3
#define AST 20
#define BST 132
#define SGEMM_SMEM ((STAGES * 128 * AST + STAGES * 16 * BST) * 4)

__global__ void __launch_bounds__(256) k_sgemm(
    const float* __restrict__ Aext, int Aid,
    const float* __restrict__ B, const float* __restrict__ bias,
    int Cid, int M, int Nc, int K, int lda, int hmode, int doRelu)
{
    extern __shared__ float dsm[];
    float (*Asm)[128][AST] = (float (*)[128][AST])dsm;
    float (*Bsm)[16][BST]  = (float (*)[16][BST])(dsm + STAGES * 128 * AST);

    const float* A = Aext ? Aext : buf(Aid);
    float* C = buf(Cid);

    int tid  = threadIdx.x;
    int lane = tid & 31;
    int w    = tid >> 5;
    int wm   = w >> 2;
    int wn   = w & 3;
    int m0   = wm * 64;
    int n0   = wn * 32;
    int brow = blockIdx.y * 128;
    int bcol = blockIdx.x * 128;
    if (hmode) A += bcol;          // per-head A column block

    int r  = lane >> 2;
    int cA = lane & 3;

    float acc[4][4][4];
#pragma unroll
    for (int i = 0; i < 4; i++)
#pragma unroll
        for (int j = 0; j < 4; j++)
#pragma unroll
            for (int q = 0; q < 4; q++) acc[i][j][q] = 0.f;

    int amr[2], amk[2], aok[2];
    int bkr[2], bnn[2];
#pragma unroll
    for (int i = 0; i < 2; i++) {
        int chunk = tid + i * 256;
        amr[i] = chunk >> 2;
        amk[i] = (chunk & 3) * 4;
        aok[i] = (brow + amr[i] < M) ? 16 : 0;
        bkr[i] = chunk >> 5;
        bnn[i] = (chunk & 31) * 4;
    }

    int ktiles = K >> 4;

#pragma unroll
    for (int s = 0; s < STAGES - 1; s++) {
        int kt = s << 4;
#pragma unroll
        for (int i = 0; i < 2; i++) {
            uint32_t ad = (uint32_t)__cvta_generic_to_shared(&Asm[s][amr[i]][amk[i]]);
            cpasync16(ad, &A[(size_t)(brow + amr[i]) * lda + kt + amk[i]], aok[i]);
        }
#pragma unroll
        for (int i = 0; i < 2; i++) {
            uint32_t bd = (uint32_t)__cvta_generic_to_shared(&Bsm[s][bkr[i]][bnn[i]]);
            cpasync16(bd, &B[(size_t)(kt + bkr[i]) * Nc + bcol + bnn[i]], 16);
        }
        asm volatile("cp.async.commit_group;\n" ::);
    }

    for (int t = 0; t < ktiles; t++) {
        asm volatile("cp.async.wait_group %0;\n" :: "n"(STAGES - 2));
        __syncthreads();

        int tn = t + STAGES - 1;
        if (tn < ktiles) {
            int s = tn % STAGES;
            int kt = tn << 4;
#pragma unroll
            for (int i = 0; i < 2; i++) {
                uint32_t ad = (uint32_t)__cvta_generic_to_shared(&Asm[s][amr[i]][amk[i]]);
                cpasync16(ad, &A[(size_t)(brow + amr[i]) * lda + kt + amk[i]], aok[i]);
            }
#pragma unroll
            for (int i = 0; i < 2; i++) {
                uint32_t bd = (uint32_t)__cvta_generic_to_shared(&Bsm[s][bkr[i]][bnn[i]]);
                cpasync16(bd, &B[(size_t)(kt + bkr[i]) * Nc + bcol + bnn[i]], 16);
            }
        }
        asm volatile("cp.async.commit_group;\n" ::);

        const float (*As)[AST] = Asm[t % STAGES];
        const float (*Bs)[BST] = Bsm[t % STAGES];

#pragma unroll
        for (int ks = 0; ks < 16; ks += 8) {
            uint32_t af[4][4];
#pragma unroll
            for (int mi = 0; mi < 4; mi++) {
                int mrow = m0 + mi * 16 + r;
                af[mi][0] = tf32r(As[mrow][ks + cA]);
                af[mi][1] = tf32r(As[mrow + 8][ks + cA]);
                af[mi][2] = tf32r(As[mrow][ks + cA + 4]);
                af[mi][3] = tf32r(As[mrow + 8][ks + cA + 4]);
            }
            uint32_t bf[4][2];
#pragma unroll
            for (int ni = 0; ni < 4; ni++) {
                int ncol = n0 + ni * 8 + r;
                bf[ni][0] = tf32r(Bs[ks + cA][ncol]);
                bf[ni][1] = tf32r(Bs[ks + cA + 4][ncol]);
            }
#pragma unroll
            for (int mi = 0; mi < 4; mi++)
#pragma unroll
                for (int ni = 0; ni < 4; ni++) {
                    asm volatile(
                        "mma.sync.aligned.m16n8k8.row.col.f32.tf32.tf32.f32 "
                        "{%0,%1,%2,%3}, {%4,%5,%6,%7}, {%8,%9}, {%0,%1,%2,%3};"
                        : "+f"(acc[mi][ni][0]), "+f"(acc[mi][ni][1]),
                          "+f"(acc[mi][ni][2]), "+f"(acc[mi][ni][3])
                        : "r"(af[mi][0]), "r"(af[mi][1]), "r"(af[mi][2]), "r"(af[mi][3]),
                          "r"(bf[ni][0]), "r"(bf[ni][1]));
                }
        }
        __syncthreads();
    }

#pragma unroll
    for (int mi = 0; mi < 4; mi++) {
        int row0 = brow + m0 + mi * 16 + (lane >> 2);
#pragma unroll
        for (int ni = 0; ni < 4; ni++) {
            int col = bcol + n0 + ni * 8 + 2 * (lane & 3);
            float bx = bias ? bias[col]     : 0.f;
            float by = bias ? bias[col + 1] : 0.f;
            float v0 = acc[mi][ni][0] + bx;
            float v1 = acc[mi][ni][1] + by;
            float v2 = acc[mi][ni][2] + bx;
            float v3 = acc[mi][ni][3] + by;
            if (doRelu) {
                v0 = fmaxf(v0, 0.f); v1 = fmaxf(v1, 0.f);
                v2 = fmaxf(v2, 0.f); v3 = fmaxf(v3, 0.f);
            }
            if (row0 < M) {
                C[(size_t)row0 * Nc + col]     = v0;
                C[(size_t)row0 * Nc + col + 1] = v1;
            }
            if (row0 + 8 < M) {
                C[(size_t)(row0 + 8) * Nc + col]     = v2;
                C[(size_t)(row0 + 8) * Nc + col + 1] = v3;
            }
        }
    }
}

// ---------------- GCN gather (CSR) ------------------------------------------
__global__ void __launch_bounds__(128) k_gcn_gather(
    int Hid, int Oid, const float* __restrict__ bias, int C, int doRelu)
{
    int tpn = C >> 2;
    int npb = 128 / tpn;
    int local = threadIdx.x / tpn;
    int lane  = threadIdx.x - local * tpn;
    int n = blockIdx.x * npb + local;
    if (n >= NN) return;
    int c = lane * 4;
    const float* H = buf(Hid);
    float* O = buf(Oid);

    float4 hv = *(const float4*)&H[(size_t)n * C + c];
    float dn = g_dinv[n];
    float4 acc;
    acc.x = hv.x * dn; acc.y = hv.y * dn; acc.z = hv.z * dn; acc.w = hv.w * dn;

    int start = g_rowptr[n], end = g_rowptr[n + 1];
    for (int i = start; i < end; i++) {
        int s = g_col[i];
        float wgt = g_dinv[s];
        float4 v = *(const float4*)&H[(size_t)s * C + c];
        acc.x += v.x * wgt; acc.y += v.y * wgt; acc.z += v.z * wgt; acc.w += v.w * wgt;
    }
    float4 o;
    o.x = acc.x * dn + bias[c + 0];
    o.y = acc.y * dn + bias[c + 1];
    o.z = acc.z * dn + bias[c + 2];
    o.w = acc.w * dn + bias[c + 3];
    if (doRelu) {
        o.x = fmaxf(o.x, 0.f); o.y = fmaxf(o.y, 0.f);
        o.z = fmaxf(o.z, 0.f); o.w = fmaxf(o.w, 0.f);
    }
    *(float4*)&O[(size_t)n * C + c] = o;
}

// ---------------- GAT --------------------------------------------------------
// w~ precompute: wtilS[h][c] = sum_k gat_w[c, h*128+k] * att_s[h,k]
__global__ void k_wtil(const float* __restrict__ gat_w,
                       const float* __restrict__ attS, const float* __restrict__ attD)
{
    int t = blockIdx.x * blockDim.x + threadIdx.x;
    if (t >= HEADS * C1) return;
    int h = t >> 7;          // wtil layout [h][c]
    int c = t & 127;
    const float* wr = &gat_w[(size_t)c * C2 + h * 128];
    const float* as = &attS[h * 128];
    const float* ad = &attD[h * 128];
    float ss = 0.f, sd = 0.f;
#pragma unroll 4
    for (int k = 0; k < 128; k++) {
        float wv = wr[k];
        ss += wv * as[k];
        sd += wv * ad[k];
    }
    g_wtilS[t] = ss;
    g_wtilD[t] = sd;
}

// attention logits from g1 directly: warp per node
__global__ void __launch_bounds__(256) k_att2() {
    __shared__ float sws[HEADS * C1], swd[HEADS * C1];
    int tid = threadIdx.x;
    for (int i = tid; i < HEADS * C1; i += 256) { sws[i] = g_wtilS[i]; swd[i] = g_wtilD[i]; }
    __syncthreads();
    int n = (blockIdx.x * 256 + tid) >> 5;
    int lane = tid & 31;
    if (n >= NN) return;
    float ss[HEADS] = {0,0,0,0}, sd[HEADS] = {0,0,0,0};
    for (int c = lane; c < C1; c += 32) {
        float v = g_g1[(size_t)n * C1 + c];
#pragma unroll
        for (int h = 0; h < HEADS; h++) {
            ss[h] += v * sws[h * C1 + c];
            sd[h] += v * swd[h * C1 + c];
        }
    }
#pragma unroll
    for (int h = 0; h < HEADS; h++)
#pragma unroll
        for (int o = 16; o; o >>= 1) {
            ss[h] += __shfl_xor_sync(0xffffffffu, ss[h], o);
            sd[h] += __shfl_xor_sync(0xffffffffu, sd[h], o);
        }
    if (lane == 0) {
#pragma unroll
        for (int h = 0; h < HEADS; h++) {
            g_asrc[n * HEADS + h] = ss[h];
            g_adst[n * HEADS + h] = sd[h];
        }
    }
}

// softmax per dst node: one warp per node; writes normalized alpha + aself
__global__ void k_gat_softmax() {
    int n = (blockIdx.x * blockDim.x + threadIdx.x) >> 5;
    int lane = threadIdx.x & 31;
    if (n >= NN) return;
    int start = g_rowptr[n], end = g_rowptr[n + 1];

    float adst[HEADS], selfe[HEADS];
#pragma unroll
    for (int h = 0; h < HEADS; h++) {
        adst[h]  = g_adst[n * HEADS + h];
        selfe[h] = lrelu(g_asrc[n * HEADS + h] + adst[h]);
    }

    float mx[HEADS];
#pragma unroll
    for (int h = 0; h < HEADS; h++) mx[h] = selfe[h];
    for (int i = start + lane; i < end; i += 32) {
        int s = g_col[i];
#pragma unroll
        for (int h = 0; h < HEADS; h++)
            mx[h] = fmaxf(mx[h], lrelu(g_asrc[s * HEADS + h] + adst[h]));
    }
#pragma unroll
    for (int h = 0; h < HEADS; h++)
#pragma unroll
        for (int o = 16; o; o >>= 1)
            mx[h] = fmaxf(mx[h], __shfl_xor_sync(0xffffffffu, mx[h], o));

    float zz[HEADS];
#pragma unroll
    for (int h = 0; h < HEADS; h++) zz[h] = (lane == 0) ? __expf(selfe[h] - mx[h]) : 0.f;
    for (int i = start + lane; i < end; i += 32) {
        int s = g_col[i];
        float4 ev;
        ev.x = __expf(lrelu(g_asrc[s * HEADS + 0] + adst[0]) - mx[0]);
        ev.y = __expf(lrelu(g_asrc[s * HEADS + 1] + adst[1]) - mx[1]);
        ev.z = __expf(lrelu(g_asrc[s * HEADS + 2] + adst[2]) - mx[2]);
        ev.w = __expf(lrelu(g_asrc[s * HEADS + 3] + adst[3]) - mx[3]);
        *(float4*)&g_alpha[(size_t)i * HEADS] = ev;
        zz[0] += ev.x; zz[1] += ev.y; zz[2] += ev.z; zz[3] += ev.w;
    }
#pragma unroll
    for (int h = 0; h < HEADS; h++)
#pragma unroll
        for (int o = 16; o; o >>= 1)
            zz[h] += __shfl_xor_sync(0xffffffffu, zz[h], o);

    float rz[HEADS];
#pragma unroll
    for (int h = 0; h < HEADS; h++) rz[h] = 1.0f / zz[h];

    for (int i = start + lane; i < end; i += 32) {
        float4 a = *(float4*)&g_alpha[(size_t)i * HEADS];
        a.x *= rz[0]; a.y *= rz[1]; a.z *= rz[2]; a.w *= rz[3];
        *(float4*)&g_alpha[(size_t)i * HEADS] = a;
    }
    if (lane == 0) {
#pragma unroll
        for (int h = 0; h < HEADS; h++)
            g_aself[n * HEADS + h] = __expf(selfe[h] - mx[h]) * rz[h];
    }
}

// pre-projection aggregation: p[n,h,c] = aself_h*g1[n,c] + sum alpha_h*g1[src,c]
#define GCHUNK 64
__global__ void __launch_bounds__(128) k_gat_agg2() {
    int n = blockIdx.x;
    int tid = threadIdx.x;     // channel c = tid
    int start = g_rowptr[n], end = g_rowptr[n + 1];

    __shared__ int    s_src[GCHUNK];
    __shared__ float4 s_al [GCHUNK];

    float g1v = g_g1[(size_t)n * C1 + tid];
    float4 as = *(const float4*)&g_aself[n * HEADS];
    float a0 = g1v * as.x, a1 = g1v * as.y, a2 = g1v * as.z, a3 = g1v * as.w;

    for (int base = start; base < end; base += GCHUNK) {
        int cnt = min(GCHUNK, end - base);
        if (tid < cnt) {
            s_src[tid] = g_col[base + tid];
            s_al[tid]  = *(const float4*)&g_alpha[(size_t)(base + tid) * HEADS];
        }
        __syncthreads();
        for (int j = 0; j < cnt; j++) {
            float v = g_g1[(size_t)s_src[j] * C1 + tid];
            float4 al = s_al[j];
            a0 += al.x * v; a1 += al.y * v; a2 += al.z * v; a3 += al.w * v;
        }
        __syncthreads();
    }

    float* p = &g_h2[(size_t)n * C2];
    p[0 * C1 + tid] = a0;
    p[1 * C1 + tid] = a1;
    p[2 * C1 + tid] = a2;
    p[3 * C1 + tid] = a3;
}

// ---------------- LayerNorm --------------------------------------------------
__global__ void k_ln(int Xid, int Yid, const float* __restrict__ gw,
                     const float* __restrict__ bw, int C, int ldY, int doRelu)
{
    int n = blockIdx.x;
    const float* x = buf(Xid) + (size_t)n * C;
    float* y = buf(Yid) + (size_t)n * ldY;
    int tid = threadIdx.x, lane = tid & 31, warp = tid >> 5;

    float s = 0.f, s2 = 0.f;
    for (int c = tid; c < C; c += 128) {
        float v = x[c];
        s += v; s2 += v * v;
    }
#pragma unroll
    for (int o = 16; o; o >>= 1) {
        s  += __shfl_xor_sync(0xffffffffu, s, o);
        s2 += __shfl_xor_sync(0xffffffffu, s2, o);
    }
    __shared__ float shs[4], shs2[4], smu, sinv;
    if (lane == 0) { shs[warp] = s; shs2[warp] = s2; }
    __syncthreads();
    if (tid == 0) {
        float S = shs[0] + shs[1] + shs[2] + shs[3];
        float S2 = shs2[0] + shs2[1] + shs2[2] + shs2[3];
        float mu = S / C;
        float var = S2 / C - mu * mu;
        smu = mu;
        sinv = rsqrtf(var + 1e-5f);
    }
    __syncthreads();
    float mu = smu, inv = sinv;
    for (int c = tid; c < C; c += 128) {
        float v = (x[c] - mu) * inv * gw[c] + bw[c];
        if (doRelu) v = fmaxf(v, 0.f);
        y[c] = v;
    }
}

__global__ void k_catx(const float* __restrict__ x) {
    int idx = blockIdx.x * blockDim.x + threadIdx.x;
    if (idx >= NN * C1) return;
    int n = idx / C1, c = idx - n * C1;
    g_cat[(size_t)n * CCAT + C3 + c] = x[idx];
}

__global__ void k_out(const float* __restrict__ w2, const float* __restrict__ b2,
                      float* __restrict__ out)
{
    int gw = (blockIdx.x * blockDim.x + threadIdx.x) >> 5;
    int lane = threadIdx.x & 31;
    if (gw >= NN) return;
    const float* hp = &g_mh[(size_t)gw * CM];
    float a0 = 0.f, a1 = 0.f;
#pragma unroll
    for (int c = lane; c < CM; c += 32) {
        float v = hp[c];
        a0 += v * w2[c * 2];
        a1 += v * w2[c * 2 + 1];
    }
#pragma unroll
    for (int o = 16; o; o >>= 1) {
        a0 += __shfl_xor_sync(0xffffffffu, a0, o);
        a1 += __shfl_xor_sync(0xffffffffu, a1, o);
    }
    if (lane == 0) {
        out[gw * 2 + 0] = a0 + b2[0];
        out[gw * 2 + 1] = a1 + b2[1];
    }
}

// ---------------- launch -----------------------------------------------------
static inline int cdiv(int a, int b) { return (a + b - 1) / b; }

extern "C" void kernel_launch(void* const* d_in, const int* in_sizes, int n_in,
                              void* d_out, int out_size)
{
    (void)in_sizes; (void)n_in; (void)out_size;
    const float* x      = (const float*)d_in[0];
    const int*   ei     = (const int*)d_in[1];
    const float* gcn1_w = (const float*)d_in[2];
    const float* gcn1_b = (const float*)d_in[3];
    const float* gat_w  = (const float*)d_in[4];
    const float* att_s  = (const float*)d_in[5];
    const float* att_d  = (const float*)d_in[6];
    const float* gat_b  = (const float*)d_in[7];
    const float* n1_g   = (const float*)d_in[8];
    const float* n1_b   = (const float*)d_in[9];
    const float* gcn2_w = (const float*)d_in[10];
    const float* gcn2_b = (const float*)d_in[11];
    const float* n2_g   = (const float*)d_in[12];
    const float* n2_b   = (const float*)d_in[13];
    const float* mlp_w1 = (const float*)d_in[14];
    const float* mlp_b1 = (const float*)d_in[15];
    const float* mlp_w2 = (const float*)d_in[16];
    const float* mlp_b2 = (const float*)d_in[17];
    float* out = (float*)d_out;

    const int T = 256;
    int mblk = cdiv(NN, 128);

    cudaFuncSetAttribute(k_sgemm, cudaFuncAttributeMaxDynamicSharedMemorySize, SGEMM_SMEM);

    // CSR build
    k_zero <<<cdiv(NN, T), T>>>();
    k_count<<<cdiv(EE, T), T>>>(ei);
    k_scan <<<1, 1024>>>();
    k_fill <<<cdiv(EE, T), T>>>(ei);

    // GCN1
    k_sgemm<<<dim3(1, mblk), T, SGEMM_SMEM>>>(x, -1, gcn1_w, nullptr, ID_H1, NN, C1, C1, C1, 0, 0);
    k_gcn_gather<<<NN / 4, 128>>>(ID_H1, ID_G1, gcn1_b, C1, 1);

    // GAT: logits from g1; aggregate g1; then per-head projection GEMM
    k_wtil<<<cdiv(HEADS * C1, T), T>>>(gat_w, att_s, att_d);
    k_att2<<<cdiv(NN * 32, T), T>>>();
    k_gat_softmax<<<cdiv(NN * 32, T), T>>>();
    k_gat_agg2<<<NN, 128>>>();
    k_sgemm<<<dim3(C2 / 128, mblk), T, SGEMM_SMEM>>>(nullptr, ID_H2, gat_w, gat_b, ID_GAT, NN, C2, C1, C2, 1, 0);

    // LN1
    k_ln<<<NN, 128>>>(ID_GAT, ID_GAT, n1_g, n1_b, C2, C2, 0);

    // GCN2
    k_sgemm<<<dim3(C3 / 128, mblk), T, SGEMM_SMEM>>>(nullptr, ID_GAT, gcn2_w, nullptr, ID_H3, NN, C3, C2, C2, 0, 0);
    k_gcn_gather<<<NN / 2, 128>>>(ID_H3, ID_G2, gcn2_b, C3, 0);

    // LN2 + concat
    k_ln<<<NN, 128>>>(ID_G2, ID_CAT, n2_g, n2_b, C3, CCAT, 1);
    k_catx<<<cdiv(NN * C1, T), T>>>(x);

    // MLP
    k_sgemm<<<dim3(CM / 128, mblk), T, SGEMM_SMEM>>>(nullptr, ID_CAT, mlp_w1, mlp_b1, ID_MH, NN, CM, CCAT, CCAT, 0, 1);
    k_out<<<cdiv(NN * 32, T), T>>>(mlp_w2, mlp_b2, out);
}

// round 10
// speedup vs baseline: 4.1613x; 1.0041x over previous
#include <cuda_runtime.h>
#include <cstdint>

#define NN   50000
#define EE   800000
#define C1   128
#define C2   512
#define C3   256
#define CCAT 384
#define CM   128
#define HEADS 4

// ---------------- scratch (static device globals; no allocation) -------------
__device__ float    g_dinv[NN];
__device__ int      g_cnt[NN];
__device__ int      g_cursor[NN];
__device__ int      g_rowptr[NN + 1];
__device__ int      g_col[EE];          // src node per dst-sorted edge
__device__ float    g_h1 [NN*C1];
__device__ float    g_g1 [NN*C1];
__device__ float    g_h2 [NN*C2];      // reused as p[n][h][128]
__device__ float    g_gat[NN*C2];
__device__ float    g_h3 [NN*C3];
__device__ float    g_g2 [NN*C3];
__device__ float    g_cat[NN*CCAT];
__device__ float    g_mh [NN*CM];
__device__ float    g_asrc[NN*HEADS];
__device__ float    g_adst[NN*HEADS];
__device__ float    g_aself[NN*HEADS];
__device__ float    g_alpha[(size_t)EE*HEADS];
__device__ float    g_wtilS[HEADS*C1];  // [h][c]
__device__ float    g_wtilD[HEADS*C1];

#define ID_H1  0
#define ID_G1  1
#define ID_H2  2
#define ID_GAT 3
#define ID_H3  4
#define ID_G2  5
#define ID_CAT 6
#define ID_MH  7

__device__ __forceinline__ float* buf(int id) {
    switch (id) {
        case ID_H1:  return g_h1;
        case ID_G1:  return g_g1;
        case ID_H2:  return g_h2;
        case ID_GAT: return g_gat;
        case ID_H3:  return g_h3;
        case ID_G2:  return g_g2;
        case ID_CAT: return g_cat;
        default:     return g_mh;
    }
}

__device__ __forceinline__ float lrelu(float x) { return x >= 0.f ? x : 0.2f * x; }

__device__ __forceinline__ uint32_t tf32r(float f) {
    uint32_t u;
    asm("cvt.rna.tf32.f32 %0, %1;" : "=r"(u) : "f"(f));
    return u;
}

__device__ __forceinline__ void cpasync16(uint32_t dst, const void* src, int sz) {
    asm volatile("cp.async.cg.shared.global [%0], [%1], 16, %2;\n"
                 :: "r"(dst), "l"(src), "r"(sz));
}

// ---------------- CSR build --------------------------------------------------
__global__ void k_zero() {
    int i = blockIdx.x * blockDim.x + threadIdx.x;
    if (i < NN) { g_cnt[i] = 0; g_cursor[i] = 0; }
}
__global__ void k_count(const int* __restrict__ ei) {
    int e = blockIdx.x * blockDim.x + threadIdx.x;
    if (e < EE) atomicAdd(&g_cnt[ei[EE + e]], 1);
}
__global__ void __launch_bounds__(1024) k_scan() {
    __shared__ int s_w[32];
    __shared__ int s_carry;
    int tid = threadIdx.x, lane = tid & 31, wid = tid >> 5;
    if (tid == 0) s_carry = 0;
    __syncthreads();
    for (int base = 0; base < NN; base += 1024) {
        int i = base + tid;
        int v = (i < NN) ? g_cnt[i] : 0;
        if (i < NN) g_dinv[i] = rsqrtf((float)(v + 1));
        int x = v;
#pragma unroll
        for (int o = 1; o < 32; o <<= 1) {
            int t = __shfl_up_sync(0xffffffffu, x, o);
            if (lane >= o) x += t;
        }
        if (lane == 31) s_w[wid] = x;
        __syncthreads();
        if (wid == 0) {
            int y = s_w[lane];
#pragma unroll
            for (int o = 1; o < 32; o <<= 1) {
                int t = __shfl_up_sync(0xffffffffu, y, o);
                if (lane >= o) y += t;
            }
            s_w[lane] = y;
        }
        __syncthreads();
        int woff = (wid > 0) ? s_w[wid - 1] : 0;
        int incl = x + woff;
        int c0 = s_carry;
        if (i < NN) g_rowptr[i] = c0 + incl - v;
        int tot = s_w[31];
        __syncthreads();
        if (tid == 0) s_carry = c0 + tot;
        __syncthreads();
    }
    if (tid == 0) g_rowptr[NN] = s_carry;
}
__global__ void k_fill(const int* __restrict__ ei) {
    int e = blockIdx.x * blockDim.x + threadIdx.x;
    if (e >= EE) return;
    int d = ei[EE + e];
    int pos = atomicAdd(&g_cursor[d], 1);
    g_col[g_rowptr[d] + pos] = ei[e];
}

// ---------------- TF32 tensor-core GEMM, 3-stage cp.async pipeline -----------
// hmode: A column block follows the output column block (per-head GEMM)
#define STAGES 3
#define AST 20
#define BST 132
#define SGEMM_SMEM ((STAGES * 128 * AST + STAGES * 16 * BST) * 4)

__global__ void __launch_bounds__(256) k_sgemm(
    const float* __restrict__ Aext, int Aid,
    const float* __restrict__ B, const float* __restrict__ bias,
    int Cid, int M, int Nc, int K, int lda, int hmode, int doRelu)
{
    extern __shared__ float dsm[];
    float (*Asm)[128][AST] = (float (*)[128][AST])dsm;
    float (*Bsm)[16][BST]  = (float (*)[16][BST])(dsm + STAGES * 128 * AST);

    const float* A = Aext ? Aext : buf(Aid);
    float* C = buf(Cid);

    int tid  = threadIdx.x;
    int lane = tid & 31;
    int w    = tid >> 5;
    int wm   = w >> 2;
    int wn   = w & 3;
    int m0   = wm * 64;
    int n0   = wn * 32;
    int brow = blockIdx.y * 128;
    int bcol = blockIdx.x * 128;
    if (hmode) A += bcol;          // per-head A column block

    int r  = lane >> 2;
    int cA = lane & 3;

    float acc[4][4][4];
#pragma unroll
    for (int i = 0; i < 4; i++)
#pragma unroll
        for (int j = 0; j < 4; j++)
#pragma unroll
            for (int q = 0; q < 4; q++) acc[i][j][q] = 0.f;

    int amr[2], amk[2], aok[2];
    int bkr[2], bnn[2];
#pragma unroll
    for (int i = 0; i < 2; i++) {
        int chunk = tid + i * 256;
        amr[i] = chunk >> 2;
        amk[i] = (chunk & 3) * 4;
        aok[i] = (brow + amr[i] < M) ? 16 : 0;
        bkr[i] = chunk >> 5;
        bnn[i] = (chunk & 31) * 4;
    }

    int ktiles = K >> 4;

#pragma unroll
    for (int s = 0; s < STAGES - 1; s++) {
        int kt = s << 4;
#pragma unroll
        for (int i = 0; i < 2; i++) {
            uint32_t ad = (uint32_t)__cvta_generic_to_shared(&Asm[s][amr[i]][amk[i]]);
            cpasync16(ad, &A[(size_t)(brow + amr[i]) * lda + kt + amk[i]], aok[i]);
        }
#pragma unroll
        for (int i = 0; i < 2; i++) {
            uint32_t bd = (uint32_t)__cvta_generic_to_shared(&Bsm[s][bkr[i]][bnn[i]]);
            cpasync16(bd, &B[(size_t)(kt + bkr[i]) * Nc + bcol + bnn[i]], 16);
        }
        asm volatile("cp.async.commit_group;\n" ::);
    }

    for (int t = 0; t < ktiles; t++) {
        asm volatile("cp.async.wait_group %0;\n" :: "n"(STAGES - 2));
        __syncthreads();

        int tn = t + STAGES - 1;
        if (tn < ktiles) {
            int s = tn % STAGES;
            int kt = tn << 4;
#pragma unroll
            for (int i = 0; i < 2; i++) {
                uint32_t ad = (uint32_t)__cvta_generic_to_shared(&Asm[s][amr[i]][amk[i]]);
                cpasync16(ad, &A[(size_t)(brow + amr[i]) * lda + kt + amk[i]], aok[i]);
            }
#pragma unroll
            for (int i = 0; i < 2; i++) {
                uint32_t bd = (uint32_t)__cvta_generic_to_shared(&Bsm[s][bkr[i]][bnn[i]]);
                cpasync16(bd, &B[(size_t)(kt + bkr[i]) * Nc + bcol + bnn[i]], 16);
            }
        }
        asm volatile("cp.async.commit_group;\n" ::);

        const float (*As)[AST] = Asm[t % STAGES];
        const float (*Bs)[BST] = Bsm[t % STAGES];

#pragma unroll
        for (int ks = 0; ks < 16; ks += 8) {
            uint32_t af[4][4];
#pragma unroll
            for (int mi = 0; mi < 4; mi++) {
                int mrow = m0 + mi * 16 + r;
                af[mi][0] = tf32r(As[mrow][ks + cA]);
                af[mi][1] = tf32r(As[mrow + 8][ks + cA]);
                af[mi][2] = tf32r(As[mrow][ks + cA + 4]);
                af[mi][3] = tf32r(As[mrow + 8][ks + cA + 4]);
            }
            uint32_t bf[4][2];
#pragma unroll
            for (int ni = 0; ni < 4; ni++) {
                int ncol = n0 + ni * 8 + r;
                bf[ni][0] = tf32r(Bs[ks + cA][ncol]);
                bf[ni][1] = tf32r(Bs[ks + cA + 4][ncol]);
            }
#pragma unroll
            for (int mi = 0; mi < 4; mi++)
#pragma unroll
                for (int ni = 0; ni < 4; ni++) {
                    asm volatile(
                        "mma.sync.aligned.m16n8k8.row.col.f32.tf32.tf32.f32 "
                        "{%0,%1,%2,%3}, {%4,%5,%6,%7}, {%8,%9}, {%0,%1,%2,%3};"
                        : "+f"(acc[mi][ni][0]), "+f"(acc[mi][ni][1]),
                          "+f"(acc[mi][ni][2]), "+f"(acc[mi][ni][3])
                        : "r"(af[mi][0]), "r"(af[mi][1]), "r"(af[mi][2]), "r"(af[mi][3]),
                          "r"(bf[ni][0]), "r"(bf[ni][1]));
                }
        }
        __syncthreads();
    }

#pragma unroll
    for (int mi = 0; mi < 4; mi++) {
        int row0 = brow + m0 + mi * 16 + (lane >> 2);
#pragma unroll
        for (int ni = 0; ni < 4; ni++) {
            int col = bcol + n0 + ni * 8 + 2 * (lane & 3);
            float bx = bias ? bias[col]     : 0.f;
            float by = bias ? bias[col + 1] : 0.f;
            float v0 = acc[mi][ni][0] + bx;
            float v1 = acc[mi][ni][1] + by;
            float v2 = acc[mi][ni][2] + bx;
            float v3 = acc[mi][ni][3] + by;
            if (doRelu) {
                v0 = fmaxf(v0, 0.f); v1 = fmaxf(v1, 0.f);
                v2 = fmaxf(v2, 0.f); v3 = fmaxf(v3, 0.f);
            }
            if (row0 < M) {
                C[(size_t)row0 * Nc + col]     = v0;
                C[(size_t)row0 * Nc + col + 1] = v1;
            }
            if (row0 + 8 < M) {
                C[(size_t)(row0 + 8) * Nc + col]     = v2;
                C[(size_t)(row0 + 8) * Nc + col + 1] = v3;
            }
        }
    }
}

// ---------------- GCN gather (CSR) ------------------------------------------
__global__ void __launch_bounds__(128) k_gcn_gather(
    int Hid, int Oid, const float* __restrict__ bias, int C, int doRelu)
{
    int tpn = C >> 2;
    int npb = 128 / tpn;
    int local = threadIdx.x / tpn;
    int lane  = threadIdx.x - local * tpn;
    int n = blockIdx.x * npb + local;
    if (n >= NN) return;
    int c = lane * 4;
    const float* H = buf(Hid);
    float* O = buf(Oid);

    float4 hv = *(const float4*)&H[(size_t)n * C + c];
    float dn = g_dinv[n];
    float4 acc;
    acc.x = hv.x * dn; acc.y = hv.y * dn; acc.z = hv.z * dn; acc.w = hv.w * dn;

    int start = g_rowptr[n], end = g_rowptr[n + 1];
    for (int i = start; i < end; i++) {
        int s = g_col[i];
        float wgt = g_dinv[s];
        float4 v = *(const float4*)&H[(size_t)s * C + c];
        acc.x += v.x * wgt; acc.y += v.y * wgt; acc.z += v.z * wgt; acc.w += v.w * wgt;
    }
    float4 o;
    o.x = acc.x * dn + bias[c + 0];
    o.y = acc.y * dn + bias[c + 1];
    o.z = acc.z * dn + bias[c + 2];
    o.w = acc.w * dn + bias[c + 3];
    if (doRelu) {
        o.x = fmaxf(o.x, 0.f); o.y = fmaxf(o.y, 0.f);
        o.z = fmaxf(o.z, 0.f); o.w = fmaxf(o.w, 0.f);
    }
    *(float4*)&O[(size_t)n * C + c] = o;
}

// ---------------- GAT --------------------------------------------------------
// w~ precompute: wtilS[h][c] = sum_k gat_w[c, h*128+k] * att_s[h,k]
__global__ void k_wtil(const float* __restrict__ gat_w,
                       const float* __restrict__ attS, const float* __restrict__ attD)
{
    int t = blockIdx.x * blockDim.x + threadIdx.x;
    if (t >= HEADS * C1) return;
    int h = t >> 7;          // wtil layout [h][c]
    int c = t & 127;
    const float* wr = &gat_w[(size_t)c * C2 + h * 128];
    const float* as = &attS[h * 128];
    const float* ad = &attD[h * 128];
    float ss = 0.f, sd = 0.f;
#pragma unroll 4
    for (int k = 0; k < 128; k++) {
        float wv = wr[k];
        ss += wv * as[k];
        sd += wv * ad[k];
    }
    g_wtilS[t] = ss;
    g_wtilD[t] = sd;
}

// attention logits from g1 directly: warp per node
__global__ void __launch_bounds__(256) k_att2() {
    __shared__ float sws[HEADS * C1], swd[HEADS * C1];
    int tid = threadIdx.x;
    for (int i = tid; i < HEADS * C1; i += 256) { sws[i] = g_wtilS[i]; swd[i] = g_wtilD[i]; }
    __syncthreads();
    int n = (blockIdx.x * 256 + tid) >> 5;
    int lane = tid & 31;
    if (n >= NN) return;
    float ss[HEADS] = {0,0,0,0}, sd[HEADS] = {0,0,0,0};
    for (int c = lane; c < C1; c += 32) {
        float v = g_g1[(size_t)n * C1 + c];
#pragma unroll
        for (int h = 0; h < HEADS; h++) {
            ss[h] += v * sws[h * C1 + c];
            sd[h] += v * swd[h * C1 + c];
        }
    }
#pragma unroll
    for (int h = 0; h < HEADS; h++)
#pragma unroll
        for (int o = 16; o; o >>= 1) {
            ss[h] += __shfl_xor_sync(0xffffffffu, ss[h], o);
            sd[h] += __shfl_xor_sync(0xffffffffu, sd[h], o);
        }
    if (lane == 0) {
#pragma unroll
        for (int h = 0; h < HEADS; h++) {
            g_asrc[n * HEADS + h] = ss[h];
            g_adst[n * HEADS + h] = sd[h];
        }
    }
}

// softmax per dst node: one warp per node; writes normalized alpha + aself
__global__ void k_gat_softmax() {
    int n = (blockIdx.x * blockDim.x + threadIdx.x) >> 5;
    int lane = threadIdx.x & 31;
    if (n >= NN) return;
    int start = g_rowptr[n], end = g_rowptr[n + 1];

    float adst[HEADS], selfe[HEADS];
#pragma unroll
    for (int h = 0; h < HEADS; h++) {
        adst[h]  = g_adst[n * HEADS + h];
        selfe[h] = lrelu(g_asrc[n * HEADS + h] + adst[h]);
    }

    float mx[HEADS];
#pragma unroll
    for (int h = 0; h < HEADS; h++) mx[h] = selfe[h];
    for (int i = start + lane; i < end; i += 32) {
        int s = g_col[i];
#pragma unroll
        for (int h = 0; h < HEADS; h++)
            mx[h] = fmaxf(mx[h], lrelu(g_asrc[s * HEADS + h] + adst[h]));
    }
#pragma unroll
    for (int h = 0; h < HEADS; h++)
#pragma unroll
        for (int o = 16; o; o >>= 1)
            mx[h] = fmaxf(mx[h], __shfl_xor_sync(0xffffffffu, mx[h], o));

    float zz[HEADS];
#pragma unroll
    for (int h = 0; h < HEADS; h++) zz[h] = (lane == 0) ? __expf(selfe[h] - mx[h]) : 0.f;
    for (int i = start + lane; i < end; i += 32) {
        int s = g_col[i];
        float4 ev;
        ev.x = __expf(lrelu(g_asrc[s * HEADS + 0] + adst[0]) - mx[0]);
        ev.y = __expf(lrelu(g_asrc[s * HEADS + 1] + adst[1]) - mx[1]);
        ev.z = __expf(lrelu(g_asrc[s * HEADS + 2] + adst[2]) - mx[2]);
        ev.w = __expf(lrelu(g_asrc[s * HEADS + 3] + adst[3]) - mx[3]);
        *(float4*)&g_alpha[(size_t)i * HEADS] = ev;
        zz[0] += ev.x; zz[1] += ev.y; zz[2] += ev.z; zz[3] += ev.w;
    }
#pragma unroll
    for (int h = 0; h < HEADS; h++)
#pragma unroll
        for (int o = 16; o; o >>= 1)
            zz[h] += __shfl_xor_sync(0xffffffffu, zz[h], o);

    float rz[HEADS];
#pragma unroll
    for (int h = 0; h < HEADS; h++) rz[h] = 1.0f / zz[h];

    for (int i = start + lane; i < end; i += 32) {
        float4 a = *(float4*)&g_alpha[(size_t)i * HEADS];
        a.x *= rz[0]; a.y *= rz[1]; a.z *= rz[2]; a.w *= rz[3];
        *(float4*)&g_alpha[(size_t)i * HEADS] = a;
    }
    if (lane == 0) {
#pragma unroll
        for (int h = 0; h < HEADS; h++)
            g_aself[n * HEADS + h] = __expf(selfe[h] - mx[h]) * rz[h];
    }
}

// pre-projection aggregation: p[n,h,c] = aself_h*g1[n,c] + sum alpha_h*g1[src,c]
#define GCHUNK 64
__global__ void __launch_bounds__(128) k_gat_agg2() {
    int n = blockIdx.x;
    int tid = threadIdx.x;     // channel c = tid
    int start = g_rowptr[n], end = g_rowptr[n + 1];

    __shared__ int    s_src[GCHUNK];
    __shared__ float4 s_al [GCHUNK];

    float g1v = g_g1[(size_t)n * C1 + tid];
    float4 as = *(const float4*)&g_aself[n * HEADS];
    float a0 = g1v * as.x, a1 = g1v * as.y, a2 = g1v * as.z, a3 = g1v * as.w;

    for (int base = start; base < end; base += GCHUNK) {
        int cnt = min(GCHUNK, end - base);
        if (tid < cnt) {
            s_src[tid] = g_col[base + tid];
            s_al[tid]  = *(const float4*)&g_alpha[(size_t)(base + tid) * HEADS];
        }
        __syncthreads();
        for (int j = 0; j < cnt; j++) {
            float v = g_g1[(size_t)s_src[j] * C1 + tid];
            float4 al = s_al[j];
            a0 += al.x * v; a1 += al.y * v; a2 += al.z * v; a3 += al.w * v;
        }
        __syncthreads();
    }

    float* p = &g_h2[(size_t)n * C2];
    p[0 * C1 + tid] = a0;
    p[1 * C1 + tid] = a1;
    p[2 * C1 + tid] = a2;
    p[3 * C1 + tid] = a3;
}

// ---------------- LayerNorm --------------------------------------------------
__global__ void k_ln(int Xid, int Yid, const float* __restrict__ gw,
                     const float* __restrict__ bw, int C, int ldY, int doRelu)
{
    int n = blockIdx.x;
    const float* x = buf(Xid) + (size_t)n * C;
    float* y = buf(Yid) + (size_t)n * ldY;
    int tid = threadIdx.x, lane = tid & 31, warp = tid >> 5;

    float s = 0.f, s2 = 0.f;
    for (int c = tid; c < C; c += 128) {
        float v = x[c];
        s += v; s2 += v * v;
    }
#pragma unroll
    for (int o = 16; o; o >>= 1) {
        s  += __shfl_xor_sync(0xffffffffu, s, o);
        s2 += __shfl_xor_sync(0xffffffffu, s2, o);
    }
    __shared__ float shs[4], shs2[4], smu, sinv;
    if (lane == 0) { shs[warp] = s; shs2[warp] = s2; }
    __syncthreads();
    if (tid == 0) {
        float S = shs[0] + shs[1] + shs[2] + shs[3];
        float S2 = shs2[0] + shs2[1] + shs2[2] + shs2[3];
        float mu = S / C;
        float var = S2 / C - mu * mu;
        smu = mu;
        sinv = rsqrtf(var + 1e-5f);
    }
    __syncthreads();
    float mu = smu, inv = sinv;
    for (int c = tid; c < C; c += 128) {
        float v = (x[c] - mu) * inv * gw[c] + bw[c];
        if (doRelu) v = fmaxf(v, 0.f);
        y[c] = v;
    }
}

__global__ void k_catx(const float* __restrict__ x) {
    int idx = blockIdx.x * blockDim.x + threadIdx.x;
    if (idx >= NN * C1) return;
    int n = idx / C1, c = idx - n * C1;
    g_cat[(size_t)n * CCAT + C3 + c] = x[idx];
}

__global__ void k_out(const float* __restrict__ w2, const float* __restrict__ b2,
                      float* __restrict__ out)
{
    int gw = (blockIdx.x * blockDim.x + threadIdx.x) >> 5;
    int lane = threadIdx.x & 31;
    if (gw >= NN) return;
    const float* hp = &g_mh[(size_t)gw * CM];
    float a0 = 0.f, a1 = 0.f;
#pragma unroll
    for (int c = lane; c < CM; c += 32) {
        float v = hp[c];
        a0 += v * w2[c * 2];
        a1 += v * w2[c * 2 + 1];
    }
#pragma unroll
    for (int o = 16; o; o >>= 1) {
        a0 += __shfl_xor_sync(0xffffffffu, a0, o);
        a1 += __shfl_xor_sync(0xffffffffu, a1, o);
    }
    if (lane == 0) {
        out[gw * 2 + 0] = a0 + b2[0];
        out[gw * 2 + 1] = a1 + b2[1];
    }
}

// ---------------- launch -----------------------------------------------------
static inline int cdiv(int a, int b) { return (a + b - 1) / b; }

extern "C" void kernel_launch(void* const* d_in, const int* in_sizes, int n_in,
                              void* d_out, int out_size)
{
    (void)in_sizes; (void)n_in; (void)out_size;
    const float* x      = (const float*)d_in[0];
    const int*   ei     = (const int*)d_in[1];
    const float* gcn1_w = (const float*)d_in[2];
    const float* gcn1_b = (const float*)d_in[3];
    const float* gat_w  = (const float*)d_in[4];
    const float* att_s  = (const float*)d_in[5];
    const float* att_d  = (const float*)d_in[6];
    const float* gat_b  = (const float*)d_in[7];
    const float* n1_g   = (const float*)d_in[8];
    const float* n1_b   = (const float*)d_in[9];
    const float* gcn2_w = (const float*)d_in[10];
    const float* gcn2_b = (const float*)d_in[11];
    const float* n2_g   = (const float*)d_in[12];
    const float* n2_b   = (const float*)d_in[13];
    const float* mlp_w1 = (const float*)d_in[14];
    const float* mlp_b1 = (const float*)d_in[15];
    const float* mlp_w2 = (const float*)d_in[16];
    const float* mlp_b2 = (const float*)d_in[17];
    float* out = (float*)d_out;

    const int T = 256;
    int mblk = cdiv(NN, 128);

    cudaFuncSetAttribute(k_sgemm, cudaFuncAttributeMaxDynamicSharedMemorySize, SGEMM_SMEM);

    // CSR build
    k_zero <<<cdiv(NN, T), T>>>();
    k_count<<<cdiv(EE, T), T>>>(ei);
    k_scan <<<1, 1024>>>();
    k_fill <<<cdiv(EE, T), T>>>(ei);

    // GCN1
    k_sgemm<<<dim3(1, mblk), T, SGEMM_SMEM>>>(x, -1, gcn1_w, nullptr, ID_H1, NN, C1, C1, C1, 0, 0);
    k_gcn_gather<<<NN / 4, 128>>>(ID_H1, ID_G1, gcn1_b, C1, 1);

    // GAT: logits from g1; aggregate g1; then per-head projection GEMM
    k_wtil<<<cdiv(HEADS * C1, T), T>>>(gat_w, att_s, att_d);
    k_att2<<<cdiv(NN * 32, T), T>>>();
    k_gat_softmax<<<cdiv(NN * 32, T), T>>>();
    k_gat_agg2<<<NN, 128>>>();
    k_sgemm<<<dim3(C2 / 128, mblk), T, SGEMM_SMEM>>>(nullptr, ID_H2, gat_w, gat_b, ID_GAT, NN, C2, C1, C2, 1, 0);

    // LN1
    k_ln<<<NN, 128>>>(ID_GAT, ID_GAT, n1_g, n1_b, C2, C2, 0);

    // GCN2
    k_sgemm<<<dim3(C3 / 128, mblk), T, SGEMM_SMEM>>>(nullptr, ID_GAT, gcn2_w, nullptr, ID_H3, NN, C3, C2, C2, 0, 0);
    k_gcn_gather<<<NN / 2, 128>>>(ID_H3, ID_G2, gcn2_b, C3, 0);

    // LN2 + concat
    k_ln<<<NN, 128>>>(ID_G2, ID_CAT, n2_g, n2_b, C3, CCAT, 1);
    k_catx<<<cdiv(NN * C1, T), T>>>(x);

    // MLP
    k_sgemm<<<dim3(CM / 128, mblk), T, SGEMM_SMEM>>>(nullptr, ID_CAT, mlp_w1, mlp_b1, ID_MH, NN, CM, CCAT, CCAT, 0, 1);
    k_out<<<cdiv(NN * 32, T), T>>>(mlp_w2, mlp_b2, out);
}

// round 12
// speedup vs baseline: 4.3150x; 1.0369x over previous
#include <cuda_runtime.h>
#include <cstdint>

#define NN   50000
#define EE   800000
#define C1   128
#define C2   512
#define C3   256
#define CCAT 384
#define CM   128
#define HEADS 4

// weight scratch offsets (floats)
#define WOFF_G1  0
#define WOFF_GAT 16384
#define WOFF_G2  81920
#define WOFF_MLP 212992
#define WTOTAL   262144

// ---------------- scratch (static device globals; no allocation) -------------
__device__ float    g_dinv[NN];
__device__ int      g_cnt[NN];
__device__ int      g_cursor[NN];
__device__ int      g_rowptr[NN + 1];
__device__ int      g_col[EE];
__device__ int      g_bsum[64];
__device__ float    g_h1 [NN*C1];
__device__ float    g_g1 [NN*C1];
__device__ float    g_h2 [NN*C2];      // p[n][h][128] (tf32-rounded)
__device__ float    g_gat[NN*C2];
__device__ float    g_h3 [NN*C3];
__device__ float    g_g2 [NN*C3];
__device__ float    g_cat[NN*CCAT];
__device__ float    g_mh [NN*CM];      // rounded-x early; MLP hidden late
__device__ float    g_asrc[NN*HEADS];
__device__ float    g_adst[NN*HEADS];
__device__ float    g_aself[NN*HEADS];
__device__ float    g_alpha[(size_t)EE*HEADS];
__device__ float    g_wtilS[HEADS*C1];
__device__ float    g_wtilD[HEADS*C1];
__device__ float    g_wbuf[WTOTAL];    // tf32-rounded weights

#define ID_H1  0
#define ID_G1  1
#define ID_H2  2
#define ID_GAT 3
#define ID_H3  4
#define ID_G2  5
#define ID_CAT 6
#define ID_MH  7

__device__ __forceinline__ float* buf(int id) {
    switch (id) {
        case ID_H1:  return g_h1;
        case ID_G1:  return g_g1;
        case ID_H2:  return g_h2;
        case ID_GAT: return g_gat;
        case ID_H3:  return g_h3;
        case ID_G2:  return g_g2;
        case ID_CAT: return g_cat;
        default:     return g_mh;
    }
}

__device__ __forceinline__ float lrelu(float x) { return x >= 0.f ? x : 0.2f * x; }

__device__ __forceinline__ uint32_t tf32r(float f) {
    uint32_t u;
    asm("cvt.rna.tf32.f32 %0, %1;" : "=r"(u) : "f"(f));
    return u;
}
__device__ __forceinline__ float tf32f(float f) { return __uint_as_float(tf32r(f)); }

__device__ __forceinline__ void cpasync16(uint32_t dst, const void* src, int sz) {
    asm volatile("cp.async.cg.shared.global [%0], [%1], 16, %2;\n"
                 :: "r"(dst), "l"(src), "r"(sz));
}

// ---------------- weight / x pre-rounding ------------------------------------
__global__ void k_roundw(const float* __restrict__ w1, const float* __restrict__ wg,
                         const float* __restrict__ w2, const float* __restrict__ wm)
{
    int i = blockIdx.x * blockDim.x + threadIdx.x;
    if (i >= WTOTAL) return;
    float v;
    if (i < WOFF_GAT)      v = w1[i - WOFF_G1];
    else if (i < WOFF_G2)  v = wg[i - WOFF_GAT];
    else if (i < WOFF_MLP) v = w2[i - WOFF_G2];
    else                   v = wm[i - WOFF_MLP];
    g_wbuf[i] = tf32f(v);
}
__global__ void k_roundx(const float* __restrict__ x) {
    int i = blockIdx.x * blockDim.x + threadIdx.x;
    if (i < NN * C1) g_mh[i] = tf32f(x[i]);
}

// ---------------- CSR build --------------------------------------------------
__global__ void k_zero() {
    int i = blockIdx.x * blockDim.x + threadIdx.x;
    if (i < NN) { g_cnt[i] = 0; g_cursor[i] = 0; }
}
__global__ void k_count(const int* __restrict__ ei) {
    int e = blockIdx.x * blockDim.x + threadIdx.x;
    if (e < EE) atomicAdd(&g_cnt[ei[EE + e]], 1);
}
// parallel scan: per-block sums -> serial scan of 49 -> per-block scan+offset
__global__ void __launch_bounds__(1024) k_scan1() {
    __shared__ int s_w[32];
    int tid = threadIdx.x, lane = tid & 31, wid = tid >> 5;
    int i = blockIdx.x * 1024 + tid;
    int v = (i < NN) ? g_cnt[i] : 0;
    if (i < NN) g_dinv[i] = rsqrtf((float)(v + 1));
    int x = v;
#pragma unroll
    for (int o = 16; o; o >>= 1) x += __shfl_xor_sync(0xffffffffu, x, o);
    if (lane == 0) s_w[wid] = x;
    __syncthreads();
    if (tid == 0) {
        int t = 0;
        for (int j = 0; j < 32; j++) t += s_w[j];
        g_bsum[blockIdx.x] = t;
    }
}
__global__ void k_scan2(int nblk) {
    if (threadIdx.x == 0) {
        int acc = 0;
        for (int j = 0; j < nblk; j++) { int t = g_bsum[j]; g_bsum[j] = acc; acc += t; }
        g_rowptr[NN] = acc;
    }
}
__global__ void __launch_bounds__(1024) k_scan3() {
    __shared__ int s_w[32];
    int tid = threadIdx.x, lane = tid & 31, wid = tid >> 5;
    int i = blockIdx.x * 1024 + tid;
    int v = (i < NN) ? g_cnt[i] : 0;
    int x = v;
#pragma unroll
    for (int o = 1; o < 32; o <<= 1) {
        int t = __shfl_up_sync(0xffffffffu, x, o);
        if (lane >= o) x += t;
    }
    if (lane == 31) s_w[wid] = x;
    __syncthreads();
    if (wid == 0) {
        int y = s_w[lane];
#pragma unroll
        for (int o = 1; o < 32; o <<= 1) {
            int t = __shfl_up_sync(0xffffffffu, y, o);
            if (lane >= o) y += t;
        }
        s_w[lane] = y;
    }
    __syncthreads();
    int woff = (wid > 0) ? s_w[wid - 1] : 0;
    if (i < NN) g_rowptr[i] = g_bsum[blockIdx.x] + woff + x - v;
}
__global__ void k_fill(const int* __restrict__ ei) {
    int e = blockIdx.x * blockDim.x + threadIdx.x;
    if (e >= EE) return;
    int d = ei[EE + e];
    int pos = atomicAdd(&g_cursor[d], 1);
    g_col[g_rowptr[d] + pos] = ei[e];
}

// ---------------- TF32 tensor-core GEMM, 3-stage cp.async, NO mainloop cvt ---
// all A/B inputs are pre-rounded to tf32 (bit-identical to in-loop cvt)
#define STAGES 3
#define AST 20
#define BST 132
#define SGEMM_SMEM ((STAGES * 128 * AST + STAGES * 16 * BST) * 4)

__global__ void __launch_bounds__(256) k_sgemm(
    const float* __restrict__ Aext, int Aid,
    const float* __restrict__ B, const float* __restrict__ bias,
    int Cid, int M, int Nc, int K, int lda, int hmode, int doRelu)
{
    extern __shared__ float dsm[];
    float (*Asm)[128][AST] = (float (*)[128][AST])dsm;
    float (*Bsm)[16][BST]  = (float (*)[16][BST])(dsm + STAGES * 128 * AST);

    const float* A = Aext ? Aext : buf(Aid);
    float* C = buf(Cid);

    int tid  = threadIdx.x;
    int lane = tid & 31;
    int w    = tid >> 5;
    int wm   = w >> 2;
    int wn   = w & 3;
    int m0   = wm * 64;
    int n0   = wn * 32;
    int brow = blockIdx.y * 128;
    int bcol = blockIdx.x * 128;
    if (hmode) A += bcol;

    int r  = lane >> 2;
    int cA = lane & 3;

    float acc[4][4][4];
#pragma unroll
    for (int i = 0; i < 4; i++)
#pragma unroll
        for (int j = 0; j < 4; j++)
#pragma unroll
            for (int q = 0; q < 4; q++) acc[i][j][q] = 0.f;

    int amr[2], amk[2], aok[2];
    int bkr[2], bnn[2];
#pragma unroll
    for (int i = 0; i < 2; i++) {
        int chunk = tid + i * 256;
        amr[i] = chunk >> 2;
        amk[i] = (chunk & 3) * 4;
        aok[i] = (brow + amr[i] < M) ? 16 : 0;
        bkr[i] = chunk >> 5;
        bnn[i] = (chunk & 31) * 4;
    }

    int ktiles = K >> 4;

#pragma unroll
    for (int s = 0; s < STAGES - 1; s++) {
        int kt = s << 4;
#pragma unroll
        for (int i = 0; i < 2; i++) {
            uint32_t ad = (uint32_t)__cvta_generic_to_shared(&Asm[s][amr[i]][amk[i]]);
            cpasync16(ad, &A[(size_t)(brow + amr[i]) * lda + kt + amk[i]], aok[i]);
        }
#pragma unroll
        for (int i = 0; i < 2; i++) {
            uint32_t bd = (uint32_t)__cvta_generic_to_shared(&Bsm[s][bkr[i]][bnn[i]]);
            cpasync16(bd, &B[(size_t)(kt + bkr[i]) * Nc + bcol + bnn[i]], 16);
        }
        asm volatile("cp.async.commit_group;\n" ::);
    }

    for (int t = 0; t < ktiles; t++) {
        asm volatile("cp.async.wait_group %0;\n" :: "n"(STAGES - 2));
        __syncthreads();

        int tn = t + STAGES - 1;
        if (tn < ktiles) {
            int s = tn % STAGES;
            int kt = tn << 4;
#pragma unroll
            for (int i = 0; i < 2; i++) {
                uint32_t ad = (uint32_t)__cvta_generic_to_shared(&Asm[s][amr[i]][amk[i]]);
                cpasync16(ad, &A[(size_t)(brow + amr[i]) * lda + kt + amk[i]], aok[i]);
            }
#pragma unroll
            for (int i = 0; i < 2; i++) {
                uint32_t bd = (uint32_t)__cvta_generic_to_shared(&Bsm[s][bkr[i]][bnn[i]]);
                cpasync16(bd, &B[(size_t)(kt + bkr[i]) * Nc + bcol + bnn[i]], 16);
            }
        }
        asm volatile("cp.async.commit_group;\n" ::);

        const float (*As)[AST] = Asm[t % STAGES];
        const float (*Bs)[BST] = Bsm[t % STAGES];

#pragma unroll
        for (int ks = 0; ks < 16; ks += 8) {
            uint32_t af[4][4];
#pragma unroll
            for (int mi = 0; mi < 4; mi++) {
                int mrow = m0 + mi * 16 + r;
                af[mi][0] = __float_as_uint(As[mrow][ks + cA]);
                af[mi][1] = __float_as_uint(As[mrow + 8][ks + cA]);
                af[mi][2] = __float_as_uint(As[mrow][ks + cA + 4]);
                af[mi][3] = __float_as_uint(As[mrow + 8][ks + cA + 4]);
            }
            uint32_t bf[4][2];
#pragma unroll
            for (int ni = 0; ni < 4; ni++) {
                int ncol = n0 + ni * 8 + r;
                bf[ni][0] = __float_as_uint(Bs[ks + cA][ncol]);
                bf[ni][1] = __float_as_uint(Bs[ks + cA + 4][ncol]);
            }
#pragma unroll
            for (int mi = 0; mi < 4; mi++)
#pragma unroll
                for (int ni = 0; ni < 4; ni++) {
                    asm volatile(
                        "mma.sync.aligned.m16n8k8.row.col.f32.tf32.tf32.f32 "
                        "{%0,%1,%2,%3}, {%4,%5,%6,%7}, {%8,%9}, {%0,%1,%2,%3};"
                        : "+f"(acc[mi][ni][0]), "+f"(acc[mi][ni][1]),
                          "+f"(acc[mi][ni][2]), "+f"(acc[mi][ni][3])
                        : "r"(af[mi][0]), "r"(af[mi][1]), "r"(af[mi][2]), "r"(af[mi][3]),
                          "r"(bf[ni][0]), "r"(bf[ni][1]));
                }
        }
        __syncthreads();
    }

#pragma unroll
    for (int mi = 0; mi < 4; mi++) {
        int row0 = brow + m0 + mi * 16 + (lane >> 2);
#pragma unroll
        for (int ni = 0; ni < 4; ni++) {
            int col = bcol + n0 + ni * 8 + 2 * (lane & 3);
            float bx = bias ? bias[col]     : 0.f;
            float by = bias ? bias[col + 1] : 0.f;
            float v0 = acc[mi][ni][0] + bx;
            float v1 = acc[mi][ni][1] + by;
            float v2 = acc[mi][ni][2] + bx;
            float v3 = acc[mi][ni][3] + by;
            if (doRelu) {
                v0 = fmaxf(v0, 0.f); v1 = fmaxf(v1, 0.f);
                v2 = fmaxf(v2, 0.f); v3 = fmaxf(v3, 0.f);
            }
            if (row0 < M) {
                C[(size_t)row0 * Nc + col]     = v0;
                C[(size_t)row0 * Nc + col + 1] = v1;
            }
            if (row0 + 8 < M) {
                C[(size_t)(row0 + 8) * Nc + col]     = v2;
                C[(size_t)(row0 + 8) * Nc + col + 1] = v3;
            }
        }
    }
}

// ---------------- GCN gather (CSR) ------------------------------------------
__global__ void __launch_bounds__(128) k_gcn_gather(
    int Hid, int Oid, const float* __restrict__ bias, int C, int doRelu)
{
    int tpn = C >> 2;
    int npb = 128 / tpn;
    int local = threadIdx.x / tpn;
    int lane  = threadIdx.x - local * tpn;
    int n = blockIdx.x * npb + local;
    if (n >= NN) return;
    int c = lane * 4;
    const float* H = buf(Hid);
    float* O = buf(Oid);

    float4 hv = *(const float4*)&H[(size_t)n * C + c];
    float dn = g_dinv[n];
    float4 acc;
    acc.x = hv.x * dn; acc.y = hv.y * dn; acc.z = hv.z * dn; acc.w = hv.w * dn;

    int start = g_rowptr[n], end = g_rowptr[n + 1];
    for (int i = start; i < end; i++) {
        int s = g_col[i];
        float wgt = g_dinv[s];
        float4 v = *(const float4*)&H[(size_t)s * C + c];
        acc.x += v.x * wgt; acc.y += v.y * wgt; acc.z += v.z * wgt; acc.w += v.w * wgt;
    }
    float4 o;
    o.x = acc.x * dn + bias[c + 0];
    o.y = acc.y * dn + bias[c + 1];
    o.z = acc.z * dn + bias[c + 2];
    o.w = acc.w * dn + bias[c + 3];
    if (doRelu) {
        o.x = fmaxf(o.x, 0.f); o.y = fmaxf(o.y, 0.f);
        o.z = fmaxf(o.z, 0.f); o.w = fmaxf(o.w, 0.f);
    }
    *(float4*)&O[(size_t)n * C + c] = o;
}

// ---------------- GAT --------------------------------------------------------
__global__ void k_wtil(const float* __restrict__ gat_w,
                       const float* __restrict__ attS, const float* __restrict__ attD)
{
    int t = blockIdx.x * blockDim.x + threadIdx.x;
    if (t >= HEADS * C1) return;
    int h = t >> 7;
    int c = t & 127;
    const float* wr = &gat_w[(size_t)c * C2 + h * 128];
    const float* as = &attS[h * 128];
    const float* ad = &attD[h * 128];
    float ss = 0.f, sd = 0.f;
#pragma unroll 4
    for (int k = 0; k < 128; k++) {
        float wv = wr[k];
        ss += wv * as[k];
        sd += wv * ad[k];
    }
    g_wtilS[t] = ss;
    g_wtilD[t] = sd;
}

__global__ void __launch_bounds__(256) k_att2() {
    __shared__ float sws[HEADS * C1], swd[HEADS * C1];
    int tid = threadIdx.x;
    for (int i = tid; i < HEADS * C1; i += 256) { sws[i] = g_wtilS[i]; swd[i] = g_wtilD[i]; }
    __syncthreads();
    int n = (blockIdx.x * 256 + tid) >> 5;
    int lane = tid & 31;
    if (n >= NN) return;
    float ss[HEADS] = {0,0,0,0}, sd[HEADS] = {0,0,0,0};
    for (int c = lane; c < C1; c += 32) {
        float v = g_g1[(size_t)n * C1 + c];
#pragma unroll
        for (int h = 0; h < HEADS; h++) {
            ss[h] += v * sws[h * C1 + c];
            sd[h] += v * swd[h * C1 + c];
        }
    }
#pragma unroll
    for (int h = 0; h < HEADS; h++)
#pragma unroll
        for (int o = 16; o; o >>= 1) {
            ss[h] += __shfl_xor_sync(0xffffffffu, ss[h], o);
            sd[h] += __shfl_xor_sync(0xffffffffu, sd[h], o);
        }
    if (lane == 0) {
#pragma unroll
        for (int h = 0; h < HEADS; h++) {
            g_asrc[n * HEADS + h] = ss[h];
            g_adst[n * HEADS + h] = sd[h];
        }
    }
}

__global__ void k_gat_softmax() {
    int n = (blockIdx.x * blockDim.x + threadIdx.x) >> 5;
    int lane = threadIdx.x & 31;
    if (n >= NN) return;
    int start = g_rowptr[n], end = g_rowptr[n + 1];

    float adst[HEADS], selfe[HEADS];
#pragma unroll
    for (int h = 0; h < HEADS; h++) {
        adst[h]  = g_adst[n * HEADS + h];
        selfe[h] = lrelu(g_asrc[n * HEADS + h] + adst[h]);
    }

    float mx[HEADS];
#pragma unroll
    for (int h = 0; h < HEADS; h++) mx[h] = selfe[h];
    for (int i = start + lane; i < end; i += 32) {
        int s = g_col[i];
#pragma unroll
        for (int h = 0; h < HEADS; h++)
            mx[h] = fmaxf(mx[h], lrelu(g_asrc[s * HEADS + h] + adst[h]));
    }
#pragma unroll
    for (int h = 0; h < HEADS; h++)
#pragma unroll
        for (int o = 16; o; o >>= 1)
            mx[h] = fmaxf(mx[h], __shfl_xor_sync(0xffffffffu, mx[h], o));

    float zz[HEADS];
#pragma unroll
    for (int h = 0; h < HEADS; h++) zz[h] = (lane == 0) ? __expf(selfe[h] - mx[h]) : 0.f;
    for (int i = start + lane; i < end; i += 32) {
        int s = g_col[i];
        float4 ev;
        ev.x = __expf(lrelu(g_asrc[s * HEADS + 0] + adst[0]) - mx[0]);
        ev.y = __expf(lrelu(g_asrc[s * HEADS + 1] + adst[1]) - mx[1]);
        ev.z = __expf(lrelu(g_asrc[s * HEADS + 2] + adst[2]) - mx[2]);
        ev.w = __expf(lrelu(g_asrc[s * HEADS + 3] + adst[3]) - mx[3]);
        *(float4*)&g_alpha[(size_t)i * HEADS] = ev;
        zz[0] += ev.x; zz[1] += ev.y; zz[2] += ev.z; zz[3] += ev.w;
    }
#pragma unroll
    for (int h = 0; h < HEADS; h++)
#pragma unroll
        for (int o = 16; o; o >>= 1)
            zz[h] += __shfl_xor_sync(0xffffffffu, zz[h], o);

    float rz[HEADS];
#pragma unroll
    for (int h = 0; h < HEADS; h++) rz[h] = 1.0f / zz[h];

    for (int i = start + lane; i < end; i += 32) {
        float4 a = *(float4*)&g_alpha[(size_t)i * HEADS];
        a.x *= rz[0]; a.y *= rz[1]; a.z *= rz[2]; a.w *= rz[3];
        *(float4*)&g_alpha[(size_t)i * HEADS] = a;
    }
    if (lane == 0) {
#pragma unroll
        for (int h = 0; h < HEADS; h++)
            g_aself[n * HEADS + h] = __expf(selfe[h] - mx[h]) * rz[h];
    }
}

// pre-projection aggregation; p written tf32-rounded (sole consumer = GAT GEMM)
#define GCHUNK 64
__global__ void __launch_bounds__(128) k_gat_agg2() {
    int n = blockIdx.x;
    int tid = threadIdx.x;
    int start = g_rowptr[n], end = g_rowptr[n + 1];

    __shared__ int    s_src[GCHUNK];
    __shared__ float4 s_al [GCHUNK];

    float g1v = g_g1[(size_t)n * C1 + tid];
    float4 as = *(const float4*)&g_aself[n * HEADS];
    float a0 = g1v * as.x, a1 = g1v * as.y, a2 = g1v * as.z, a3 = g1v * as.w;

    for (int base = start; base < end; base += GCHUNK) {
        int cnt = min(GCHUNK, end - base);
        if (tid < cnt) {
            s_src[tid] = g_col[base + tid];
            s_al[tid]  = *(const float4*)&g_alpha[(size_t)(base + tid) * HEADS];
        }
        __syncthreads();
        for (int j = 0; j < cnt; j++) {
            float v = g_g1[(size_t)s_src[j] * C1 + tid];
            float4 al = s_al[j];
            a0 += al.x * v; a1 += al.y * v; a2 += al.z * v; a3 += al.w * v;
        }
        __syncthreads();
    }

    float* p = &g_h2[(size_t)n * C2];
    p[0 * C1 + tid] = tf32f(a0);
    p[1 * C1 + tid] = tf32f(a1);
    p[2 * C1 + tid] = tf32f(a2);
    p[3 * C1 + tid] = tf32f(a3);
}

// ---------------- LayerNorm (rounded output; optional x append) --------------
__global__ void k_ln(int Xid, int Yid, const float* __restrict__ gw,
                     const float* __restrict__ bw, int C, int ldY, int doRelu,
                     const float* __restrict__ xapp)
{
    int n = blockIdx.x;
    const float* x = buf(Xid) + (size_t)n * C;
    float* y = buf(Yid) + (size_t)n * ldY;
    int tid = threadIdx.x, lane = tid & 31, warp = tid >> 5;

    float s = 0.f, s2 = 0.f;
    for (int c = tid; c < C; c += 128) {
        float v = x[c];
        s += v; s2 += v * v;
    }
#pragma unroll
    for (int o = 16; o; o >>= 1) {
        s  += __shfl_xor_sync(0xffffffffu, s, o);
        s2 += __shfl_xor_sync(0xffffffffu, s2, o);
    }
    __shared__ float shs[4], shs2[4], smu, sinv;
    if (lane == 0) { shs[warp] = s; shs2[warp] = s2; }
    __syncthreads();
    if (tid == 0) {
        float S = shs[0] + shs[1] + shs[2] + shs[3];
        float S2 = shs2[0] + shs2[1] + shs2[2] + shs2[3];
        float mu = S / C;
        float var = S2 / C - mu * mu;
        smu = mu;
        sinv = rsqrtf(var + 1e-5f);
    }
    __syncthreads();
    float mu = smu, inv = sinv;
    for (int c = tid; c < C; c += 128) {
        float v = (x[c] - mu) * inv * gw[c] + bw[c];
        if (doRelu) v = fmaxf(v, 0.f);
        y[c] = tf32f(v);
    }
    if (xapp) {
        for (int c = tid; c < C1; c += 128)
            y[C + c] = tf32f(xapp[(size_t)n * C1 + c]);
    }
}

__global__ void k_out(const float* __restrict__ w2, const float* __restrict__ b2,
                      float* __restrict__ out)
{
    int gw = (blockIdx.x * blockDim.x + threadIdx.x) >> 5;
    int lane = threadIdx.x & 31;
    if (gw >= NN) return;
    const float* hp = &g_mh[(size_t)gw * CM];
    float a0 = 0.f, a1 = 0.f;
#pragma unroll
    for (int c = lane; c < CM; c += 32) {
        float v = hp[c];
        a0 += v * w2[c * 2];
        a1 += v * w2[c * 2 + 1];
    }
#pragma unroll
    for (int o = 16; o; o >>= 1) {
        a0 += __shfl_xor_sync(0xffffffffu, a0, o);
        a1 += __shfl_xor_sync(0xffffffffu, a1, o);
    }
    if (lane == 0) {
        out[gw * 2 + 0] = a0 + b2[0];
        out[gw * 2 + 1] = a1 + b2[1];
    }
}

// ---------------- launch -----------------------------------------------------
static inline int cdiv(int a, int b) { return (a + b - 1) / b; }

extern "C" void kernel_launch(void* const* d_in, const int* in_sizes, int n_in,
                              void* d_out, int out_size)
{
    (void)in_sizes; (void)n_in; (void)out_size;
    const float* x      = (const float*)d_in[0];
    const int*   ei     = (const int*)d_in[1];
    const float* gcn1_w = (const float*)d_in[2];
    const float* gcn1_b = (const float*)d_in[3];
    const float* gat_w  = (const float*)d_in[4];
    const float* att_s  = (const float*)d_in[5];
    const float* att_d  = (const float*)d_in[6];
    const float* gat_b  = (const float*)d_in[7];
    const float* n1_g   = (const float*)d_in[8];
    const float* n1_b   = (const float*)d_in[9];
    const float* gcn2_w = (const float*)d_in[10];
    const float* gcn2_b = (const float*)d_in[11];
    const float* n2_g   = (const float*)d_in[12];
    const float* n2_b   = (const float*)d_in[13];
    const float* mlp_w1 = (const float*)d_in[14];
    const float* mlp_b1 = (const float*)d_in[15];
    const float* mlp_w2 = (const float*)d_in[16];
    const float* mlp_b2 = (const float*)d_in[17];
    float* out = (float*)d_out;

    const int T = 256;
    int mblk = cdiv(NN, 128);
    int sblk = cdiv(NN, 1024);   // 49

    cudaFuncSetAttribute(k_sgemm, cudaFuncAttributeMaxDynamicSharedMemorySize, SGEMM_SMEM);

    float* wb = nullptr;
    cudaGetSymbolAddress((void**)&wb, g_wbuf);

    // pre-round weights and x (bit-identical to in-GEMM cvt)
    k_roundw<<<cdiv(WTOTAL, T), T>>>(gcn1_w, gat_w, gcn2_w, mlp_w1);
    k_roundx<<<cdiv(NN * C1, T), T>>>(x);

    // CSR build
    k_zero <<<cdiv(NN, T), T>>>();
    k_count<<<cdiv(EE, T), T>>>(ei);
    k_scan1<<<sblk, 1024>>>();
    k_scan2<<<1, 32>>>(sblk);
    k_scan3<<<sblk, 1024>>>();
    k_fill <<<cdiv(EE, T), T>>>(ei);

    // GCN1 (A = rounded x in g_mh)
    k_sgemm<<<dim3(1, mblk), T, SGEMM_SMEM>>>(nullptr, ID_MH, wb + WOFF_G1, nullptr, ID_H1, NN, C1, C1, C1, 0, 0);
    k_gcn_gather<<<NN / 4, 128>>>(ID_H1, ID_G1, gcn1_b, C1, 1);

    // GAT: logits from g1; softmax; pre-projection aggregate; per-head GEMM
    k_wtil<<<cdiv(HEADS * C1, T), T>>>(gat_w, att_s, att_d);
    k_att2<<<cdiv(NN * 32, T), T>>>();
    k_gat_softmax<<<cdiv(NN * 32, T), T>>>();
    k_gat_agg2<<<NN, 128>>>();
    k_sgemm<<<dim3(C2 / 128, mblk), T, SGEMM_SMEM>>>(nullptr, ID_H2, wb + WOFF_GAT, gat_b, ID_GAT, NN, C2, C1, C2, 1, 0);

    // LN1 (rounded output; sole consumer is GCN2 GEMM)
    k_ln<<<NN, 128>>>(ID_GAT, ID_GAT, n1_g, n1_b, C2, C2, 0, nullptr);

    // GCN2
    k_sgemm<<<dim3(C3 / 128, mblk), T, SGEMM_SMEM>>>(nullptr, ID_GAT, wb + WOFF_G2, nullptr, ID_H3, NN, C3, C2, C2, 0, 0);
    k_gcn_gather<<<NN / 2, 128>>>(ID_H3, ID_G2, gcn2_b, C3, 0);

    // LN2 + fused x-append (rounded; sole consumer is MLP GEMM)
    k_ln<<<NN, 128>>>(ID_G2, ID_CAT, n2_g, n2_b, C3, CCAT, 1, x);

    // MLP
    k_sgemm<<<dim3(CM / 128, mblk), T, SGEMM_SMEM>>>(nullptr, ID_CAT, wb + WOFF_MLP, mlp_b1, ID_MH, NN, CM, CCAT, CCAT, 0, 1);
    k_out<<<cdiv(NN * 32, T), T>>>(mlp_w2, mlp_b2, out);
}

// round 13
// speedup vs baseline: 4.3273x; 1.0028x over previous
#include <cuda_runtime.h>
#include <cstdint>

#define NN   50000
#define EE   800000
#define C1   128
#define C2   512
#define C3   256
#define CCAT 384
#define CM   128
#define HEADS 4

// weight scratch offsets (floats)
#define WOFF_G1  0
#define WOFF_GAT 16384
#define WOFF_G2  81920
#define WOFF_MLP 212992
#define WTOTAL   262144

// ---------------- scratch (static device globals; no allocation) -------------
__device__ float    g_dinv[NN];
__device__ int      g_cnt[NN];
__device__ int      g_cursor[NN];
__device__ int      g_rowptr[NN + 1];
__device__ int      g_col[EE];
__device__ int      g_bsum[64];
__device__ float    g_h1 [NN*C1];
__device__ float    g_g1 [NN*C1];
__device__ float    g_h2 [NN*C2];      // p[n][h][128] (tf32-rounded)
__device__ float    g_gat[NN*C2];
__device__ float    g_h3 [NN*C3];
__device__ float    g_g2 [NN*C3];
__device__ float    g_cat[NN*CCAT];
__device__ float    g_mh [NN*CM];      // rounded-x early; MLP hidden late
__device__ float    g_asrc[NN*HEADS];
__device__ float    g_adst[NN*HEADS];
__device__ float    g_aself[NN*HEADS];
__device__ float    g_alpha[(size_t)EE*HEADS];
__device__ float    g_wtilS[HEADS*C1];
__device__ float    g_wtilD[HEADS*C1];
__device__ float    g_wbuf[WTOTAL];    // tf32-rounded weights

#define ID_H1  0
#define ID_G1  1
#define ID_H2  2
#define ID_GAT 3
#define ID_H3  4
#define ID_G2  5
#define ID_CAT 6
#define ID_MH  7

__device__ __forceinline__ float* buf(int id) {
    switch (id) {
        case ID_H1:  return g_h1;
        case ID_G1:  return g_g1;
        case ID_H2:  return g_h2;
        case ID_GAT: return g_gat;
        case ID_H3:  return g_h3;
        case ID_G2:  return g_g2;
        case ID_CAT: return g_cat;
        default:     return g_mh;
    }
}

__device__ __forceinline__ float lrelu(float x) { return x >= 0.f ? x : 0.2f * x; }

__device__ __forceinline__ uint32_t tf32r(float f) {
    uint32_t u;
    asm("cvt.rna.tf32.f32 %0, %1;" : "=r"(u) : "f"(f));
    return u;
}
__device__ __forceinline__ float tf32f(float f) { return __uint_as_float(tf32r(f)); }

__device__ __forceinline__ void cpasync16(uint32_t dst, const void* src, int sz) {
    asm volatile("cp.async.cg.shared.global [%0], [%1], 16, %2;\n"
                 :: "r"(dst), "l"(src), "r"(sz));
}

// ---------------- weight / x pre-rounding ------------------------------------
__global__ void k_roundw(const float* __restrict__ w1, const float* __restrict__ wg,
                         const float* __restrict__ w2, const float* __restrict__ wm)
{
    int i = blockIdx.x * blockDim.x + threadIdx.x;
    if (i >= WTOTAL) return;
    float v;
    if (i < WOFF_GAT)      v = w1[i - WOFF_G1];
    else if (i < WOFF_G2)  v = wg[i - WOFF_GAT];
    else if (i < WOFF_MLP) v = w2[i - WOFF_G2];
    else                   v = wm[i - WOFF_MLP];
    g_wbuf[i] = tf32f(v);
}
__global__ void k_roundx(const float* __restrict__ x) {
    int i = blockIdx.x * blockDim.x + threadIdx.x;
    if (i < NN * C1) g_mh[i] = tf32f(x[i]);
}

// ---------------- CSR build --------------------------------------------------
__global__ void k_zero() {
    int i = blockIdx.x * blockDim.x + threadIdx.x;
    if (i < NN) { g_cnt[i] = 0; g_cursor[i] = 0; }
}
__global__ void k_count(const int* __restrict__ ei) {
    int e = blockIdx.x * blockDim.x + threadIdx.x;
    if (e < EE) atomicAdd(&g_cnt[ei[EE + e]], 1);
}
// parallel scan: per-block sums -> serial scan of 49 -> per-block scan+offset
__global__ void __launch_bounds__(1024) k_scan1() {
    __shared__ int s_w[32];
    int tid = threadIdx.x, lane = tid & 31, wid = tid >> 5;
    int i = blockIdx.x * 1024 + tid;
    int v = (i < NN) ? g_cnt[i] : 0;
    if (i < NN) g_dinv[i] = rsqrtf((float)(v + 1));
    int x = v;
#pragma unroll
    for (int o = 16; o; o >>= 1) x += __shfl_xor_sync(0xffffffffu, x, o);
    if (lane == 0) s_w[wid] = x;
    __syncthreads();
    if (tid == 0) {
        int t = 0;
        for (int j = 0; j < 32; j++) t += s_w[j];
        g_bsum[blockIdx.x] = t;
    }
}
__global__ void k_scan2(int nblk) {
    if (threadIdx.x == 0) {
        int acc = 0;
        for (int j = 0; j < nblk; j++) { int t = g_bsum[j]; g_bsum[j] = acc; acc += t; }
        g_rowptr[NN] = acc;
    }
}
__global__ void __launch_bounds__(1024) k_scan3() {
    __shared__ int s_w[32];
    int tid = threadIdx.x, lane = tid & 31, wid = tid >> 5;
    int i = blockIdx.x * 1024 + tid;
    int v = (i < NN) ? g_cnt[i] : 0;
    int x = v;
#pragma unroll
    for (int o = 1; o < 32; o <<= 1) {
        int t = __shfl_up_sync(0xffffffffu, x, o);
        if (lane >= o) x += t;
    }
    if (lane == 31) s_w[wid] = x;
    __syncthreads();
    if (wid == 0) {
        int y = s_w[lane];
#pragma unroll
        for (int o = 1; o < 32; o <<= 1) {
            int t = __shfl_up_sync(0xffffffffu, y, o);
            if (lane >= o) y += t;
        }
        s_w[lane] = y;
    }
    __syncthreads();
    int woff = (wid > 0) ? s_w[wid - 1] : 0;
    if (i < NN) g_rowptr[i] = g_bsum[blockIdx.x] + woff + x - v;
}
__global__ void k_fill(const int* __restrict__ ei) {
    int e = blockIdx.x * blockDim.x + threadIdx.x;
    if (e >= EE) return;
    int d = ei[EE + e];
    int pos = atomicAdd(&g_cursor[d], 1);
    g_col[g_rowptr[d] + pos] = ei[e];
}

// ---------------- TF32 tensor-core GEMM, 3-stage cp.async, NO mainloop cvt ---
// all A/B inputs are pre-rounded to tf32 (bit-identical to in-loop cvt)
#define STAGES 3
#define AST 20
#define BST 132
#define SGEMM_SMEM ((STAGES * 128 * AST + STAGES * 16 * BST) * 4)

__global__ void __launch_bounds__(256) k_sgemm(
    const float* __restrict__ Aext, int Aid,
    const float* __restrict__ B, const float* __restrict__ bias,
    int Cid, int M, int Nc, int K, int lda, int hmode, int doRelu)
{
    extern __shared__ float dsm[];
    float (*Asm)[128][AST] = (float (*)[128][AST])dsm;
    float (*Bsm)[16][BST]  = (float (*)[16][BST])(dsm + STAGES * 128 * AST);

    const float* A = Aext ? Aext : buf(Aid);
    float* C = buf(Cid);

    int tid  = threadIdx.x;
    int lane = tid & 31;
    int w    = tid >> 5;
    int wm   = w >> 2;
    int wn   = w & 3;
    int m0   = wm * 64;
    int n0   = wn * 32;
    int brow = blockIdx.y * 128;
    int bcol = blockIdx.x * 128;
    if (hmode) A += bcol;

    int r  = lane >> 2;
    int cA = lane & 3;

    float acc[4][4][4];
#pragma unroll
    for (int i = 0; i < 4; i++)
#pragma unroll
        for (int j = 0; j < 4; j++)
#pragma unroll
            for (int q = 0; q < 4; q++) acc[i][j][q] = 0.f;

    int amr[2], amk[2], aok[2];
    int bkr[2], bnn[2];
#pragma unroll
    for (int i = 0; i < 2; i++) {
        int chunk = tid + i * 256;
        amr[i] = chunk >> 2;
        amk[i] = (chunk & 3) * 4;
        aok[i] = (brow + amr[i] < M) ? 16 : 0;
        bkr[i] = chunk >> 5;
        bnn[i] = (chunk & 31) * 4;
    }

    int ktiles = K >> 4;

#pragma unroll
    for (int s = 0; s < STAGES - 1; s++) {
        int kt = s << 4;
#pragma unroll
        for (int i = 0; i < 2; i++) {
            uint32_t ad = (uint32_t)__cvta_generic_to_shared(&Asm[s][amr[i]][amk[i]]);
            cpasync16(ad, &A[(size_t)(brow + amr[i]) * lda + kt + amk[i]], aok[i]);
        }
#pragma unroll
        for (int i = 0; i < 2; i++) {
            uint32_t bd = (uint32_t)__cvta_generic_to_shared(&Bsm[s][bkr[i]][bnn[i]]);
            cpasync16(bd, &B[(size_t)(kt + bkr[i]) * Nc + bcol + bnn[i]], 16);
        }
        asm volatile("cp.async.commit_group;\n" ::);
    }

    for (int t = 0; t < ktiles; t++) {
        asm volatile("cp.async.wait_group %0;\n" :: "n"(STAGES - 2));
        __syncthreads();

        int tn = t + STAGES - 1;
        if (tn < ktiles) {
            int s = tn % STAGES;
            int kt = tn << 4;
#pragma unroll
            for (int i = 0; i < 2; i++) {
                uint32_t ad = (uint32_t)__cvta_generic_to_shared(&Asm[s][amr[i]][amk[i]]);
                cpasync16(ad, &A[(size_t)(brow + amr[i]) * lda + kt + amk[i]], aok[i]);
            }
#pragma unroll
            for (int i = 0; i < 2; i++) {
                uint32_t bd = (uint32_t)__cvta_generic_to_shared(&Bsm[s][bkr[i]][bnn[i]]);
                cpasync16(bd, &B[(size_t)(kt + bkr[i]) * Nc + bcol + bnn[i]], 16);
            }
        }
        asm volatile("cp.async.commit_group;\n" ::);

        const float (*As)[AST] = Asm[t % STAGES];
        const float (*Bs)[BST] = Bsm[t % STAGES];

#pragma unroll
        for (int ks = 0; ks < 16; ks += 8) {
            uint32_t af[4][4];
#pragma unroll
            for (int mi = 0; mi < 4; mi++) {
                int mrow = m0 + mi * 16 + r;
                af[mi][0] = __float_as_uint(As[mrow][ks + cA]);
                af[mi][1] = __float_as_uint(As[mrow + 8][ks + cA]);
                af[mi][2] = __float_as_uint(As[mrow][ks + cA + 4]);
                af[mi][3] = __float_as_uint(As[mrow + 8][ks + cA + 4]);
            }
            uint32_t bf[4][2];
#pragma unroll
            for (int ni = 0; ni < 4; ni++) {
                int ncol = n0 + ni * 8 + r;
                bf[ni][0] = __float_as_uint(Bs[ks + cA][ncol]);
                bf[ni][1] = __float_as_uint(Bs[ks + cA + 4][ncol]);
            }
#pragma unroll
            for (int mi = 0; mi < 4; mi++)
#pragma unroll
                for (int ni = 0; ni < 4; ni++) {
                    asm volatile(
                        "mma.sync.aligned.m16n8k8.row.col.f32.tf32.tf32.f32 "
                        "{%0,%1,%2,%3}, {%4,%5,%6,%7}, {%8,%9}, {%0,%1,%2,%3};"
                        : "+f"(acc[mi][ni][0]), "+f"(acc[mi][ni][1]),
                          "+f"(acc[mi][ni][2]), "+f"(acc[mi][ni][3])
                        : "r"(af[mi][0]), "r"(af[mi][1]), "r"(af[mi][2]), "r"(af[mi][3]),
                          "r"(bf[ni][0]), "r"(bf[ni][1]));
                }
        }
        __syncthreads();
    }

#pragma unroll
    for (int mi = 0; mi < 4; mi++) {
        int row0 = brow + m0 + mi * 16 + (lane >> 2);
#pragma unroll
        for (int ni = 0; ni < 4; ni++) {
            int col = bcol + n0 + ni * 8 + 2 * (lane & 3);
            float bx = bias ? bias[col]     : 0.f;
            float by = bias ? bias[col + 1] : 0.f;
            float v0 = acc[mi][ni][0] + bx;
            float v1 = acc[mi][ni][1] + by;
            float v2 = acc[mi][ni][2] + bx;
            float v3 = acc[mi][ni][3] + by;
            if (doRelu) {
                v0 = fmaxf(v0, 0.f); v1 = fmaxf(v1, 0.f);
                v2 = fmaxf(v2, 0.f); v3 = fmaxf(v3, 0.f);
            }
            if (row0 < M) {
                C[(size_t)row0 * Nc + col]     = v0;
                C[(size_t)row0 * Nc + col + 1] = v1;
            }
            if (row0 + 8 < M) {
                C[(size_t)(row0 + 8) * Nc + col]     = v2;
                C[(size_t)(row0 + 8) * Nc + col + 1] = v3;
            }
        }
    }
}

// ---------------- GCN gather (CSR) ------------------------------------------
__global__ void __launch_bounds__(128) k_gcn_gather(
    int Hid, int Oid, const float* __restrict__ bias, int C, int doRelu)
{
    int tpn = C >> 2;
    int npb = 128 / tpn;
    int local = threadIdx.x / tpn;
    int lane  = threadIdx.x - local * tpn;
    int n = blockIdx.x * npb + local;
    if (n >= NN) return;
    int c = lane * 4;
    const float* H = buf(Hid);
    float* O = buf(Oid);

    float4 hv = *(const float4*)&H[(size_t)n * C + c];
    float dn = g_dinv[n];
    float4 acc;
    acc.x = hv.x * dn; acc.y = hv.y * dn; acc.z = hv.z * dn; acc.w = hv.w * dn;

    int start = g_rowptr[n], end = g_rowptr[n + 1];
    for (int i = start; i < end; i++) {
        int s = g_col[i];
        float wgt = g_dinv[s];
        float4 v = *(const float4*)&H[(size_t)s * C + c];
        acc.x += v.x * wgt; acc.y += v.y * wgt; acc.z += v.z * wgt; acc.w += v.w * wgt;
    }
    float4 o;
    o.x = acc.x * dn + bias[c + 0];
    o.y = acc.y * dn + bias[c + 1];
    o.z = acc.z * dn + bias[c + 2];
    o.w = acc.w * dn + bias[c + 3];
    if (doRelu) {
        o.x = fmaxf(o.x, 0.f); o.y = fmaxf(o.y, 0.f);
        o.z = fmaxf(o.z, 0.f); o.w = fmaxf(o.w, 0.f);
    }
    *(float4*)&O[(size_t)n * C + c] = o;
}

// ---------------- GAT --------------------------------------------------------
__global__ void k_wtil(const float* __restrict__ gat_w,
                       const float* __restrict__ attS, const float* __restrict__ attD)
{
    int t = blockIdx.x * blockDim.x + threadIdx.x;
    if (t >= HEADS * C1) return;
    int h = t >> 7;
    int c = t & 127;
    const float* wr = &gat_w[(size_t)c * C2 + h * 128];
    const float* as = &attS[h * 128];
    const float* ad = &attD[h * 128];
    float ss = 0.f, sd = 0.f;
#pragma unroll 4
    for (int k = 0; k < 128; k++) {
        float wv = wr[k];
        ss += wv * as[k];
        sd += wv * ad[k];
    }
    g_wtilS[t] = ss;
    g_wtilD[t] = sd;
}

__global__ void __launch_bounds__(256) k_att2() {
    __shared__ float sws[HEADS * C1], swd[HEADS * C1];
    int tid = threadIdx.x;
    for (int i = tid; i < HEADS * C1; i += 256) { sws[i] = g_wtilS[i]; swd[i] = g_wtilD[i]; }
    __syncthreads();
    int n = (blockIdx.x * 256 + tid) >> 5;
    int lane = tid & 31;
    if (n >= NN) return;
    float ss[HEADS] = {0,0,0,0}, sd[HEADS] = {0,0,0,0};
    for (int c = lane; c < C1; c += 32) {
        float v = g_g1[(size_t)n * C1 + c];
#pragma unroll
        for (int h = 0; h < HEADS; h++) {
            ss[h] += v * sws[h * C1 + c];
            sd[h] += v * swd[h * C1 + c];
        }
    }
#pragma unroll
    for (int h = 0; h < HEADS; h++)
#pragma unroll
        for (int o = 16; o; o >>= 1) {
            ss[h] += __shfl_xor_sync(0xffffffffu, ss[h], o);
            sd[h] += __shfl_xor_sync(0xffffffffu, sd[h], o);
        }
    if (lane == 0) {
#pragma unroll
        for (int h = 0; h < HEADS; h++) {
            g_asrc[n * HEADS + h] = ss[h];
            g_adst[n * HEADS + h] = sd[h];
        }
    }
}

__global__ void k_gat_softmax() {
    int n = (blockIdx.x * blockDim.x + threadIdx.x) >> 5;
    int lane = threadIdx.x & 31;
    if (n >= NN) return;
    int start = g_rowptr[n], end = g_rowptr[n + 1];

    float adst[HEADS], selfe[HEADS];
#pragma unroll
    for (int h = 0; h < HEADS; h++) {
        adst[h]  = g_adst[n * HEADS + h];
        selfe[h] = lrelu(g_asrc[n * HEADS + h] + adst[h]);
    }

    float mx[HEADS];
#pragma unroll
    for (int h = 0; h < HEADS; h++) mx[h] = selfe[h];
    for (int i = start + lane; i < end; i += 32) {
        int s = g_col[i];
#pragma unroll
        for (int h = 0; h < HEADS; h++)
            mx[h] = fmaxf(mx[h], lrelu(g_asrc[s * HEADS + h] + adst[h]));
    }
#pragma unroll
    for (int h = 0; h < HEADS; h++)
#pragma unroll
        for (int o = 16; o; o >>= 1)
            mx[h] = fmaxf(mx[h], __shfl_xor_sync(0xffffffffu, mx[h], o));

    float zz[HEADS];
#pragma unroll
    for (int h = 0; h < HEADS; h++) zz[h] = (lane == 0) ? __expf(selfe[h] - mx[h]) : 0.f;
    for (int i = start + lane; i < end; i += 32) {
        int s = g_col[i];
        float4 ev;
        ev.x = __expf(lrelu(g_asrc[s * HEADS + 0] + adst[0]) - mx[0]);
        ev.y = __expf(lrelu(g_asrc[s * HEADS + 1] + adst[1]) - mx[1]);
        ev.z = __expf(lrelu(g_asrc[s * HEADS + 2] + adst[2]) - mx[2]);
        ev.w = __expf(lrelu(g_asrc[s * HEADS + 3] + adst[3]) - mx[3]);
        *(float4*)&g_alpha[(size_t)i * HEADS] = ev;
        zz[0] += ev.x; zz[1] += ev.y; zz[2] += ev.z; zz[3] += ev.w;
    }
#pragma unroll
    for (int h = 0; h < HEADS; h++)
#pragma unroll
        for (int o = 16; o; o >>= 1)
            zz[h] += __shfl_xor_sync(0xffffffffu, zz[h], o);

    float rz[HEADS];
#pragma unroll
    for (int h = 0; h < HEADS; h++) rz[h] = 1.0f / zz[h];

    for (int i = start + lane; i < end; i += 32) {
        float4 a = *(float4*)&g_alpha[(size_t)i * HEADS];
        a.x *= rz[0]; a.y *= rz[1]; a.z *= rz[2]; a.w *= rz[3];
        *(float4*)&g_alpha[(size_t)i * HEADS] = a;
    }
    if (lane == 0) {
#pragma unroll
        for (int h = 0; h < HEADS; h++)
            g_aself[n * HEADS + h] = __expf(selfe[h] - mx[h]) * rz[h];
    }
}

// pre-projection aggregation; p written tf32-rounded (sole consumer = GAT GEMM)
#define GCHUNK 64
__global__ void __launch_bounds__(128) k_gat_agg2() {
    int n = blockIdx.x;
    int tid = threadIdx.x;
    int start = g_rowptr[n], end = g_rowptr[n + 1];

    __shared__ int    s_src[GCHUNK];
    __shared__ float4 s_al [GCHUNK];

    float g1v = g_g1[(size_t)n * C1 + tid];
    float4 as = *(const float4*)&g_aself[n * HEADS];
    float a0 = g1v * as.x, a1 = g1v * as.y, a2 = g1v * as.z, a3 = g1v * as.w;

    for (int base = start; base < end; base += GCHUNK) {
        int cnt = min(GCHUNK, end - base);
        if (tid < cnt) {
            s_src[tid] = g_col[base + tid];
            s_al[tid]  = *(const float4*)&g_alpha[(size_t)(base + tid) * HEADS];
        }
        __syncthreads();
        for (int j = 0; j < cnt; j++) {
            float v = g_g1[(size_t)s_src[j] * C1 + tid];
            float4 al = s_al[j];
            a0 += al.x * v; a1 += al.y * v; a2 += al.z * v; a3 += al.w * v;
        }
        __syncthreads();
    }

    float* p = &g_h2[(size_t)n * C2];
    p[0 * C1 + tid] = tf32f(a0);
    p[1 * C1 + tid] = tf32f(a1);
    p[2 * C1 + tid] = tf32f(a2);
    p[3 * C1 + tid] = tf32f(a3);
}

// ---------------- LayerNorm (rounded output; optional x append) --------------
__global__ void k_ln(int Xid, int Yid, const float* __restrict__ gw,
                     const float* __restrict__ bw, int C, int ldY, int doRelu,
                     const float* __restrict__ xapp)
{
    int n = blockIdx.x;
    const float* x = buf(Xid) + (size_t)n * C;
    float* y = buf(Yid) + (size_t)n * ldY;
    int tid = threadIdx.x, lane = tid & 31, warp = tid >> 5;

    float s = 0.f, s2 = 0.f;
    for (int c = tid; c < C; c += 128) {
        float v = x[c];
        s += v; s2 += v * v;
    }
#pragma unroll
    for (int o = 16; o; o >>= 1) {
        s  += __shfl_xor_sync(0xffffffffu, s, o);
        s2 += __shfl_xor_sync(0xffffffffu, s2, o);
    }
    __shared__ float shs[4], shs2[4], smu, sinv;
    if (lane == 0) { shs[warp] = s; shs2[warp] = s2; }
    __syncthreads();
    if (tid == 0) {
        float S = shs[0] + shs[1] + shs[2] + shs[3];
        float S2 = shs2[0] + shs2[1] + shs2[2] + shs2[3];
        float mu = S / C;
        float var = S2 / C - mu * mu;
        smu = mu;
        sinv = rsqrtf(var + 1e-5f);
    }
    __syncthreads();
    float mu = smu, inv = sinv;
    for (int c = tid; c < C; c += 128) {
        float v = (x[c] - mu) * inv * gw[c] + bw[c];
        if (doRelu) v = fmaxf(v, 0.f);
        y[c] = tf32f(v);
    }
    if (xapp) {
        for (int c = tid; c < C1; c += 128)
            y[C + c] = tf32f(xapp[(size_t)n * C1 + c]);
    }
}

__global__ void k_out(const float* __restrict__ w2, const float* __restrict__ b2,
                      float* __restrict__ out)
{
    int gw = (blockIdx.x * blockDim.x + threadIdx.x) >> 5;
    int lane = threadIdx.x & 31;
    if (gw >= NN) return;
    const float* hp = &g_mh[(size_t)gw * CM];
    float a0 = 0.f, a1 = 0.f;
#pragma unroll
    for (int c = lane; c < CM; c += 32) {
        float v = hp[c];
        a0 += v * w2[c * 2];
        a1 += v * w2[c * 2 + 1];
    }
#pragma unroll
    for (int o = 16; o; o >>= 1) {
        a0 += __shfl_xor_sync(0xffffffffu, a0, o);
        a1 += __shfl_xor_sync(0xffffffffu, a1, o);
    }
    if (lane == 0) {
        out[gw * 2 + 0] = a0 + b2[0];
        out[gw * 2 + 1] = a1 + b2[1];
    }
}

// ---------------- launch -----------------------------------------------------
static inline int cdiv(int a, int b) { return (a + b - 1) / b; }

extern "C" void kernel_launch(void* const* d_in, const int* in_sizes, int n_in,
                              void* d_out, int out_size)
{
    (void)in_sizes; (void)n_in; (void)out_size;
    const float* x      = (const float*)d_in[0];
    const int*   ei     = (const int*)d_in[1];
    const float* gcn1_w = (const float*)d_in[2];
    const float* gcn1_b = (const float*)d_in[3];
    const float* gat_w  = (const float*)d_in[4];
    const float* att_s  = (const float*)d_in[5];
    const float* att_d  = (const float*)d_in[6];
    const float* gat_b  = (const float*)d_in[7];
    const float* n1_g   = (const float*)d_in[8];
    const float* n1_b   = (const float*)d_in[9];
    const float* gcn2_w = (const float*)d_in[10];
    const float* gcn2_b = (const float*)d_in[11];
    const float* n2_g   = (const float*)d_in[12];
    const float* n2_b   = (const float*)d_in[13];
    const float* mlp_w1 = (const float*)d_in[14];
    const float* mlp_b1 = (const float*)d_in[15];
    const float* mlp_w2 = (const float*)d_in[16];
    const float* mlp_b2 = (const float*)d_in[17];
    float* out = (float*)d_out;

    const int T = 256;
    int mblk = cdiv(NN, 128);
    int sblk = cdiv(NN, 1024);   // 49

    cudaFuncSetAttribute(k_sgemm, cudaFuncAttributeMaxDynamicSharedMemorySize, SGEMM_SMEM);

    float* wb = nullptr;
    cudaGetSymbolAddress((void**)&wb, g_wbuf);

    // pre-round weights and x (bit-identical to in-GEMM cvt)
    k_roundw<<<cdiv(WTOTAL, T), T>>>(gcn1_w, gat_w, gcn2_w, mlp_w1);
    k_roundx<<<cdiv(NN * C1, T), T>>>(x);

    // CSR build
    k_zero <<<cdiv(NN, T), T>>>();
    k_count<<<cdiv(EE, T), T>>>(ei);
    k_scan1<<<sblk, 1024>>>();
    k_scan2<<<1, 32>>>(sblk);
    k_scan3<<<sblk, 1024>>>();
    k_fill <<<cdiv(EE, T), T>>>(ei);

    // GCN1 (A = rounded x in g_mh)
    k_sgemm<<<dim3(1, mblk), T, SGEMM_SMEM>>>(nullptr, ID_MH, wb + WOFF_G1, nullptr, ID_H1, NN, C1, C1, C1, 0, 0);
    k_gcn_gather<<<NN / 4, 128>>>(ID_H1, ID_G1, gcn1_b, C1, 1);

    // GAT: logits from g1; softmax; pre-projection aggregate; per-head GEMM
    k_wtil<<<cdiv(HEADS * C1, T), T>>>(gat_w, att_s, att_d);
    k_att2<<<cdiv(NN * 32, T), T>>>();
    k_gat_softmax<<<cdiv(NN * 32, T), T>>>();
    k_gat_agg2<<<NN, 128>>>();
    k_sgemm<<<dim3(C2 / 128, mblk), T, SGEMM_SMEM>>>(nullptr, ID_H2, wb + WOFF_GAT, gat_b, ID_GAT, NN, C2, C1, C2, 1, 0);

    // LN1 (rounded output; sole consumer is GCN2 GEMM)
    k_ln<<<NN, 128>>>(ID_GAT, ID_GAT, n1_g, n1_b, C2, C2, 0, nullptr);

    // GCN2
    k_sgemm<<<dim3(C3 / 128, mblk), T, SGEMM_SMEM>>>(nullptr, ID_GAT, wb + WOFF_G2, nullptr, ID_H3, NN, C3, C2, C2, 0, 0);
    k_gcn_gather<<<NN / 2, 128>>>(ID_H3, ID_G2, gcn2_b, C3, 0);

    // LN2 + fused x-append (rounded; sole consumer is MLP GEMM)
    k_ln<<<NN, 128>>>(ID_G2, ID_CAT, n2_g, n2_b, C3, CCAT, 1, x);

    // MLP
    k_sgemm<<<dim3(CM / 128, mblk), T, SGEMM_SMEM>>>(nullptr, ID_CAT, wb + WOFF_MLP, mlp_b1, ID_MH, NN, CM, CCAT, CCAT, 0, 1);
    k_out<<<cdiv(NN * 32, T), T>>>(mlp_w2, mlp_b2, out);
}